// round 1
// baseline (speedup 1.0000x reference)
#include <cuda_runtime.h>
#include <math.h>

#define TT 2048
#define BB 8
#define DM 1024
#define DI 2048
#define NS 64
#define MTOT (TT*BB)   /* 16384 token-batch rows */

// Scratch (static __device__ globals: no allocation in kernel_launch)
__device__ float g_WfT[DM * 256];                   // [1024][256]  fused weights, transposed (k-major)
__device__ float g_KVQZ[(size_t)MTOT * 256];        // [16384][256] cols: 0-63 k, 64-127 v, 128-191 q, 192-255 z
__device__ float g_Y[(size_t)MTOT * NS];            // [16384][64]  scan outputs

// ---------------------------------------------------------------------------
// Kernel 1: fused weights.  WfT[d][r] = sum_i Wsel[r][i] * Win[i][d]
// r in [0,256): 0-63 -> W_k, 64-127 -> W_v, 128-191 -> W_q, 192-255 -> W_z
// ---------------------------------------------------------------------------
__global__ void __launch_bounds__(256) k_fuse(
    const float* __restrict__ Win, const float* __restrict__ Wk,
    const float* __restrict__ Wv,  const float* __restrict__ Wq,
    const float* __restrict__ Wz)
{
    __shared__ float As[16][65];   // [k][m]
    __shared__ float Bs[16][68];   // [k][d]  (row stride 272B, 16B aligned)
    const int d0 = blockIdx.x * 64;
    const int m0 = blockIdx.y * 64;
    const int t  = threadIdx.x;
    const int tx = t & 15, ty = t >> 4;
    float acc[4][4] = {};

    const int lm = t >> 2, lk = (t & 3) * 4;
    const int r  = m0 + lm;
    const float* W = (r < 64) ? Wk : (r < 128) ? Wv : (r < 192) ? Wq : Wz;
    const float* arow = W + (size_t)(r & 63) * DI;
    const int bk = t >> 4, bd = (t & 15) * 4;

    for (int k0 = 0; k0 < DI; k0 += 16) {
        float4 a = *(const float4*)(arow + k0 + lk);
        As[lk+0][lm] = a.x; As[lk+1][lm] = a.y; As[lk+2][lm] = a.z; As[lk+3][lm] = a.w;
        float4 b = *(const float4*)(Win + (size_t)(k0 + bk) * DM + d0 + bd);
        *(float4*)&Bs[bk][bd] = b;
        __syncthreads();
        #pragma unroll
        for (int k = 0; k < 16; k++) {
            float av[4];
            #pragma unroll
            for (int i = 0; i < 4; i++) av[i] = As[k][ty*4 + i];
            float4 bv = *(const float4*)&Bs[k][tx*4];
            float bb4[4] = {bv.x, bv.y, bv.z, bv.w};
            #pragma unroll
            for (int i = 0; i < 4; i++)
                #pragma unroll
                for (int j = 0; j < 4; j++)
                    acc[i][j] = fmaf(av[i], bb4[j], acc[i][j]);
        }
        __syncthreads();
    }
    #pragma unroll
    for (int i = 0; i < 4; i++)
        #pragma unroll
        for (int j = 0; j < 4; j++)
            g_WfT[(size_t)(d0 + tx*4 + j) * 256 + (m0 + ty*4 + i)] = acc[i][j];
}

// ---------------------------------------------------------------------------
// Kernel 2: projection GEMM.  KVQZ[m][n] = sum_d X[m][d] * WfT[d][n]
// M=16384, N=256, K=1024.  128x128 tile, 8x8 micro, K-chunk 8.
// ---------------------------------------------------------------------------
__global__ void __launch_bounds__(256, 2) k_proj(const float* __restrict__ X)
{
    __shared__ float As[8][132];   // [k][m]
    __shared__ float Bs[8][132];   // [k][n]
    const int n0 = blockIdx.x * 128;
    const int m0 = blockIdx.y * 128;
    const int t  = threadIdx.x;
    const int tx = t & 15, ty = t >> 4;
    float acc[8][8] = {};

    const int lm = t >> 1, lk = (t & 1) * 4;
    const int bk = t >> 5, bn = (t & 31) * 4;
    const float* arow = X + (size_t)(m0 + lm) * DM + lk;
    const float* brow = g_WfT + (size_t)bk * 256 + n0 + bn;

    for (int k0 = 0; k0 < DM; k0 += 8) {
        float4 a = *(const float4*)(arow + k0);
        As[lk+0][lm] = a.x; As[lk+1][lm] = a.y; As[lk+2][lm] = a.z; As[lk+3][lm] = a.w;
        float4 b = *(const float4*)(brow + (size_t)k0 * 256);
        *(float4*)&Bs[bk][bn] = b;
        __syncthreads();
        #pragma unroll
        for (int k = 0; k < 8; k++) {
            float av[8], bv[8];
            *(float4*)&av[0] = *(const float4*)&As[k][ty*8];
            *(float4*)&av[4] = *(const float4*)&As[k][ty*8 + 4];
            *(float4*)&bv[0] = *(const float4*)&Bs[k][tx*8];
            *(float4*)&bv[4] = *(const float4*)&Bs[k][tx*8 + 4];
            #pragma unroll
            for (int i = 0; i < 8; i++)
                #pragma unroll
                for (int j = 0; j < 8; j++)
                    acc[i][j] = fmaf(av[i], bv[j], acc[i][j]);
        }
        __syncthreads();
    }
    #pragma unroll
    for (int i = 0; i < 8; i++) {
        float* outp = g_KVQZ + (size_t)(m0 + ty*8 + i) * 256 + n0 + tx*8;
        *(float4*)(outp)     = make_float4(acc[i][0], acc[i][1], acc[i][2], acc[i][3]);
        *(float4*)(outp + 4) = make_float4(acc[i][4], acc[i][5], acc[i][6], acc[i][7]);
    }
}

// ---------------------------------------------------------------------------
// Kernel 3: normalize k rows (cols 0-63 of KVQZ): k /= (||k|| + 1e-6)
// One warp per row.
// ---------------------------------------------------------------------------
__global__ void __launch_bounds__(256) k_norm()
{
    const int row  = blockIdx.x * 8 + (threadIdx.x >> 5);
    const int lane = threadIdx.x & 31;
    float* kr = g_KVQZ + (size_t)row * 256 + lane * 2;
    float2 v = *(float2*)kr;
    float ss = v.x * v.x + v.y * v.y;
    #pragma unroll
    for (int m = 16; m >= 1; m >>= 1)
        ss += __shfl_xor_sync(0xffffffffu, ss, m);
    float inv = __fdividef(1.f, sqrtf(ss) + 1e-6f);
    v.x *= inv; v.y *= inv;
    *(float2*)kr = v;
}

// ---------------------------------------------------------------------------
// Kernel 4: sequential delta-rule scan.
// State rows are independent: S[n,:] += (v[n] - S[n,:].k) k^T, y[n]=tanh(S[n,:].q)*sig(z[n]).
// 16 blocks (2 per batch, 32 rows each) x 256 threads.
// 8 lanes per row, 8 state elements per lane (registers), shfl_xor reductions.
// k/v/q/z for step t+1 software-prefetched during step t.
// ---------------------------------------------------------------------------
__global__ void __launch_bounds__(256, 1) k_scan()
{
    const int b    = blockIdx.x >> 1;
    const int half = blockIdx.x & 1;
    const int grp  = threadIdx.x & 7;
    const int row  = half * 32 + (threadIdx.x >> 3);
    const int c0   = grp * 8;
    const float* __restrict__ base = g_KVQZ + (size_t)b * 256;
    float* __restrict__ yb = g_Y + (size_t)b * NS + row;

    float s[8] = {0.f,0.f,0.f,0.f,0.f,0.f,0.f,0.f};

    float4 ka, kb, qa, qb; float vv, zz;
    {   // prefetch t=0
        const float* p = base;
        ka = *(const float4*)(p + c0);        kb = *(const float4*)(p + c0 + 4);
        qa = *(const float4*)(p + 128 + c0);  qb = *(const float4*)(p + 128 + c0 + 4);
        vv = p[64 + row];                     zz = p[192 + row];
    }

    for (int t = 0; t < TT; t++) {
        float kk[8] = {ka.x,ka.y,ka.z,ka.w,kb.x,kb.y,kb.z,kb.w};
        float qq[8] = {qa.x,qa.y,qa.z,qa.w,qb.x,qb.y,qb.z,qb.w};
        float cv = vv, cz = zz;

        // prefetch t+1 (clamped on last iter; loads are independent of compute below)
        int tn = (t + 1 < TT) ? (t + 1) : t;
        const float* p = base + (size_t)tn * (BB * 256);
        ka = *(const float4*)(p + c0);        kb = *(const float4*)(p + c0 + 4);
        qa = *(const float4*)(p + 128 + c0);  qb = *(const float4*)(p + 128 + c0 + 4);
        vv = p[64 + row];                     zz = p[192 + row];

        // pred = S[row,:] . k
        float a0 = 0.f, a1 = 0.f;
        #pragma unroll
        for (int i = 0; i < 8; i += 2) {
            a0 = fmaf(s[i],   kk[i],   a0);
            a1 = fmaf(s[i+1], kk[i+1], a1);
        }
        float pred = a0 + a1;
        pred += __shfl_xor_sync(0xffffffffu, pred, 1);
        pred += __shfl_xor_sync(0xffffffffu, pred, 2);
        pred += __shfl_xor_sync(0xffffffffu, pred, 4);

        // delta-rule update
        float delta = cv - pred;
        #pragma unroll
        for (int i = 0; i < 8; i++) s[i] = fmaf(delta, kk[i], s[i]);

        // readout: tanh(S.q) * sigmoid(z)
        float b0 = 0.f, b1 = 0.f;
        #pragma unroll
        for (int i = 0; i < 8; i += 2) {
            b0 = fmaf(s[i],   qq[i],   b0);
            b1 = fmaf(s[i+1], qq[i+1], b1);
        }
        float dq = b0 + b1;
        dq += __shfl_xor_sync(0xffffffffu, dq, 1);
        dq += __shfl_xor_sync(0xffffffffu, dq, 2);
        dq += __shfl_xor_sync(0xffffffffu, dq, 4);

        float ax = fabsf(dq);
        float e  = __expf(-2.f * ax);
        float th = __fdividef(1.f - e, 1.f + e);      // tanh(|dq|), overflow-safe
        th = copysignf(th, dq);
        float sg = __fdividef(1.f, 1.f + __expf(-cz));
        float y  = th * sg;

        if (grp == 0) yb[(size_t)t * (BB * NS)] = y;
    }
}

// ---------------------------------------------------------------------------
// Kernel 5: output projection.  Out[m][d] = sum_n Y[m][n] * Wout[d][n]
// M=16384, N(=d)=1024, K(=n)=64.  128x128 tile, 8x8 micro, K-chunk 8.
// ---------------------------------------------------------------------------
__global__ void __launch_bounds__(256, 2) k_out(
    const float* __restrict__ Wout, float* __restrict__ Out)
{
    __shared__ float As[8][132];   // [k][m] from Y
    __shared__ float Bs[8][132];   // [k][d] from Wout (transposed on load)
    const int d0 = blockIdx.x * 128;
    const int m0 = blockIdx.y * 128;
    const int t  = threadIdx.x;
    const int tx = t & 15, ty = t >> 4;
    float acc[8][8] = {};

    const int lm = t >> 1, lk = (t & 1) * 4;
    const int bd = t >> 1, bk = (t & 1) * 4;

    for (int k0 = 0; k0 < NS; k0 += 8) {
        float4 a = *(const float4*)(g_Y + (size_t)(m0 + lm) * NS + k0 + lk);
        As[lk+0][lm] = a.x; As[lk+1][lm] = a.y; As[lk+2][lm] = a.z; As[lk+3][lm] = a.w;
        float4 w = *(const float4*)(Wout + (size_t)(d0 + bd) * NS + k0 + bk);
        Bs[bk+0][bd] = w.x; Bs[bk+1][bd] = w.y; Bs[bk+2][bd] = w.z; Bs[bk+3][bd] = w.w;
        __syncthreads();
        #pragma unroll
        for (int k = 0; k < 8; k++) {
            float av[8], bv[8];
            *(float4*)&av[0] = *(const float4*)&As[k][ty*8];
            *(float4*)&av[4] = *(const float4*)&As[k][ty*8 + 4];
            *(float4*)&bv[0] = *(const float4*)&Bs[k][tx*8];
            *(float4*)&bv[4] = *(const float4*)&Bs[k][tx*8 + 4];
            #pragma unroll
            for (int i = 0; i < 8; i++)
                #pragma unroll
                for (int j = 0; j < 8; j++)
                    acc[i][j] = fmaf(av[i], bv[j], acc[i][j]);
        }
        __syncthreads();
    }
    #pragma unroll
    for (int i = 0; i < 8; i++) {
        float* outp = Out + (size_t)(m0 + ty*8 + i) * DM + d0 + tx*8;
        *(float4*)(outp)     = make_float4(acc[i][0], acc[i][1], acc[i][2], acc[i][3]);
        *(float4*)(outp + 4) = make_float4(acc[i][4], acc[i][5], acc[i][6], acc[i][7]);
    }
}

// ---------------------------------------------------------------------------
extern "C" void kernel_launch(void* const* d_in, const int* in_sizes, int n_in,
                              void* d_out, int out_size)
{
    const float* x    = (const float*)d_in[0];  // [2048, 8, 1024]
    const float* Win  = (const float*)d_in[1];  // [2048, 1024]
    const float* Wk   = (const float*)d_in[2];  // [64, 2048]
    const float* Wv   = (const float*)d_in[3];
    const float* Wq   = (const float*)d_in[4];
    const float* Wz   = (const float*)d_in[5];
    const float* Wout = (const float*)d_in[6];  // [1024, 64]
    float* out = (float*)d_out;                 // [2048, 8, 1024]

    k_fuse<<<dim3(16, 4),   256>>>(Win, Wk, Wv, Wq, Wz);
    k_proj<<<dim3(2, 128),  256>>>(x);
    k_norm<<<2048,          256>>>();
    k_scan<<<16,            256>>>();
    k_out <<<dim3(8, 128),  256>>>(Wout, out);
}

// round 3
// speedup vs baseline: 1.2095x; 1.2095x over previous
#include <cuda_runtime.h>
#include <math.h>

#define TT 2048
#define BB 8
#define DM 1024
#define DI 2048
#define NS 64
#define MTOT (TT*BB)   /* 16384 token-batch rows */

// Scratch (static __device__ globals: no allocation in kernel_launch)
__device__ float g_WfT[DM * 256];                   // [1024][256]  fused weights, transposed (k-major)
__device__ float g_KVQZ[(size_t)MTOT * 256];        // [16384][256] cols: 0-63 k, 64-127 v, 128-191 q, 192-255 z
__device__ float g_Y[(size_t)MTOT * NS];            // [16384][64]  scan outputs

// ---------------- packed f32x2 helpers ----------------
__device__ __forceinline__ unsigned long long pk2(float lo, float hi) {
    unsigned long long r;
    asm("mov.b64 %0, {%1, %2};" : "=l"(r) : "f"(lo), "f"(hi));
    return r;
}
__device__ __forceinline__ void unpk2(unsigned long long v, float& lo, float& hi) {
    asm("mov.b64 {%0, %1}, %2;" : "=f"(lo), "=f"(hi) : "l"(v));
}
__device__ __forceinline__ unsigned long long fma2(unsigned long long a,
                                                   unsigned long long b,
                                                   unsigned long long c) {
    unsigned long long d;
    asm("fma.rn.f32x2 %0, %1, %2, %3;" : "=l"(d) : "l"(a), "l"(b), "l"(c));
    return d;
}
__device__ __forceinline__ unsigned long long mul2(unsigned long long a,
                                                   unsigned long long b) {
    unsigned long long d;
    asm("mul.rn.f32x2 %0, %1, %2;" : "=l"(d) : "l"(a), "l"(b));
    return d;
}
__device__ __forceinline__ unsigned long long add2(unsigned long long a,
                                                   unsigned long long b) {
    unsigned long long d;
    asm("add.rn.f32x2 %0, %1, %2;" : "=l"(d) : "l"(a), "l"(b));
    return d;
}
// 8-lane group sum (lanes grouped by low 3 bits); result valid in all 8 lanes.
__device__ __forceinline__ float red8(float v) {
    v += __shfl_xor_sync(0xffffffffu, v, 1);
    v += __shfl_xor_sync(0xffffffffu, v, 2);
    v += __shfl_xor_sync(0xffffffffu, v, 4);
    return v;
}

// ---------------------------------------------------------------------------
// Kernel 1: fused weights.  WfT[d][r] = sum_i Wsel[r][i] * Win[i][d]
// ---------------------------------------------------------------------------
__global__ void __launch_bounds__(256) k_fuse(
    const float* __restrict__ Win, const float* __restrict__ Wk,
    const float* __restrict__ Wv,  const float* __restrict__ Wq,
    const float* __restrict__ Wz)
{
    __shared__ float As[16][65];   // [k][m]
    __shared__ float Bs[16][68];   // [k][d]
    const int d0 = blockIdx.x * 64;
    const int m0 = blockIdx.y * 64;
    const int t  = threadIdx.x;
    const int tx = t & 15, ty = t >> 4;
    float acc[4][4] = {};

    const int lm = t >> 2, lk = (t & 3) * 4;
    const int r  = m0 + lm;
    const float* W = (r < 64) ? Wk : (r < 128) ? Wv : (r < 192) ? Wq : Wz;
    const float* arow = W + (size_t)(r & 63) * DI;
    const int bk = t >> 4, bd = (t & 15) * 4;

    for (int k0 = 0; k0 < DI; k0 += 16) {
        float4 a = *(const float4*)(arow + k0 + lk);
        As[lk+0][lm] = a.x; As[lk+1][lm] = a.y; As[lk+2][lm] = a.z; As[lk+3][lm] = a.w;
        float4 b = *(const float4*)(Win + (size_t)(k0 + bk) * DM + d0 + bd);
        *(float4*)&Bs[bk][bd] = b;
        __syncthreads();
        #pragma unroll
        for (int k = 0; k < 16; k++) {
            float av[4];
            #pragma unroll
            for (int i = 0; i < 4; i++) av[i] = As[k][ty*4 + i];
            float4 bv = *(const float4*)&Bs[k][tx*4];
            float bb4[4] = {bv.x, bv.y, bv.z, bv.w};
            #pragma unroll
            for (int i = 0; i < 4; i++)
                #pragma unroll
                for (int j = 0; j < 4; j++)
                    acc[i][j] = fmaf(av[i], bb4[j], acc[i][j]);
        }
        __syncthreads();
    }
    #pragma unroll
    for (int i = 0; i < 4; i++)
        #pragma unroll
        for (int j = 0; j < 4; j++)
            g_WfT[(size_t)(d0 + tx*4 + j) * 256 + (m0 + ty*4 + i)] = acc[i][j];
}

// ---------------------------------------------------------------------------
// Kernel 2: projection GEMM (f32x2 packed FMA).
// KVQZ[m][n] = sum_d X[m][d] * WfT[d][n].  M=16384, N=256, K=1024.
// ---------------------------------------------------------------------------
__global__ void __launch_bounds__(256, 2) k_proj(const float* __restrict__ X)
{
    __shared__ __align__(16) float As[8][132];   // [k][m]
    __shared__ __align__(16) float Bs[8][132];   // [k][n]
    const int n0 = blockIdx.x * 128;
    const int m0 = blockIdx.y * 128;
    const int t  = threadIdx.x;
    const int tx = t & 15, ty = t >> 4;
    unsigned long long acc2[8][4];
    #pragma unroll
    for (int i = 0; i < 8; i++)
        #pragma unroll
        for (int j = 0; j < 4; j++) acc2[i][j] = 0ull;

    const int lm = t >> 1, lk = (t & 1) * 4;
    const int bk = t >> 5, bn = (t & 31) * 4;
    const float* arow = X + (size_t)(m0 + lm) * DM + lk;
    const float* brow = g_WfT + (size_t)bk * 256 + n0 + bn;

    for (int k0 = 0; k0 < DM; k0 += 8) {
        float4 a = *(const float4*)(arow + k0);
        As[lk+0][lm] = a.x; As[lk+1][lm] = a.y; As[lk+2][lm] = a.z; As[lk+3][lm] = a.w;
        float4 b = *(const float4*)(brow + (size_t)k0 * 256);
        *(float4*)&Bs[bk][bn] = b;
        __syncthreads();
        #pragma unroll
        for (int k = 0; k < 8; k++) {
            float av[8];
            *(float4*)&av[0] = *(const float4*)&As[k][ty*8];
            *(float4*)&av[4] = *(const float4*)&As[k][ty*8 + 4];
            const ulonglong2* bq = (const ulonglong2*)&Bs[k][tx*8];
            ulonglong2 b01 = bq[0], b23 = bq[1];
            unsigned long long bp[4] = {b01.x, b01.y, b23.x, b23.y};
            #pragma unroll
            for (int i = 0; i < 8; i++) {
                unsigned long long ai = pk2(av[i], av[i]);
                #pragma unroll
                for (int j = 0; j < 4; j++)
                    acc2[i][j] = fma2(ai, bp[j], acc2[i][j]);
            }
        }
        __syncthreads();
    }
    #pragma unroll
    for (int i = 0; i < 8; i++) {
        float o[8];
        #pragma unroll
        for (int j = 0; j < 4; j++) unpk2(acc2[i][j], o[2*j], o[2*j+1]);
        float* outp = g_KVQZ + (size_t)(m0 + ty*8 + i) * 256 + n0 + tx*8;
        *(float4*)(outp)     = make_float4(o[0], o[1], o[2], o[3]);
        *(float4*)(outp + 4) = make_float4(o[4], o[5], o[6], o[7]);
    }
}

// ---------------------------------------------------------------------------
// Kernel 3: normalize k rows (cols 0-63 of KVQZ): k /= (||k|| + 1e-6)
// ---------------------------------------------------------------------------
__global__ void __launch_bounds__(256) k_norm()
{
    const int row  = blockIdx.x * 8 + (threadIdx.x >> 5);
    const int lane = threadIdx.x & 31;
    float* kr = g_KVQZ + (size_t)row * 256 + lane * 2;
    float2 v = *(float2*)kr;
    float ss = v.x * v.x + v.y * v.y;
    #pragma unroll
    for (int m = 16; m >= 1; m >>= 1)
        ss += __shfl_xor_sync(0xffffffffu, ss, m);
    float inv = __fdividef(1.f, sqrtf(ss) + 1e-6f);
    v.x *= inv; v.y *= inv;
    *(float2*)kr = v;
}

// ---------------------------------------------------------------------------
// Kernel 4: sequential delta-rule scan.
// 32 blocks x 128 threads: block = (batch, quarter of 16 state rows).
// 8 lanes/row, 8 state elems/lane packed as 4 x f32x2 in registers.
// k/q/v/z staged through smem via cp.async 3-slot ring (8-step segments).
// Group reduction: 3-level shfl_xor tree (redux.f32 unsupported on sm_103a).
// ---------------------------------------------------------------------------
__global__ void __launch_bounds__(128, 1) k_scan()
{
    __shared__ __align__(16) float st[3 * 8 * 160];  // 3 slots x 8 steps x (k64,q64,v16,z16)
    const int tid  = threadIdx.x;
    const int b    = blockIdx.x >> 2;
    const int quar = blockIdx.x & 3;
    const int grp  = tid & 7;
    const int r    = tid >> 3;              // local row 0..15
    const int row  = quar * 16 + r;
    const float* __restrict__ base = g_KVQZ + (size_t)b * 256;
    float* __restrict__ yout = g_Y + (size_t)b * NS + row;

    unsigned long long sp[4] = {0ull, 0ull, 0ull, 0ull};

    const unsigned sbase = (unsigned)__cvta_generic_to_shared(st);

    auto refill = [&](int seg) {
        const int slot = seg % 3;
        const float* s0 = base + (size_t)seg * 8 * 2048;
        for (int c = tid; c < 320; c += 128) {
            int stp = c / 40, j = c - stp * 40;
            int soff, doff;
            if (j < 16)      { soff = j * 4;                          doff = j * 16; }
            else if (j < 32) { soff = 128 + (j - 16) * 4;             doff = 256 + (j - 16) * 16; }
            else if (j < 36) { soff = 64 + quar * 16 + (j - 32) * 4;  doff = 512 + (j - 32) * 16; }
            else             { soff = 192 + quar * 16 + (j - 36) * 4; doff = 576 + (j - 36) * 16; }
            const float* gp = s0 + (size_t)stp * 2048 + soff;
            unsigned sa = sbase + (unsigned)((slot * 8 + stp) * 640 + doff);
            asm volatile("cp.async.cg.shared.global [%0], [%1], 16;" :: "r"(sa), "l"(gp));
        }
        asm volatile("cp.async.commit_group;" ::);
    };

    refill(0);
    refill(1);

    for (int seg = 0; seg < TT / 8; seg++) {
        asm volatile("cp.async.wait_group 1;" ::);
        __syncthreads();
        if (seg + 2 < TT / 8) refill(seg + 2);
        else asm volatile("cp.async.commit_group;" ::);

        const float* sl = st + (seg % 3) * 8 * 160;
        // register prefetch of step 0
        ulonglong2 ka = *(const ulonglong2*)(sl + grp * 8);
        ulonglong2 kb = *(const ulonglong2*)(sl + grp * 8 + 4);
        ulonglong2 qa = *(const ulonglong2*)(sl + 64 + grp * 8);
        ulonglong2 qb = *(const ulonglong2*)(sl + 64 + grp * 8 + 4);
        float cv = sl[128 + r], cz = sl[144 + r];

        #pragma unroll
        for (int u = 0; u < 8; u++) {
            const unsigned long long k0 = ka.x, k1 = ka.y, k2 = kb.x, k3 = kb.y;
            const unsigned long long q0 = qa.x, q1 = qa.y, q2 = qb.x, q3 = qb.y;
            const float vv = cv, zz = cz;

            if (u < 7) {  // prefetch next step (same segment, guaranteed resident)
                const float* sn = sl + (u + 1) * 160;
                ka = *(const ulonglong2*)(sn + grp * 8);
                kb = *(const ulonglong2*)(sn + grp * 8 + 4);
                qa = *(const ulonglong2*)(sn + 64 + grp * 8);
                qb = *(const ulonglong2*)(sn + 64 + grp * 8 + 4);
                cv = sn[128 + r]; cz = sn[144 + r];
            }

            // pred = S[row,:] . k    (two chains, then pair-add)
            unsigned long long pa = mul2(sp[0], k0);
            unsigned long long pb = mul2(sp[1], k1);
            pa = fma2(sp[2], k2, pa);
            pb = fma2(sp[3], k3, pb);
            pa = add2(pa, pb);
            float plo, phi; unpk2(pa, plo, phi);
            float pred = red8(plo + phi);

            // delta-rule update
            float delta = vv - pred;
            unsigned long long dd = pk2(delta, delta);
            sp[0] = fma2(dd, k0, sp[0]);
            sp[1] = fma2(dd, k1, sp[1]);
            sp[2] = fma2(dd, k2, sp[2]);
            sp[3] = fma2(dd, k3, sp[3]);

            // readout: tanh(S.q) * sigmoid(z)
            unsigned long long ya = mul2(sp[0], q0);
            unsigned long long yc = mul2(sp[1], q1);
            ya = fma2(sp[2], q2, ya);
            yc = fma2(sp[3], q3, yc);
            ya = add2(ya, yc);
            float ylo, yhi; unpk2(ya, ylo, yhi);
            float dq = red8(ylo + yhi);

            if (grp == 0) {
                float ax = fabsf(dq);
                float e  = __expf(-2.f * ax);
                float th = __fdividef(1.f - e, 1.f + e);
                th = copysignf(th, dq);
                float sg = __fdividef(1.f, 1.f + __expf(-zz));
                yout[(size_t)(seg * 8 + u) * (BB * NS)] = th * sg;
            }
        }
    }
}

// ---------------------------------------------------------------------------
// Kernel 5: output projection (f32x2 packed FMA).
// Out[m][d] = sum_n Y[m][n] * Wout[d][n].  M=16384, N(=d)=1024, K(=n)=64.
// ---------------------------------------------------------------------------
__global__ void __launch_bounds__(256, 2) k_out(
    const float* __restrict__ Wout, float* __restrict__ Out)
{
    __shared__ __align__(16) float As[8][132];   // [k][m] from Y
    __shared__ __align__(16) float Bs[8][132];   // [k][d] from Wout (transposed on load)
    const int d0 = blockIdx.x * 128;
    const int m0 = blockIdx.y * 128;
    const int t  = threadIdx.x;
    const int tx = t & 15, ty = t >> 4;
    unsigned long long acc2[8][4];
    #pragma unroll
    for (int i = 0; i < 8; i++)
        #pragma unroll
        for (int j = 0; j < 4; j++) acc2[i][j] = 0ull;

    const int lm = t >> 1, lk = (t & 1) * 4;
    const int bd = t >> 1, bk = (t & 1) * 4;

    for (int k0 = 0; k0 < NS; k0 += 8) {
        float4 a = *(const float4*)(g_Y + (size_t)(m0 + lm) * NS + k0 + lk);
        As[lk+0][lm] = a.x; As[lk+1][lm] = a.y; As[lk+2][lm] = a.z; As[lk+3][lm] = a.w;
        float4 w = *(const float4*)(Wout + (size_t)(d0 + bd) * NS + k0 + bk);
        Bs[bk+0][bd] = w.x; Bs[bk+1][bd] = w.y; Bs[bk+2][bd] = w.z; Bs[bk+3][bd] = w.w;
        __syncthreads();
        #pragma unroll
        for (int k = 0; k < 8; k++) {
            float av[8];
            *(float4*)&av[0] = *(const float4*)&As[k][ty*8];
            *(float4*)&av[4] = *(const float4*)&As[k][ty*8 + 4];
            const ulonglong2* bq = (const ulonglong2*)&Bs[k][tx*8];
            ulonglong2 b01 = bq[0], b23 = bq[1];
            unsigned long long bp[4] = {b01.x, b01.y, b23.x, b23.y};
            #pragma unroll
            for (int i = 0; i < 8; i++) {
                unsigned long long ai = pk2(av[i], av[i]);
                #pragma unroll
                for (int j = 0; j < 4; j++)
                    acc2[i][j] = fma2(ai, bp[j], acc2[i][j]);
            }
        }
        __syncthreads();
    }
    #pragma unroll
    for (int i = 0; i < 8; i++) {
        float o[8];
        #pragma unroll
        for (int j = 0; j < 4; j++) unpk2(acc2[i][j], o[2*j], o[2*j+1]);
        float* outp = Out + (size_t)(m0 + ty*8 + i) * DM + d0 + tx*8;
        *(float4*)(outp)     = make_float4(o[0], o[1], o[2], o[3]);
        *(float4*)(outp + 4) = make_float4(o[4], o[5], o[6], o[7]);
    }
}

// ---------------------------------------------------------------------------
extern "C" void kernel_launch(void* const* d_in, const int* in_sizes, int n_in,
                              void* d_out, int out_size)
{
    const float* x    = (const float*)d_in[0];  // [2048, 8, 1024]
    const float* Win  = (const float*)d_in[1];  // [2048, 1024]
    const float* Wk   = (const float*)d_in[2];  // [64, 2048]
    const float* Wv   = (const float*)d_in[3];
    const float* Wq   = (const float*)d_in[4];
    const float* Wz   = (const float*)d_in[5];
    const float* Wout = (const float*)d_in[6];  // [1024, 64]
    float* out = (float*)d_out;                 // [2048, 8, 1024]

    k_fuse<<<dim3(16, 4),   256>>>(Win, Wk, Wv, Wq, Wz);
    k_proj<<<dim3(2, 128),  256>>>(x);
    k_norm<<<2048,          256>>>();
    k_scan<<<32,            128>>>();
    k_out <<<dim3(8, 128),  256>>>(Wout, out);
}

// round 4
// speedup vs baseline: 1.3005x; 1.0753x over previous
#include <cuda_runtime.h>
#include <math.h>

#define TT 2048
#define BB 8
#define DM 1024
#define DI 2048
#define NS 64
#define MTOT (TT*BB)   /* 16384 token-batch rows */

// Scratch (static __device__ globals: no allocation in kernel_launch)
__device__ float g_WfT[DM * 256];                   // [1024][256]  fused weights, transposed
__device__ float g_KVQZ[(size_t)MTOT * 256];        // [16384][256] cols: 0-63 k, 64-127 v, 128-191 q, 192-255 z
__device__ float g_Y[(size_t)MTOT * NS];            // [16384][64]  raw dq from scan, then activated in-place

// ---------------- packed f32x2 helpers ----------------
__device__ __forceinline__ unsigned long long pk2(float lo, float hi) {
    unsigned long long r;
    asm("mov.b64 %0, {%1, %2};" : "=l"(r) : "f"(lo), "f"(hi));
    return r;
}
__device__ __forceinline__ void unpk2(unsigned long long v, float& lo, float& hi) {
    asm("mov.b64 {%0, %1}, %2;" : "=f"(lo), "=f"(hi) : "l"(v));
}
__device__ __forceinline__ unsigned long long fma2(unsigned long long a,
                                                   unsigned long long b,
                                                   unsigned long long c) {
    unsigned long long d;
    asm("fma.rn.f32x2 %0, %1, %2, %3;" : "=l"(d) : "l"(a), "l"(b), "l"(c));
    return d;
}
__device__ __forceinline__ unsigned long long mul2(unsigned long long a,
                                                   unsigned long long b) {
    unsigned long long d;
    asm("mul.rn.f32x2 %0, %1, %2;" : "=l"(d) : "l"(a), "l"(b));
    return d;
}
__device__ __forceinline__ unsigned long long add2(unsigned long long a,
                                                   unsigned long long b) {
    unsigned long long d;
    asm("add.rn.f32x2 %0, %1, %2;" : "=l"(d) : "l"(a), "l"(b));
    return d;
}

// ---------------------------------------------------------------------------
// Kernel 1: fused weights.  WfT[d][r] = sum_i Wsel[r][i] * Win[i][d]
// ---------------------------------------------------------------------------
__global__ void __launch_bounds__(256) k_fuse(
    const float* __restrict__ Win, const float* __restrict__ Wk,
    const float* __restrict__ Wv,  const float* __restrict__ Wq,
    const float* __restrict__ Wz)
{
    __shared__ float As[16][65];   // [k][m]
    __shared__ float Bs[16][68];   // [k][d]
    const int d0 = blockIdx.x * 64;
    const int m0 = blockIdx.y * 64;
    const int t  = threadIdx.x;
    const int tx = t & 15, ty = t >> 4;
    float acc[4][4] = {};

    const int lm = t >> 2, lk = (t & 3) * 4;
    const int r  = m0 + lm;
    const float* W = (r < 64) ? Wk : (r < 128) ? Wv : (r < 192) ? Wq : Wz;
    const float* arow = W + (size_t)(r & 63) * DI;
    const int bk = t >> 4, bd = (t & 15) * 4;

    for (int k0 = 0; k0 < DI; k0 += 16) {
        float4 a = *(const float4*)(arow + k0 + lk);
        As[lk+0][lm] = a.x; As[lk+1][lm] = a.y; As[lk+2][lm] = a.z; As[lk+3][lm] = a.w;
        float4 b = *(const float4*)(Win + (size_t)(k0 + bk) * DM + d0 + bd);
        *(float4*)&Bs[bk][bd] = b;
        __syncthreads();
        #pragma unroll
        for (int k = 0; k < 16; k++) {
            float av[4];
            #pragma unroll
            for (int i = 0; i < 4; i++) av[i] = As[k][ty*4 + i];
            float4 bv = *(const float4*)&Bs[k][tx*4];
            float bb4[4] = {bv.x, bv.y, bv.z, bv.w};
            #pragma unroll
            for (int i = 0; i < 4; i++)
                #pragma unroll
                for (int j = 0; j < 4; j++)
                    acc[i][j] = fmaf(av[i], bb4[j], acc[i][j]);
        }
        __syncthreads();
    }
    #pragma unroll
    for (int i = 0; i < 4; i++)
        #pragma unroll
        for (int j = 0; j < 4; j++)
            g_WfT[(size_t)(d0 + tx*4 + j) * 256 + (m0 + ty*4 + i)] = acc[i][j];
}

// ---------------------------------------------------------------------------
// Kernel 2: projection GEMM (f32x2 packed FMA, A duplicated in smem so packed
// 64-bit loads give broadcast pairs directly — no per-iter mov.b64 packs).
// KVQZ[m][n] = sum_d X[m][d] * WfT[d][n].  M=16384, N=256, K=1024.
// ---------------------------------------------------------------------------
__global__ void __launch_bounds__(256, 2) k_proj(const float* __restrict__ X)
{
    __shared__ __align__(16) float As2[8][264];  // [k][2m] duplicated pairs
    __shared__ __align__(16) float Bs[8][132];   // [k][n]
    const int n0 = blockIdx.x * 128;
    const int m0 = blockIdx.y * 128;
    const int t  = threadIdx.x;
    const int tx = t & 15, ty = t >> 4;
    unsigned long long acc2[8][4];
    #pragma unroll
    for (int i = 0; i < 8; i++)
        #pragma unroll
        for (int j = 0; j < 4; j++) acc2[i][j] = 0ull;

    const int lm = t >> 1, lk = (t & 1) * 4;
    const int bk = t >> 5, bn = (t & 31) * 4;
    const float* arow = X + (size_t)(m0 + lm) * DM + lk;
    const float* brow = g_WfT + (size_t)bk * 256 + n0 + bn;

    for (int k0 = 0; k0 < DM; k0 += 8) {
        float4 a = *(const float4*)(arow + k0);
        *(float2*)&As2[lk+0][2*lm] = make_float2(a.x, a.x);
        *(float2*)&As2[lk+1][2*lm] = make_float2(a.y, a.y);
        *(float2*)&As2[lk+2][2*lm] = make_float2(a.z, a.z);
        *(float2*)&As2[lk+3][2*lm] = make_float2(a.w, a.w);
        float4 b = *(const float4*)(brow + (size_t)k0 * 256);
        *(float4*)&Bs[bk][bn] = b;
        __syncthreads();
        #pragma unroll
        for (int k = 0; k < 8; k++) {
            unsigned long long av2[8];
            #pragma unroll
            for (int i = 0; i < 8; i++)
                av2[i] = *(const unsigned long long*)&As2[k][(ty*8 + i) * 2];
            const ulonglong2* bq = (const ulonglong2*)&Bs[k][tx*8];
            ulonglong2 b01 = bq[0], b23 = bq[1];
            unsigned long long bp[4] = {b01.x, b01.y, b23.x, b23.y};
            #pragma unroll
            for (int i = 0; i < 8; i++)
                #pragma unroll
                for (int j = 0; j < 4; j++)
                    acc2[i][j] = fma2(av2[i], bp[j], acc2[i][j]);
        }
        __syncthreads();
    }
    #pragma unroll
    for (int i = 0; i < 8; i++) {
        float o[8];
        #pragma unroll
        for (int j = 0; j < 4; j++) unpk2(acc2[i][j], o[2*j], o[2*j+1]);
        float* outp = g_KVQZ + (size_t)(m0 + ty*8 + i) * 256 + n0 + tx*8;
        *(float4*)(outp)     = make_float4(o[0], o[1], o[2], o[3]);
        *(float4*)(outp + 4) = make_float4(o[4], o[5], o[6], o[7]);
    }
}

// ---------------------------------------------------------------------------
// Kernel 3: normalize k rows (cols 0-63 of KVQZ): k /= (||k|| + 1e-6)
// ---------------------------------------------------------------------------
__global__ void __launch_bounds__(256) k_norm()
{
    const int row  = blockIdx.x * 8 + (threadIdx.x >> 5);
    const int lane = threadIdx.x & 31;
    float* kr = g_KVQZ + (size_t)row * 256 + lane * 2;
    float2 v = *(float2*)kr;
    float ss = v.x * v.x + v.y * v.y;
    #pragma unroll
    for (int m = 16; m >= 1; m >>= 1)
        ss += __shfl_xor_sync(0xffffffffu, ss, m);
    float inv = __fdividef(1.f, sqrtf(ss) + 1e-6f);
    v.x *= inv; v.y *= inv;
    *(float2*)kr = v;
}

// ---------------------------------------------------------------------------
// Kernel 4: sequential delta-rule scan.
// 16 blocks x 128 threads (1 warp/SMSP): block = (batch, half of 32 rows).
// 4 lanes/row, 16 state elems/lane as 8 x f32x2 (2-level shfl reduce).
// dq readout reduction is software-pipelined: reduced interleaved with the
// NEXT step's pred reduction (two dependent shfl chains share latency).
// tanh/sigmoid deferred to k_act. k/q/v staged via cp.async 3-slot ring.
// ---------------------------------------------------------------------------
__global__ void __launch_bounds__(128, 1) k_scan()
{
    __shared__ __align__(16) float st[3 * 8 * 160];  // 3 slots x 8 steps x (k64,q64,v32)
    const int tid  = threadIdx.x;
    const int b    = blockIdx.x >> 1;
    const int half = blockIdx.x & 1;
    const int grp  = tid & 3;               // column group: elems grp*16..grp*16+15
    const int r    = tid >> 2;              // local row 0..31
    const float* __restrict__ base = g_KVQZ + (size_t)b * 256;
    float* __restrict__ yout = g_Y + (size_t)b * NS + half * 32 + r;

    unsigned long long sp[8];
    #pragma unroll
    for (int i = 0; i < 8; i++) sp[i] = 0ull;

    const unsigned sbase = (unsigned)__cvta_generic_to_shared(st);

    auto refill = [&](int seg) {
        const int slot = seg % 3;
        const float* s0 = base + (size_t)seg * 8 * 2048;
        #pragma unroll
        for (int it = 0; it < 3; it++) {
            int c = tid + it * 128;                   // c in [0,384) but only <320 valid
            if (c < 320) {
                int stp = c / 40, j = c - stp * 40;
                int soff, doff;
                if (j < 16)      { soff = j * 4;                          doff = j * 4; }
                else if (j < 32) { soff = 128 + (j - 16) * 4;             doff = 64 + (j - 16) * 4; }
                else             { soff = 64 + half * 32 + (j - 32) * 4;  doff = 128 + (j - 32) * 4; }
                const float* gp = s0 + (size_t)stp * 2048 + soff;
                unsigned sa = sbase + (unsigned)(((slot * 8 + stp) * 160 + doff) * 4);
                asm volatile("cp.async.cg.shared.global [%0], [%1], 16;" :: "r"(sa), "l"(gp));
            }
        }
        asm volatile("cp.async.commit_group;" ::);
    };

    refill(0);
    refill(1);

    float pend = 0.f;   // dq partial sum for previous step (per-lane)

    for (int seg = 0; seg < TT / 8; seg++) {
        asm volatile("cp.async.wait_group 1;" ::);
        __syncthreads();
        if (seg + 2 < TT / 8) refill(seg + 2);
        else asm volatile("cp.async.commit_group;" ::);

        const float* sl = st + (seg % 3) * 8 * 160;
        // load step-0 k
        unsigned long long kc[8];
        {
            const ulonglong2* kp = (const ulonglong2*)(sl + grp * 16);
            ulonglong2 a = kp[0], bq = kp[1], c = kp[2], d = kp[3];
            kc[0]=a.x; kc[1]=a.y; kc[2]=bq.x; kc[3]=bq.y;
            kc[4]=c.x; kc[5]=c.y; kc[6]=d.x;  kc[7]=d.y;
        }

        #pragma unroll
        for (int u = 0; u < 8; u++) {
            const float* sc = sl + u * 160;
            const int gt = seg * 8 + u;
            float vv = sc[128 + r];

            // q for this step (needed only after update; LDS latency hidden)
            unsigned long long qv[8];
            {
                const ulonglong2* qp = (const ulonglong2*)(sc + 64 + grp * 16);
                ulonglong2 a = qp[0], bq = qp[1], c = qp[2], d = qp[3];
                qv[0]=a.x; qv[1]=a.y; qv[2]=bq.x; qv[3]=bq.y;
                qv[4]=c.x; qv[5]=c.y; qv[6]=d.x;  qv[7]=d.y;
            }

            // pred partial = S[row, grp-cols] . k
            unsigned long long p0 = mul2(sp[0], kc[0]);
            unsigned long long p1 = mul2(sp[1], kc[1]);
            unsigned long long p2 = mul2(sp[2], kc[2]);
            unsigned long long p3 = mul2(sp[3], kc[3]);
            p0 = fma2(sp[4], kc[4], p0);
            p1 = fma2(sp[5], kc[5], p1);
            p2 = fma2(sp[6], kc[6], p2);
            p3 = fma2(sp[7], kc[7], p3);
            p0 = add2(p0, p1); p2 = add2(p2, p3); p0 = add2(p0, p2);
            float plo, phi; unpk2(p0, plo, phi);
            float pp = plo + phi;

            // interleaved 4-lane reductions: pred (this step) + dq (prev step)
            float a1 = __shfl_xor_sync(0xffffffffu, pp,   1);
            float b1 = __shfl_xor_sync(0xffffffffu, pend, 1);
            pp += a1;
            float dd = pend + b1;
            float a2 = __shfl_xor_sync(0xffffffffu, pp, 2);
            float b2 = __shfl_xor_sync(0xffffffffu, dd, 2);
            pp += a2;
            dd += b2;

            if (grp == 0 && gt > 0)
                yout[(size_t)(gt - 1) * (BB * NS)] = dd;   // raw dq; activation in k_act

            // delta-rule update
            float delta = vv - pp;
            unsigned long long dp = pk2(delta, delta);
            #pragma unroll
            for (int i = 0; i < 8; i++) sp[i] = fma2(dp, kc[i], sp[i]);

            // dq partial for this step (pended)
            unsigned long long y0 = mul2(sp[0], qv[0]);
            unsigned long long y1 = mul2(sp[1], qv[1]);
            unsigned long long y2 = mul2(sp[2], qv[2]);
            unsigned long long y3 = mul2(sp[3], qv[3]);
            y0 = fma2(sp[4], qv[4], y0);
            y1 = fma2(sp[5], qv[5], y1);
            y2 = fma2(sp[6], qv[6], y2);
            y3 = fma2(sp[7], qv[7], y3);
            y0 = add2(y0, y1); y2 = add2(y2, y3); y0 = add2(y0, y2);
            float ylo, yhi; unpk2(y0, ylo, yhi);
            pend = ylo + yhi;

            // prefetch next step's k (same slot; resident)
            if (u < 7) {
                const ulonglong2* kp = (const ulonglong2*)(sc + 160 + grp * 16);
                ulonglong2 a = kp[0], bq = kp[1], c = kp[2], d = kp[3];
                kc[0]=a.x; kc[1]=a.y; kc[2]=bq.x; kc[3]=bq.y;
                kc[4]=c.x; kc[5]=c.y; kc[6]=d.x;  kc[7]=d.y;
            }
        }
    }

    // flush last step's dq
    float b1 = __shfl_xor_sync(0xffffffffu, pend, 1);
    float dd = pend + b1;
    float b2 = __shfl_xor_sync(0xffffffffu, dd, 2);
    dd += b2;
    if (grp == 0) yout[(size_t)(TT - 1) * (BB * NS)] = dd;
}

// ---------------------------------------------------------------------------
// Kernel 4b: activation.  g_Y[m][n] = tanh(dq) * sigmoid(z),  z from g_KVQZ.
// ---------------------------------------------------------------------------
__global__ void __launch_bounds__(256) k_act()
{
    const int i = blockIdx.x * 256 + threadIdx.x;   // over MTOT*16 float4-quads
    const int m = i >> 4, n4 = (i & 15) * 4;
    float4 dq = *(const float4*)(g_Y + (size_t)m * NS + n4);
    float4 z  = *(const float4*)(g_KVQZ + (size_t)m * 256 + 192 + n4);
    float o[4]; float dqa[4] = {dq.x, dq.y, dq.z, dq.w};
    float za[4] = {z.x, z.y, z.z, z.w};
    #pragma unroll
    for (int j = 0; j < 4; j++) {
        float ax = fabsf(dqa[j]);
        float e  = __expf(-2.f * ax);
        float th = __fdividef(1.f - e, 1.f + e);
        th = copysignf(th, dqa[j]);
        float sg = __fdividef(1.f, 1.f + __expf(-za[j]));
        o[j] = th * sg;
    }
    *(float4*)(g_Y + (size_t)m * NS + n4) = make_float4(o[0], o[1], o[2], o[3]);
}

// ---------------------------------------------------------------------------
// Kernel 5: output projection (f32x2 packed FMA).
// Out[m][d] = sum_n Y[m][n] * Wout[d][n].  M=16384, N(=d)=1024, K(=n)=64.
// ---------------------------------------------------------------------------
__global__ void __launch_bounds__(256, 2) k_out(
    const float* __restrict__ Wout, float* __restrict__ Out)
{
    __shared__ __align__(16) float As[8][132];   // [k][m] from Y
    __shared__ __align__(16) float Bs[8][132];   // [k][d] from Wout (transposed on load)
    const int d0 = blockIdx.x * 128;
    const int m0 = blockIdx.y * 128;
    const int t  = threadIdx.x;
    const int tx = t & 15, ty = t >> 4;
    unsigned long long acc2[8][4];
    #pragma unroll
    for (int i = 0; i < 8; i++)
        #pragma unroll
        for (int j = 0; j < 4; j++) acc2[i][j] = 0ull;

    const int lm = t >> 1, lk = (t & 1) * 4;
    const int bd = t >> 1, bk = (t & 1) * 4;

    for (int k0 = 0; k0 < NS; k0 += 8) {
        float4 a = *(const float4*)(g_Y + (size_t)(m0 + lm) * NS + k0 + lk);
        As[lk+0][lm] = a.x; As[lk+1][lm] = a.y; As[lk+2][lm] = a.z; As[lk+3][lm] = a.w;
        float4 w = *(const float4*)(Wout + (size_t)(d0 + bd) * NS + k0 + bk);
        Bs[bk+0][bd] = w.x; Bs[bk+1][bd] = w.y; Bs[bk+2][bd] = w.z; Bs[bk+3][bd] = w.w;
        __syncthreads();
        #pragma unroll
        for (int k = 0; k < 8; k++) {
            float av[8];
            *(float4*)&av[0] = *(const float4*)&As[k][ty*8];
            *(float4*)&av[4] = *(const float4*)&As[k][ty*8 + 4];
            const ulonglong2* bq = (const ulonglong2*)&Bs[k][tx*8];
            ulonglong2 b01 = bq[0], b23 = bq[1];
            unsigned long long bp[4] = {b01.x, b01.y, b23.x, b23.y};
            #pragma unroll
            for (int i = 0; i < 8; i++) {
                unsigned long long ai = pk2(av[i], av[i]);
                #pragma unroll
                for (int j = 0; j < 4; j++)
                    acc2[i][j] = fma2(ai, bp[j], acc2[i][j]);
            }
        }
        __syncthreads();
    }
    #pragma unroll
    for (int i = 0; i < 8; i++) {
        float o[8];
        #pragma unroll
        for (int j = 0; j < 4; j++) unpk2(acc2[i][j], o[2*j], o[2*j+1]);
        float* outp = Out + (size_t)(m0 + ty*8 + i) * DM + d0 + tx*8;
        *(float4*)(outp)     = make_float4(o[0], o[1], o[2], o[3]);
        *(float4*)(outp + 4) = make_float4(o[4], o[5], o[6], o[7]);
    }
}

// ---------------------------------------------------------------------------
extern "C" void kernel_launch(void* const* d_in, const int* in_sizes, int n_in,
                              void* d_out, int out_size)
{
    const float* x    = (const float*)d_in[0];  // [2048, 8, 1024]
    const float* Win  = (const float*)d_in[1];  // [2048, 1024]
    const float* Wk   = (const float*)d_in[2];  // [64, 2048]
    const float* Wv   = (const float*)d_in[3];
    const float* Wq   = (const float*)d_in[4];
    const float* Wz   = (const float*)d_in[5];
    const float* Wout = (const float*)d_in[6];  // [1024, 64]
    float* out = (float*)d_out;                 // [2048, 8, 1024]

    k_fuse<<<dim3(16, 4),   256>>>(Win, Wk, Wv, Wq, Wz);
    k_proj<<<dim3(2, 128),  256>>>(x);
    k_norm<<<2048,          256>>>();
    k_scan<<<16,            128>>>();
    k_act <<<1024,          256>>>();
    k_out <<<dim3(8, 128),  256>>>(Wout, out);
}

// round 5
// speedup vs baseline: 1.4503x; 1.1151x over previous
#include <cuda_runtime.h>
#include <math.h>

#define TT 2048
#define BB 8
#define DM 1024
#define DI 2048
#define NS 64
#define MTOT (TT*BB)   /* 16384 token-batch rows */

// Scratch (static __device__ globals: no allocation in kernel_launch)
__device__ float g_WfT[DM * 256];                   // [1024][256]  fused weights, transposed
__device__ float g_KVQZ[(size_t)MTOT * 256];        // [16384][256] cols: 0-63 k, 64-127 v, 128-191 q, 192-255 z
__device__ float g_Y[(size_t)MTOT * NS];            // [16384][64]  raw dq from scan, then activated in-place

// ---------------- packed f32x2 helpers ----------------
__device__ __forceinline__ unsigned long long pk2(float lo, float hi) {
    unsigned long long r;
    asm("mov.b64 %0, {%1, %2};" : "=l"(r) : "f"(lo), "f"(hi));
    return r;
}
__device__ __forceinline__ void unpk2(unsigned long long v, float& lo, float& hi) {
    asm("mov.b64 {%0, %1}, %2;" : "=f"(lo), "=f"(hi) : "l"(v));
}
__device__ __forceinline__ unsigned long long fma2(unsigned long long a,
                                                   unsigned long long b,
                                                   unsigned long long c) {
    unsigned long long d;
    asm("fma.rn.f32x2 %0, %1, %2, %3;" : "=l"(d) : "l"(a), "l"(b), "l"(c));
    return d;
}
__device__ __forceinline__ unsigned long long mul2(unsigned long long a,
                                                   unsigned long long b) {
    unsigned long long d;
    asm("mul.rn.f32x2 %0, %1, %2;" : "=l"(d) : "l"(a), "l"(b));
    return d;
}
__device__ __forceinline__ unsigned long long add2(unsigned long long a,
                                                   unsigned long long b) {
    unsigned long long d;
    asm("add.rn.f32x2 %0, %1, %2;" : "=l"(d) : "l"(a), "l"(b));
    return d;
}

// ---------------------------------------------------------------------------
// Kernel 1: fused weights.  WfT[d][r] = sum_i Wsel[r][i] * Win[i][d]
// ---------------------------------------------------------------------------
__global__ void __launch_bounds__(256) k_fuse(
    const float* __restrict__ Win, const float* __restrict__ Wk,
    const float* __restrict__ Wv,  const float* __restrict__ Wq,
    const float* __restrict__ Wz)
{
    __shared__ float As[16][65];   // [k][m]
    __shared__ float Bs[16][68];   // [k][d]
    const int d0 = blockIdx.x * 64;
    const int m0 = blockIdx.y * 64;
    const int t  = threadIdx.x;
    const int tx = t & 15, ty = t >> 4;
    float acc[4][4] = {};

    const int lm = t >> 2, lk = (t & 3) * 4;
    const int r  = m0 + lm;
    const float* W = (r < 64) ? Wk : (r < 128) ? Wv : (r < 192) ? Wq : Wz;
    const float* arow = W + (size_t)(r & 63) * DI;
    const int bk = t >> 4, bd = (t & 15) * 4;

    for (int k0 = 0; k0 < DI; k0 += 16) {
        float4 a = *(const float4*)(arow + k0 + lk);
        As[lk+0][lm] = a.x; As[lk+1][lm] = a.y; As[lk+2][lm] = a.z; As[lk+3][lm] = a.w;
        float4 b = *(const float4*)(Win + (size_t)(k0 + bk) * DM + d0 + bd);
        *(float4*)&Bs[bk][bd] = b;
        __syncthreads();
        #pragma unroll
        for (int k = 0; k < 16; k++) {
            float av[4];
            #pragma unroll
            for (int i = 0; i < 4; i++) av[i] = As[k][ty*4 + i];
            float4 bv = *(const float4*)&Bs[k][tx*4];
            float bb4[4] = {bv.x, bv.y, bv.z, bv.w};
            #pragma unroll
            for (int i = 0; i < 4; i++)
                #pragma unroll
                for (int j = 0; j < 4; j++)
                    acc[i][j] = fmaf(av[i], bb4[j], acc[i][j]);
        }
        __syncthreads();
    }
    #pragma unroll
    for (int i = 0; i < 4; i++)
        #pragma unroll
        for (int j = 0; j < 4; j++)
            g_WfT[(size_t)(d0 + tx*4 + j) * 256 + (m0 + ty*4 + i)] = acc[i][j];
}

// ---------------------------------------------------------------------------
// Kernel 2: projection GEMM (f32x2 packed FMA).  [R3 form — faster than
// duplicated-A variant per R4 measurement]
// KVQZ[m][n] = sum_d X[m][d] * WfT[d][n].  M=16384, N=256, K=1024.
// ---------------------------------------------------------------------------
__global__ void __launch_bounds__(256, 2) k_proj(const float* __restrict__ X)
{
    __shared__ __align__(16) float As[8][132];   // [k][m]
    __shared__ __align__(16) float Bs[8][132];   // [k][n]
    const int n0 = blockIdx.x * 128;
    const int m0 = blockIdx.y * 128;
    const int t  = threadIdx.x;
    const int tx = t & 15, ty = t >> 4;
    unsigned long long acc2[8][4];
    #pragma unroll
    for (int i = 0; i < 8; i++)
        #pragma unroll
        for (int j = 0; j < 4; j++) acc2[i][j] = 0ull;

    const int lm = t >> 1, lk = (t & 1) * 4;
    const int bk = t >> 5, bn = (t & 31) * 4;
    const float* arow = X + (size_t)(m0 + lm) * DM + lk;
    const float* brow = g_WfT + (size_t)bk * 256 + n0 + bn;

    for (int k0 = 0; k0 < DM; k0 += 8) {
        float4 a = *(const float4*)(arow + k0);
        As[lk+0][lm] = a.x; As[lk+1][lm] = a.y; As[lk+2][lm] = a.z; As[lk+3][lm] = a.w;
        float4 b = *(const float4*)(brow + (size_t)k0 * 256);
        *(float4*)&Bs[bk][bn] = b;
        __syncthreads();
        #pragma unroll
        for (int k = 0; k < 8; k++) {
            float av[8];
            *(float4*)&av[0] = *(const float4*)&As[k][ty*8];
            *(float4*)&av[4] = *(const float4*)&As[k][ty*8 + 4];
            const ulonglong2* bq = (const ulonglong2*)&Bs[k][tx*8];
            ulonglong2 b01 = bq[0], b23 = bq[1];
            unsigned long long bp[4] = {b01.x, b01.y, b23.x, b23.y};
            #pragma unroll
            for (int i = 0; i < 8; i++) {
                unsigned long long ai = pk2(av[i], av[i]);
                #pragma unroll
                for (int j = 0; j < 4; j++)
                    acc2[i][j] = fma2(ai, bp[j], acc2[i][j]);
            }
        }
        __syncthreads();
    }
    #pragma unroll
    for (int i = 0; i < 8; i++) {
        float o[8];
        #pragma unroll
        for (int j = 0; j < 4; j++) unpk2(acc2[i][j], o[2*j], o[2*j+1]);
        float* outp = g_KVQZ + (size_t)(m0 + ty*8 + i) * 256 + n0 + tx*8;
        *(float4*)(outp)     = make_float4(o[0], o[1], o[2], o[3]);
        *(float4*)(outp + 4) = make_float4(o[4], o[5], o[6], o[7]);
    }
}

// ---------------------------------------------------------------------------
// Kernel 3: normalize k rows (cols 0-63 of KVQZ): k /= (||k|| + 1e-6)
// ---------------------------------------------------------------------------
__global__ void __launch_bounds__(256) k_norm()
{
    const int row  = blockIdx.x * 8 + (threadIdx.x >> 5);
    const int lane = threadIdx.x & 31;
    float* kr = g_KVQZ + (size_t)row * 256 + lane * 2;
    float2 v = *(float2*)kr;
    float ss = v.x * v.x + v.y * v.y;
    #pragma unroll
    for (int m = 16; m >= 1; m >>= 1)
        ss += __shfl_xor_sync(0xffffffffu, ss, m);
    float inv = __fdividef(1.f, sqrtf(ss) + 1e-6f);
    v.x *= inv; v.y *= inv;
    *(float2*)kr = v;
}

// ---------------------------------------------------------------------------
// Kernel 4: sequential delta-rule scan.
// 8 blocks (1/batch) x 128 threads; 2 lanes/row, 32 state elems/lane as
// 16 x f32x2. ONE shfl in the recurrence chain (pair reduce). dq readout
// reduction software-pipelined into next step's pred shfl.
// k/q/v staged via cp.async 3-slot ring (8-step segments).
// ---------------------------------------------------------------------------
__global__ void __launch_bounds__(128, 1) k_scan()
{
    __shared__ __align__(16) float st[3 * 8 * 192];  // 3 slots x 8 steps x (k64,q64,v64)
    const int tid  = threadIdx.x;
    const int b    = blockIdx.x;
    const int grp  = tid & 1;               // half: elems grp*32..grp*32+31
    const int r    = tid >> 1;              // row 0..63
    const float* __restrict__ base = g_KVQZ + (size_t)b * 256;
    float* __restrict__ yout = g_Y + (size_t)b * NS + r;

    unsigned long long sp[16];
    #pragma unroll
    for (int i = 0; i < 16; i++) sp[i] = 0ull;

    const unsigned sbase = (unsigned)__cvta_generic_to_shared(st);

    auto refill = [&](int seg) {
        const int slot = seg % 3;
        const float* s0 = base + (size_t)seg * 8 * 2048;
        #pragma unroll
        for (int it = 0; it < 3; it++) {
            int c = tid + it * 128;                   // 0..383, 48 float4 per step
            int stp = c / 48, j = c - stp * 48;
            int soff, doff;
            if (j < 16)      { soff = j * 4;              doff = j * 4; }           // k
            else if (j < 32) { soff = 128 + (j - 16) * 4; doff = 64 + (j - 16) * 4; } // q
            else             { soff = 64 + (j - 32) * 4;  doff = 128 + (j - 32) * 4; } // v
            const float* gp = s0 + (size_t)stp * 2048 + soff;
            unsigned sa = sbase + (unsigned)(((slot * 8 + stp) * 192 + doff) * 4);
            asm volatile("cp.async.cg.shared.global [%0], [%1], 16;" :: "r"(sa), "l"(gp));
        }
        asm volatile("cp.async.commit_group;" ::);
    };

    refill(0);
    refill(1);

    float pend = 0.f;   // dq partial for previous step (per-lane)

    for (int seg = 0; seg < TT / 8; seg++) {
        asm volatile("cp.async.wait_group 1;" ::);
        __syncthreads();
        if (seg + 2 < TT / 8) refill(seg + 2);
        else asm volatile("cp.async.commit_group;" ::);

        const float* sl = st + (seg % 3) * 8 * 192;
        // load step-0 k (32 floats = 16 f32x2)
        unsigned long long kc[16];
        {
            const ulonglong2* kp = (const ulonglong2*)(sl + grp * 32);
            #pragma unroll
            for (int i = 0; i < 8; i++) {
                ulonglong2 w = kp[i];
                kc[2*i] = w.x; kc[2*i+1] = w.y;
            }
        }

        #pragma unroll
        for (int u = 0; u < 8; u++) {
            const float* sc = sl + u * 192;
            const int gt = seg * 8 + u;
            float vv = sc[128 + r];

            // q for this step
            unsigned long long qv[16];
            {
                const ulonglong2* qp = (const ulonglong2*)(sc + 64 + grp * 32);
                #pragma unroll
                for (int i = 0; i < 8; i++) {
                    ulonglong2 w = qp[i];
                    qv[2*i] = w.x; qv[2*i+1] = w.y;
                }
            }

            // pred partial = S[row, half] . k  (4 chains of depth 4)
            unsigned long long p0 = mul2(sp[0], kc[0]);
            unsigned long long p1 = mul2(sp[1], kc[1]);
            unsigned long long p2 = mul2(sp[2], kc[2]);
            unsigned long long p3 = mul2(sp[3], kc[3]);
            #pragma unroll
            for (int i = 1; i < 4; i++) {
                p0 = fma2(sp[4*i+0], kc[4*i+0], p0);
                p1 = fma2(sp[4*i+1], kc[4*i+1], p1);
                p2 = fma2(sp[4*i+2], kc[4*i+2], p2);
                p3 = fma2(sp[4*i+3], kc[4*i+3], p3);
            }
            p0 = add2(p0, p1); p2 = add2(p2, p3); p0 = add2(p0, p2);
            float plo, phi; unpk2(p0, plo, phi);
            float pp = plo + phi;

            // interleaved pair reductions: pred (this step) + dq (prev step)
            float a1 = __shfl_xor_sync(0xffffffffu, pp,   1);
            float b1 = __shfl_xor_sync(0xffffffffu, pend, 1);
            pp += a1;
            float dd = pend + b1;

            if (grp == 0 && gt > 0)
                yout[(size_t)(gt - 1) * (BB * NS)] = dd;   // raw dq; activation in k_act

            // delta-rule update
            float delta = vv - pp;
            unsigned long long dp = pk2(delta, delta);
            #pragma unroll
            for (int i = 0; i < 16; i++) sp[i] = fma2(dp, kc[i], sp[i]);

            // dq partial for this step (pended to next iteration)
            unsigned long long y0 = mul2(sp[0], qv[0]);
            unsigned long long y1 = mul2(sp[1], qv[1]);
            unsigned long long y2 = mul2(sp[2], qv[2]);
            unsigned long long y3 = mul2(sp[3], qv[3]);
            #pragma unroll
            for (int i = 1; i < 4; i++) {
                y0 = fma2(sp[4*i+0], qv[4*i+0], y0);
                y1 = fma2(sp[4*i+1], qv[4*i+1], y1);
                y2 = fma2(sp[4*i+2], qv[4*i+2], y2);
                y3 = fma2(sp[4*i+3], qv[4*i+3], y3);
            }
            y0 = add2(y0, y1); y2 = add2(y2, y3); y0 = add2(y0, y2);
            float ylo, yhi; unpk2(y0, ylo, yhi);
            pend = ylo + yhi;

            // prefetch next step's k (same slot; resident)
            if (u < 7) {
                const ulonglong2* kp = (const ulonglong2*)(sc + 192 + grp * 32);
                #pragma unroll
                for (int i = 0; i < 8; i++) {
                    ulonglong2 w = kp[i];
                    kc[2*i] = w.x; kc[2*i+1] = w.y;
                }
            }
        }
    }

    // flush last step's dq
    float b1 = __shfl_xor_sync(0xffffffffu, pend, 1);
    float dd = pend + b1;
    if (grp == 0) yout[(size_t)(TT - 1) * (BB * NS)] = dd;
}

// ---------------------------------------------------------------------------
// Kernel 4b: activation.  g_Y[m][n] = tanh(dq) * sigmoid(z),  z from g_KVQZ.
// ---------------------------------------------------------------------------
__global__ void __launch_bounds__(256) k_act()
{
    const int i = blockIdx.x * 256 + threadIdx.x;   // over MTOT*16 float4-quads
    const int m = i >> 4, n4 = (i & 15) * 4;
    float4 dq = *(const float4*)(g_Y + (size_t)m * NS + n4);
    float4 z  = *(const float4*)(g_KVQZ + (size_t)m * 256 + 192 + n4);
    float o[4]; float dqa[4] = {dq.x, dq.y, dq.z, dq.w};
    float za[4] = {z.x, z.y, z.z, z.w};
    #pragma unroll
    for (int j = 0; j < 4; j++) {
        float ax = fabsf(dqa[j]);
        float e  = __expf(-2.f * ax);
        float th = __fdividef(1.f - e, 1.f + e);
        th = copysignf(th, dqa[j]);
        float sg = __fdividef(1.f, 1.f + __expf(-za[j]));
        o[j] = th * sg;
    }
    *(float4*)(g_Y + (size_t)m * NS + n4) = make_float4(o[0], o[1], o[2], o[3]);
}

// ---------------------------------------------------------------------------
// Kernel 5: output projection (f32x2 packed FMA).
// Out[m][d] = sum_n Y[m][n] * Wout[d][n].  M=16384, N(=d)=1024, K(=n)=64.
// ---------------------------------------------------------------------------
__global__ void __launch_bounds__(256, 2) k_out(
    const float* __restrict__ Wout, float* __restrict__ Out)
{
    __shared__ __align__(16) float As[8][132];   // [k][m] from Y
    __shared__ __align__(16) float Bs[8][132];   // [k][d] from Wout (transposed on load)
    const int d0 = blockIdx.x * 128;
    const int m0 = blockIdx.y * 128;
    const int t  = threadIdx.x;
    const int tx = t & 15, ty = t >> 4;
    unsigned long long acc2[8][4];
    #pragma unroll
    for (int i = 0; i < 8; i++)
        #pragma unroll
        for (int j = 0; j < 4; j++) acc2[i][j] = 0ull;

    const int lm = t >> 1, lk = (t & 1) * 4;
    const int bd = t >> 1, bk = (t & 1) * 4;

    for (int k0 = 0; k0 < NS; k0 += 8) {
        float4 a = *(const float4*)(g_Y + (size_t)(m0 + lm) * NS + k0 + lk);
        As[lk+0][lm] = a.x; As[lk+1][lm] = a.y; As[lk+2][lm] = a.z; As[lk+3][lm] = a.w;
        float4 w = *(const float4*)(Wout + (size_t)(d0 + bd) * NS + k0 + bk);
        Bs[bk+0][bd] = w.x; Bs[bk+1][bd] = w.y; Bs[bk+2][bd] = w.z; Bs[bk+3][bd] = w.w;
        __syncthreads();
        #pragma unroll
        for (int k = 0; k < 8; k++) {
            float av[8];
            *(float4*)&av[0] = *(const float4*)&As[k][ty*8];
            *(float4*)&av[4] = *(const float4*)&As[k][ty*8 + 4];
            const ulonglong2* bq = (const ulonglong2*)&Bs[k][tx*8];
            ulonglong2 b01 = bq[0], b23 = bq[1];
            unsigned long long bp[4] = {b01.x, b01.y, b23.x, b23.y};
            #pragma unroll
            for (int i = 0; i < 8; i++) {
                unsigned long long ai = pk2(av[i], av[i]);
                #pragma unroll
                for (int j = 0; j < 4; j++)
                    acc2[i][j] = fma2(ai, bp[j], acc2[i][j]);
            }
        }
        __syncthreads();
    }
    #pragma unroll
    for (int i = 0; i < 8; i++) {
        float o[8];
        #pragma unroll
        for (int j = 0; j < 4; j++) unpk2(acc2[i][j], o[2*j], o[2*j+1]);
        float* outp = Out + (size_t)(m0 + ty*8 + i) * DM + d0 + tx*8;
        *(float4*)(outp)     = make_float4(o[0], o[1], o[2], o[3]);
        *(float4*)(outp + 4) = make_float4(o[4], o[5], o[6], o[7]);
    }
}

// ---------------------------------------------------------------------------
extern "C" void kernel_launch(void* const* d_in, const int* in_sizes, int n_in,
                              void* d_out, int out_size)
{
    const float* x    = (const float*)d_in[0];  // [2048, 8, 1024]
    const float* Win  = (const float*)d_in[1];  // [2048, 1024]
    const float* Wk   = (const float*)d_in[2];  // [64, 2048]
    const float* Wv   = (const float*)d_in[3];
    const float* Wq   = (const float*)d_in[4];
    const float* Wz   = (const float*)d_in[5];
    const float* Wout = (const float*)d_in[6];  // [1024, 64]
    float* out = (float*)d_out;                 // [2048, 8, 1024]

    k_fuse<<<dim3(16, 4),   256>>>(Win, Wk, Wv, Wq, Wz);
    k_proj<<<dim3(2, 128),  256>>>(x);
    k_norm<<<2048,          256>>>();
    k_scan<<<8,             128>>>();
    k_act <<<1024,          256>>>();
    k_out <<<dim3(8, 128),  256>>>(Wout, out);
}

// round 6
// speedup vs baseline: 1.4524x; 1.0015x over previous
#include <cuda_runtime.h>
#include <math.h>

#define TT 2048
#define BB 8
#define DM 1024
#define DI 2048
#define NS 64
#define MTOT (TT*BB)   /* 16384 token-batch rows */

// Scratch (static __device__ globals: no allocation in kernel_launch)
__device__ float g_WfT[DM * 256];                   // [1024][256]  fused weights, transposed
__device__ float g_KVQZ[(size_t)MTOT * 256];        // [16384][256] cols: 0-63 k, 64-127 v, 128-191 q, 192-255 z
__device__ float g_Y[(size_t)MTOT * NS];            // [16384][64]  raw dq from scan, then activated in-place

// ---------------- packed f32x2 helpers ----------------
__device__ __forceinline__ unsigned long long pk2(float lo, float hi) {
    unsigned long long r;
    asm("mov.b64 %0, {%1, %2};" : "=l"(r) : "f"(lo), "f"(hi));
    return r;
}
__device__ __forceinline__ void unpk2(unsigned long long v, float& lo, float& hi) {
    asm("mov.b64 {%0, %1}, %2;" : "=f"(lo), "=f"(hi) : "l"(v));
}
__device__ __forceinline__ unsigned long long fma2(unsigned long long a,
                                                   unsigned long long b,
                                                   unsigned long long c) {
    unsigned long long d;
    asm("fma.rn.f32x2 %0, %1, %2, %3;" : "=l"(d) : "l"(a), "l"(b), "l"(c));
    return d;
}
__device__ __forceinline__ unsigned long long mul2(unsigned long long a,
                                                   unsigned long long b) {
    unsigned long long d;
    asm("mul.rn.f32x2 %0, %1, %2;" : "=l"(d) : "l"(a), "l"(b));
    return d;
}
__device__ __forceinline__ unsigned long long add2(unsigned long long a,
                                                   unsigned long long b) {
    unsigned long long d;
    asm("add.rn.f32x2 %0, %1, %2;" : "=l"(d) : "l"(a), "l"(b));
    return d;
}

// ---------------------------------------------------------------------------
// Kernel 1: fused weights.  WfT[d][r] = sum_i Wsel[r][i] * Win[i][d]
// ---------------------------------------------------------------------------
__global__ void __launch_bounds__(256) k_fuse(
    const float* __restrict__ Win, const float* __restrict__ Wk,
    const float* __restrict__ Wv,  const float* __restrict__ Wq,
    const float* __restrict__ Wz)
{
    __shared__ float As[16][65];   // [k][m]
    __shared__ float Bs[16][68];   // [k][d]
    const int d0 = blockIdx.x * 64;
    const int m0 = blockIdx.y * 64;
    const int t  = threadIdx.x;
    const int tx = t & 15, ty = t >> 4;
    float acc[4][4] = {};

    const int lm = t >> 2, lk = (t & 3) * 4;
    const int r  = m0 + lm;
    const float* W = (r < 64) ? Wk : (r < 128) ? Wv : (r < 192) ? Wq : Wz;
    const float* arow = W + (size_t)(r & 63) * DI;
    const int bk = t >> 4, bd = (t & 15) * 4;

    for (int k0 = 0; k0 < DI; k0 += 16) {
        float4 a = *(const float4*)(arow + k0 + lk);
        As[lk+0][lm] = a.x; As[lk+1][lm] = a.y; As[lk+2][lm] = a.z; As[lk+3][lm] = a.w;
        float4 b = *(const float4*)(Win + (size_t)(k0 + bk) * DM + d0 + bd);
        *(float4*)&Bs[bk][bd] = b;
        __syncthreads();
        #pragma unroll
        for (int k = 0; k < 16; k++) {
            float av[4];
            #pragma unroll
            for (int i = 0; i < 4; i++) av[i] = As[k][ty*4 + i];
            float4 bv = *(const float4*)&Bs[k][tx*4];
            float bb4[4] = {bv.x, bv.y, bv.z, bv.w};
            #pragma unroll
            for (int i = 0; i < 4; i++)
                #pragma unroll
                for (int j = 0; j < 4; j++)
                    acc[i][j] = fmaf(av[i], bb4[j], acc[i][j]);
        }
        __syncthreads();
    }
    #pragma unroll
    for (int i = 0; i < 4; i++)
        #pragma unroll
        for (int j = 0; j < 4; j++)
            g_WfT[(size_t)(d0 + tx*4 + j) * 256 + (m0 + ty*4 + i)] = acc[i][j];
}

// ---------------------------------------------------------------------------
// Kernel 2: projection GEMM (f32x2 packed FMA).  [R3 form — faster than
// duplicated-A variant per R4 measurement]
// KVQZ[m][n] = sum_d X[m][d] * WfT[d][n].  M=16384, N=256, K=1024.
// ---------------------------------------------------------------------------
__global__ void __launch_bounds__(256, 2) k_proj(const float* __restrict__ X)
{
    __shared__ __align__(16) float As[8][132];   // [k][m]
    __shared__ __align__(16) float Bs[8][132];   // [k][n]
    const int n0 = blockIdx.x * 128;
    const int m0 = blockIdx.y * 128;
    const int t  = threadIdx.x;
    const int tx = t & 15, ty = t >> 4;
    unsigned long long acc2[8][4];
    #pragma unroll
    for (int i = 0; i < 8; i++)
        #pragma unroll
        for (int j = 0; j < 4; j++) acc2[i][j] = 0ull;

    const int lm = t >> 1, lk = (t & 1) * 4;
    const int bk = t >> 5, bn = (t & 31) * 4;
    const float* arow = X + (size_t)(m0 + lm) * DM + lk;
    const float* brow = g_WfT + (size_t)bk * 256 + n0 + bn;

    for (int k0 = 0; k0 < DM; k0 += 8) {
        float4 a = *(const float4*)(arow + k0);
        As[lk+0][lm] = a.x; As[lk+1][lm] = a.y; As[lk+2][lm] = a.z; As[lk+3][lm] = a.w;
        float4 b = *(const float4*)(brow + (size_t)k0 * 256);
        *(float4*)&Bs[bk][bn] = b;
        __syncthreads();
        #pragma unroll
        for (int k = 0; k < 8; k++) {
            float av[8];
            *(float4*)&av[0] = *(const float4*)&As[k][ty*8];
            *(float4*)&av[4] = *(const float4*)&As[k][ty*8 + 4];
            const ulonglong2* bq = (const ulonglong2*)&Bs[k][tx*8];
            ulonglong2 b01 = bq[0], b23 = bq[1];
            unsigned long long bp[4] = {b01.x, b01.y, b23.x, b23.y};
            #pragma unroll
            for (int i = 0; i < 8; i++) {
                unsigned long long ai = pk2(av[i], av[i]);
                #pragma unroll
                for (int j = 0; j < 4; j++)
                    acc2[i][j] = fma2(ai, bp[j], acc2[i][j]);
            }
        }
        __syncthreads();
    }
    #pragma unroll
    for (int i = 0; i < 8; i++) {
        float o[8];
        #pragma unroll
        for (int j = 0; j < 4; j++) unpk2(acc2[i][j], o[2*j], o[2*j+1]);
        float* outp = g_KVQZ + (size_t)(m0 + ty*8 + i) * 256 + n0 + tx*8;
        *(float4*)(outp)     = make_float4(o[0], o[1], o[2], o[3]);
        *(float4*)(outp + 4) = make_float4(o[4], o[5], o[6], o[7]);
    }
}

// ---------------------------------------------------------------------------
// Kernel 3: normalize k rows (cols 0-63 of KVQZ): k /= (||k|| + 1e-6)
// ---------------------------------------------------------------------------
__global__ void __launch_bounds__(256) k_norm()
{
    const int row  = blockIdx.x * 8 + (threadIdx.x >> 5);
    const int lane = threadIdx.x & 31;
    float* kr = g_KVQZ + (size_t)row * 256 + lane * 2;
    float2 v = *(float2*)kr;
    float ss = v.x * v.x + v.y * v.y;
    #pragma unroll
    for (int m = 16; m >= 1; m >>= 1)
        ss += __shfl_xor_sync(0xffffffffu, ss, m);
    float inv = __fdividef(1.f, sqrtf(ss) + 1e-6f);
    v.x *= inv; v.y *= inv;
    *(float2*)kr = v;
}

// ---------------------------------------------------------------------------
// Kernel 4: sequential delta-rule scan.
// 8 blocks (1/batch) x 128 threads; 2 lanes/row, 32 state elems/lane as
// 16 x f32x2. ONE shfl in the recurrence chain (pair reduce). dq readout
// reduction software-pipelined into next step's pred shfl.
// k/q/v staged via cp.async 3-slot ring (8-step segments).
// ---------------------------------------------------------------------------
__global__ void __launch_bounds__(128, 1) k_scan()
{
    __shared__ __align__(16) float st[3 * 8 * 192];  // 3 slots x 8 steps x (k64,q64,v64)
    const int tid  = threadIdx.x;
    const int b    = blockIdx.x;
    const int grp  = tid & 1;               // half: elems grp*32..grp*32+31
    const int r    = tid >> 1;              // row 0..63
    const float* __restrict__ base = g_KVQZ + (size_t)b * 256;
    float* __restrict__ yout = g_Y + (size_t)b * NS + r;

    unsigned long long sp[16];
    #pragma unroll
    for (int i = 0; i < 16; i++) sp[i] = 0ull;

    const unsigned sbase = (unsigned)__cvta_generic_to_shared(st);

    auto refill = [&](int seg) {
        const int slot = seg % 3;
        const float* s0 = base + (size_t)seg * 8 * 2048;
        #pragma unroll
        for (int it = 0; it < 3; it++) {
            int c = tid + it * 128;                   // 0..383, 48 float4 per step
            int stp = c / 48, j = c - stp * 48;
            int soff, doff;
            if (j < 16)      { soff = j * 4;              doff = j * 4; }           // k
            else if (j < 32) { soff = 128 + (j - 16) * 4; doff = 64 + (j - 16) * 4; } // q
            else             { soff = 64 + (j - 32) * 4;  doff = 128 + (j - 32) * 4; } // v
            const float* gp = s0 + (size_t)stp * 2048 + soff;
            unsigned sa = sbase + (unsigned)(((slot * 8 + stp) * 192 + doff) * 4);
            asm volatile("cp.async.cg.shared.global [%0], [%1], 16;" :: "r"(sa), "l"(gp));
        }
        asm volatile("cp.async.commit_group;" ::);
    };

    refill(0);
    refill(1);

    float pend = 0.f;   // dq partial for previous step (per-lane)

    for (int seg = 0; seg < TT / 8; seg++) {
        asm volatile("cp.async.wait_group 1;" ::);
        __syncthreads();
        if (seg + 2 < TT / 8) refill(seg + 2);
        else asm volatile("cp.async.commit_group;" ::);

        const float* sl = st + (seg % 3) * 8 * 192;
        // load step-0 k (32 floats = 16 f32x2)
        unsigned long long kc[16];
        {
            const ulonglong2* kp = (const ulonglong2*)(sl + grp * 32);
            #pragma unroll
            for (int i = 0; i < 8; i++) {
                ulonglong2 w = kp[i];
                kc[2*i] = w.x; kc[2*i+1] = w.y;
            }
        }

        #pragma unroll
        for (int u = 0; u < 8; u++) {
            const float* sc = sl + u * 192;
            const int gt = seg * 8 + u;
            float vv = sc[128 + r];

            // q for this step
            unsigned long long qv[16];
            {
                const ulonglong2* qp = (const ulonglong2*)(sc + 64 + grp * 32);
                #pragma unroll
                for (int i = 0; i < 8; i++) {
                    ulonglong2 w = qp[i];
                    qv[2*i] = w.x; qv[2*i+1] = w.y;
                }
            }

            // pred partial = S[row, half] . k  (4 chains of depth 4)
            unsigned long long p0 = mul2(sp[0], kc[0]);
            unsigned long long p1 = mul2(sp[1], kc[1]);
            unsigned long long p2 = mul2(sp[2], kc[2]);
            unsigned long long p3 = mul2(sp[3], kc[3]);
            #pragma unroll
            for (int i = 1; i < 4; i++) {
                p0 = fma2(sp[4*i+0], kc[4*i+0], p0);
                p1 = fma2(sp[4*i+1], kc[4*i+1], p1);
                p2 = fma2(sp[4*i+2], kc[4*i+2], p2);
                p3 = fma2(sp[4*i+3], kc[4*i+3], p3);
            }
            p0 = add2(p0, p1); p2 = add2(p2, p3); p0 = add2(p0, p2);
            float plo, phi; unpk2(p0, plo, phi);
            float pp = plo + phi;

            // interleaved pair reductions: pred (this step) + dq (prev step)
            float a1 = __shfl_xor_sync(0xffffffffu, pp,   1);
            float b1 = __shfl_xor_sync(0xffffffffu, pend, 1);
            pp += a1;
            float dd = pend + b1;

            if (grp == 0 && gt > 0)
                yout[(size_t)(gt - 1) * (BB * NS)] = dd;   // raw dq; activation in k_act

            // delta-rule update
            float delta = vv - pp;
            unsigned long long dp = pk2(delta, delta);
            #pragma unroll
            for (int i = 0; i < 16; i++) sp[i] = fma2(dp, kc[i], sp[i]);

            // dq partial for this step (pended to next iteration)
            unsigned long long y0 = mul2(sp[0], qv[0]);
            unsigned long long y1 = mul2(sp[1], qv[1]);
            unsigned long long y2 = mul2(sp[2], qv[2]);
            unsigned long long y3 = mul2(sp[3], qv[3]);
            #pragma unroll
            for (int i = 1; i < 4; i++) {
                y0 = fma2(sp[4*i+0], qv[4*i+0], y0);
                y1 = fma2(sp[4*i+1], qv[4*i+1], y1);
                y2 = fma2(sp[4*i+2], qv[4*i+2], y2);
                y3 = fma2(sp[4*i+3], qv[4*i+3], y3);
            }
            y0 = add2(y0, y1); y2 = add2(y2, y3); y0 = add2(y0, y2);
            float ylo, yhi; unpk2(y0, ylo, yhi);
            pend = ylo + yhi;

            // prefetch next step's k (same slot; resident)
            if (u < 7) {
                const ulonglong2* kp = (const ulonglong2*)(sc + 192 + grp * 32);
                #pragma unroll
                for (int i = 0; i < 8; i++) {
                    ulonglong2 w = kp[i];
                    kc[2*i] = w.x; kc[2*i+1] = w.y;
                }
            }
        }
    }

    // flush last step's dq
    float b1 = __shfl_xor_sync(0xffffffffu, pend, 1);
    float dd = pend + b1;
    if (grp == 0) yout[(size_t)(TT - 1) * (BB * NS)] = dd;
}

// ---------------------------------------------------------------------------
// Kernel 4b: activation.  g_Y[m][n] = tanh(dq) * sigmoid(z),  z from g_KVQZ.
// ---------------------------------------------------------------------------
__global__ void __launch_bounds__(256) k_act()
{
    const int i = blockIdx.x * 256 + threadIdx.x;   // over MTOT*16 float4-quads
    const int m = i >> 4, n4 = (i & 15) * 4;
    float4 dq = *(const float4*)(g_Y + (size_t)m * NS + n4);
    float4 z  = *(const float4*)(g_KVQZ + (size_t)m * 256 + 192 + n4);
    float o[4]; float dqa[4] = {dq.x, dq.y, dq.z, dq.w};
    float za[4] = {z.x, z.y, z.z, z.w};
    #pragma unroll
    for (int j = 0; j < 4; j++) {
        float ax = fabsf(dqa[j]);
        float e  = __expf(-2.f * ax);
        float th = __fdividef(1.f - e, 1.f + e);
        th = copysignf(th, dqa[j]);
        float sg = __fdividef(1.f, 1.f + __expf(-za[j]));
        o[j] = th * sg;
    }
    *(float4*)(g_Y + (size_t)m * NS + n4) = make_float4(o[0], o[1], o[2], o[3]);
}

// ---------------------------------------------------------------------------
// Kernel 5: output projection (f32x2 packed FMA).
// Out[m][d] = sum_n Y[m][n] * Wout[d][n].  M=16384, N(=d)=1024, K(=n)=64.
// ---------------------------------------------------------------------------
__global__ void __launch_bounds__(256, 2) k_out(
    const float* __restrict__ Wout, float* __restrict__ Out)
{
    __shared__ __align__(16) float As[8][132];   // [k][m] from Y
    __shared__ __align__(16) float Bs[8][132];   // [k][d] from Wout (transposed on load)
    const int d0 = blockIdx.x * 128;
    const int m0 = blockIdx.y * 128;
    const int t  = threadIdx.x;
    const int tx = t & 15, ty = t >> 4;
    unsigned long long acc2[8][4];
    #pragma unroll
    for (int i = 0; i < 8; i++)
        #pragma unroll
        for (int j = 0; j < 4; j++) acc2[i][j] = 0ull;

    const int lm = t >> 1, lk = (t & 1) * 4;
    const int bd = t >> 1, bk = (t & 1) * 4;

    for (int k0 = 0; k0 < NS; k0 += 8) {
        float4 a = *(const float4*)(g_Y + (size_t)(m0 + lm) * NS + k0 + lk);
        As[lk+0][lm] = a.x; As[lk+1][lm] = a.y; As[lk+2][lm] = a.z; As[lk+3][lm] = a.w;
        float4 w = *(const float4*)(Wout + (size_t)(d0 + bd) * NS + k0 + bk);
        Bs[bk+0][bd] = w.x; Bs[bk+1][bd] = w.y; Bs[bk+2][bd] = w.z; Bs[bk+3][bd] = w.w;
        __syncthreads();
        #pragma unroll
        for (int k = 0; k < 8; k++) {
            float av[8];
            *(float4*)&av[0] = *(const float4*)&As[k][ty*8];
            *(float4*)&av[4] = *(const float4*)&As[k][ty*8 + 4];
            const ulonglong2* bq = (const ulonglong2*)&Bs[k][tx*8];
            ulonglong2 b01 = bq[0], b23 = bq[1];
            unsigned long long bp[4] = {b01.x, b01.y, b23.x, b23.y};
            #pragma unroll
            for (int i = 0; i < 8; i++) {
                unsigned long long ai = pk2(av[i], av[i]);
                #pragma unroll
                for (int j = 0; j < 4; j++)
                    acc2[i][j] = fma2(ai, bp[j], acc2[i][j]);
            }
        }
        __syncthreads();
    }
    #pragma unroll
    for (int i = 0; i < 8; i++) {
        float o[8];
        #pragma unroll
        for (int j = 0; j < 4; j++) unpk2(acc2[i][j], o[2*j], o[2*j+1]);
        float* outp = Out + (size_t)(m0 + ty*8 + i) * DM + d0 + tx*8;
        *(float4*)(outp)     = make_float4(o[0], o[1], o[2], o[3]);
        *(float4*)(outp + 4) = make_float4(o[4], o[5], o[6], o[7]);
    }
}

// ---------------------------------------------------------------------------
extern "C" void kernel_launch(void* const* d_in, const int* in_sizes, int n_in,
                              void* d_out, int out_size)
{
    const float* x    = (const float*)d_in[0];  // [2048, 8, 1024]
    const float* Win  = (const float*)d_in[1];  // [2048, 1024]
    const float* Wk   = (const float*)d_in[2];  // [64, 2048]
    const float* Wv   = (const float*)d_in[3];
    const float* Wq   = (const float*)d_in[4];
    const float* Wz   = (const float*)d_in[5];
    const float* Wout = (const float*)d_in[6];  // [1024, 64]
    float* out = (float*)d_out;                 // [2048, 8, 1024]

    k_fuse<<<dim3(16, 4),   256>>>(Win, Wk, Wv, Wq, Wz);
    k_proj<<<dim3(2, 128),  256>>>(x);
    k_norm<<<2048,          256>>>();
    k_scan<<<8,             128>>>();
    k_act <<<1024,          256>>>();
    k_out <<<dim3(8, 128),  256>>>(Wout, out);
}

// round 7
// speedup vs baseline: 1.8265x; 1.2575x over previous
#include <cuda_runtime.h>
#include <math.h>

#define TT 2048
#define BB 8
#define DM 1024
#define DI 2048
#define NS 64
#define MTOT (TT*BB)
#define NCH 32
#define NTILE 256

__device__ float g_WfT[DM * 256];
__device__ float g_KVQZ[(size_t)MTOT * 256];   // 0-63 k, 64-127 v, 128-191 q, 192-255 z
__device__ float g_Y[(size_t)MTOT * NS];       // raw dq, activated in place
__device__ float g_TK [(size_t)NTILE * 4096];  // [tile][t*64+m]   T*K
__device__ float g_TVT[(size_t)NTILE * 4096];  // [tile][n*64+t]   (T*V)^T
__device__ float g_M  [(size_t)NTILE * 4096];  // [tile][t*64+j]   tril(QK^T) incl diag

typedef unsigned long long ull;
__device__ __forceinline__ ull pk2(float lo, float hi) {
    ull r; asm("mov.b64 %0, {%1, %2};" : "=l"(r) : "f"(lo), "f"(hi)); return r;
}
__device__ __forceinline__ void unpk2(ull v, float& lo, float& hi) {
    asm("mov.b64 {%0, %1}, %2;" : "=f"(lo), "=f"(hi) : "l"(v));
}
__device__ __forceinline__ ull fma2(ull a, ull b, ull c) {
    ull d; asm("fma.rn.f32x2 %0, %1, %2, %3;" : "=l"(d) : "l"(a), "l"(b), "l"(c)); return d;
}

// ---------------------------------------------------------------------------
__global__ void __launch_bounds__(256) k_fuse(
    const float* __restrict__ Win, const float* __restrict__ Wk,
    const float* __restrict__ Wv,  const float* __restrict__ Wq,
    const float* __restrict__ Wz)
{
    __shared__ float As[16][65];
    __shared__ float Bs[16][68];
    const int d0 = blockIdx.x * 64, m0 = blockIdx.y * 64;
    const int t = threadIdx.x, tx = t & 15, ty = t >> 4;
    float acc[4][4] = {};
    const int lm = t >> 2, lk = (t & 3) * 4;
    const int r = m0 + lm;
    const float* W = (r < 64) ? Wk : (r < 128) ? Wv : (r < 192) ? Wq : Wz;
    const float* arow = W + (size_t)(r & 63) * DI;
    const int bk = t >> 4, bd = (t & 15) * 4;
    for (int k0 = 0; k0 < DI; k0 += 16) {
        float4 a = *(const float4*)(arow + k0 + lk);
        As[lk+0][lm] = a.x; As[lk+1][lm] = a.y; As[lk+2][lm] = a.z; As[lk+3][lm] = a.w;
        float4 b = *(const float4*)(Win + (size_t)(k0 + bk) * DM + d0 + bd);
        *(float4*)&Bs[bk][bd] = b;
        __syncthreads();
        #pragma unroll
        for (int k = 0; k < 16; k++) {
            float av[4];
            #pragma unroll
            for (int i = 0; i < 4; i++) av[i] = As[k][ty*4 + i];
            float4 bv = *(const float4*)&Bs[k][tx*4];
            float bb4[4] = {bv.x, bv.y, bv.z, bv.w};
            #pragma unroll
            for (int i = 0; i < 4; i++)
                #pragma unroll
                for (int j = 0; j < 4; j++)
                    acc[i][j] = fmaf(av[i], bb4[j], acc[i][j]);
        }
        __syncthreads();
    }
    #pragma unroll
    for (int i = 0; i < 4; i++)
        #pragma unroll
        for (int j = 0; j < 4; j++)
            g_WfT[(size_t)(d0 + tx*4 + j) * 256 + (m0 + ty*4 + i)] = acc[i][j];
}

// ---------------------------------------------------------------------------
__global__ void __launch_bounds__(256, 2) k_proj(const float* __restrict__ X)
{
    __shared__ __align__(16) float As[8][132];
    __shared__ __align__(16) float Bs[8][132];
    const int n0 = blockIdx.x * 128, m0 = blockIdx.y * 128;
    const int t = threadIdx.x, tx = t & 15, ty = t >> 4;
    ull acc2[8][4];
    #pragma unroll
    for (int i = 0; i < 8; i++)
        #pragma unroll
        for (int j = 0; j < 4; j++) acc2[i][j] = 0ull;
    const int lm = t >> 1, lk = (t & 1) * 4;
    const int bk = t >> 5, bn = (t & 31) * 4;
    const float* arow = X + (size_t)(m0 + lm) * DM + lk;
    const float* brow = g_WfT + (size_t)bk * 256 + n0 + bn;
    for (int k0 = 0; k0 < DM; k0 += 8) {
        float4 a = *(const float4*)(arow + k0);
        As[lk+0][lm] = a.x; As[lk+1][lm] = a.y; As[lk+2][lm] = a.z; As[lk+3][lm] = a.w;
        float4 b = *(const float4*)(brow + (size_t)k0 * 256);
        *(float4*)&Bs[bk][bn] = b;
        __syncthreads();
        #pragma unroll
        for (int k = 0; k < 8; k++) {
            float av[8];
            *(float4*)&av[0] = *(const float4*)&As[k][ty*8];
            *(float4*)&av[4] = *(const float4*)&As[k][ty*8 + 4];
            const ulonglong2* bq = (const ulonglong2*)&Bs[k][tx*8];
            ulonglong2 b01 = bq[0], b23 = bq[1];
            ull bp[4] = {b01.x, b01.y, b23.x, b23.y};
            #pragma unroll
            for (int i = 0; i < 8; i++) {
                ull ai = pk2(av[i], av[i]);
                #pragma unroll
                for (int j = 0; j < 4; j++)
                    acc2[i][j] = fma2(ai, bp[j], acc2[i][j]);
            }
        }
        __syncthreads();
    }
    #pragma unroll
    for (int i = 0; i < 8; i++) {
        float o[8];
        #pragma unroll
        for (int j = 0; j < 4; j++) unpk2(acc2[i][j], o[2*j], o[2*j+1]);
        float* outp = g_KVQZ + (size_t)(m0 + ty*8 + i) * 256 + n0 + tx*8;
        *(float4*)(outp)     = make_float4(o[0], o[1], o[2], o[3]);
        *(float4*)(outp + 4) = make_float4(o[4], o[5], o[6], o[7]);
    }
}

// ---------------------------------------------------------------------------
__global__ void __launch_bounds__(256) k_norm()
{
    const int row = blockIdx.x * 8 + (threadIdx.x >> 5);
    const int lane = threadIdx.x & 31;
    float* kr = g_KVQZ + (size_t)row * 256 + lane * 2;
    float2 v = *(float2*)kr;
    float ss = v.x * v.x + v.y * v.y;
    #pragma unroll
    for (int m = 16; m >= 1; m >>= 1)
        ss += __shfl_xor_sync(0xffffffffu, ss, m);
    float inv = __fdividef(1.f, sqrtf(ss) + 1e-6f);
    v.x *= inv; v.y *= inv;
    *(float2*)kr = v;
}

// ---------------------------------------------------------------------------
// k_pre: per (batch,chunk) WY precompute, fully parallel over 256 tiles.
// smem: Ks,Vs,Qs,A,N each [64][68].
// ---------------------------------------------------------------------------
__global__ void __launch_bounds__(256) k_pre()
{
    extern __shared__ float sm[];
    float* Ks = sm;
    float* Vs = sm + 4352;
    float* Qs = sm + 8704;
    float* Aa = sm + 13056;
    float* Nn = sm + 17408;

    const int tile = blockIdx.x;
    const int b = tile & 7, c = tile >> 3;
    const int tid = threadIdx.x;

    for (int i = tid; i < 3072; i += 256) {
        int mat = i >> 10, r = i & 1023, t = r >> 4, q = (r & 15) * 4;
        const float* src = g_KVQZ + ((size_t)((c*64+t)*8+b)) * 256 + mat * 64 + q;
        float* dst = (mat == 0 ? Ks : mat == 1 ? Vs : Qs) + t * 68 + q;
        *(float4*)dst = *(const float4*)src;
    }
    for (int i = tid; i < 4352; i += 256) Nn[i] = 0.f;
    __syncthreads();

    const int ty = tid >> 4, tx = tid & 15;
    const int t0 = ty * 4, j0 = tx * 4;

    // A = K K^T
    {
        ull acc[4][4];
        #pragma unroll
        for (int i = 0; i < 4; i++)
            #pragma unroll
            for (int j = 0; j < 4; j++) acc[i][j] = 0ull;
        for (int m2 = 0; m2 < 32; m2++) {
            ull kt[4], kj[4];
            #pragma unroll
            for (int i = 0; i < 4; i++) kt[i] = *(const ull*)(Ks + (t0+i)*68 + 2*m2);
            #pragma unroll
            for (int j = 0; j < 4; j++) kj[j] = *(const ull*)(Ks + (j0+j)*68 + 2*m2);
            #pragma unroll
            for (int i = 0; i < 4; i++)
                #pragma unroll
                for (int j = 0; j < 4; j++) acc[i][j] = fma2(kt[i], kj[j], acc[i][j]);
        }
        #pragma unroll
        for (int i = 0; i < 4; i++)
            #pragma unroll
            for (int j = 0; j < 4; j++) {
                float lo, hi; unpk2(acc[i][j], lo, hi);
                Aa[(t0+i)*68 + j0+j] = lo + hi;
            }
    }
    // M = tril(Q K^T) incl diag -> global
    {
        ull acc[4][4];
        #pragma unroll
        for (int i = 0; i < 4; i++)
            #pragma unroll
            for (int j = 0; j < 4; j++) acc[i][j] = 0ull;
        for (int m2 = 0; m2 < 32; m2++) {
            ull qt[4], kj[4];
            #pragma unroll
            for (int i = 0; i < 4; i++) qt[i] = *(const ull*)(Qs + (t0+i)*68 + 2*m2);
            #pragma unroll
            for (int j = 0; j < 4; j++) kj[j] = *(const ull*)(Ks + (j0+j)*68 + 2*m2);
            #pragma unroll
            for (int i = 0; i < 4; i++)
                #pragma unroll
                for (int j = 0; j < 4; j++) acc[i][j] = fma2(qt[i], kj[j], acc[i][j]);
        }
        #pragma unroll
        for (int i = 0; i < 4; i++)
            #pragma unroll
            for (int j = 0; j < 4; j++) {
                float lo, hi; unpk2(acc[i][j], lo, hi);
                g_M[(size_t)tile*4096 + (t0+i)*64 + j0+j] =
                    (j0+j <= t0+i) ? (lo + hi) : 0.f;
            }
    }
    __syncthreads();

    // N: (I+L)^{-1} = I + N, row-by-row forward substitution
    for (int i = 1; i < 64; i++) {
        if (tid < i) {
            float s = -Aa[i*68 + tid];
            for (int p = tid + 1; p < i; p++)
                s = fmaf(-Aa[i*68 + p], Nn[p*68 + tid], s);
            Nn[i*68 + tid] = s;
        }
        __syncthreads();
    }

    // TK = K + N K
    {
        float acc[4][4] = {};
        for (int jj = 0; jj < 64; jj++) {
            float nt[4], kv[4];
            #pragma unroll
            for (int i = 0; i < 4; i++) nt[i] = Nn[(t0+i)*68 + jj];
            #pragma unroll
            for (int j = 0; j < 4; j++) kv[j] = Ks[jj*68 + j0+j];
            #pragma unroll
            for (int i = 0; i < 4; i++)
                #pragma unroll
                for (int j = 0; j < 4; j++) acc[i][j] = fmaf(nt[i], kv[j], acc[i][j]);
        }
        #pragma unroll
        for (int i = 0; i < 4; i++)
            #pragma unroll
            for (int j = 0; j < 4; j++)
                g_TK[(size_t)tile*4096 + (t0+i)*64 + j0+j] =
                    Ks[(t0+i)*68 + j0+j] + acc[i][j];
    }
    // TVT[n][t] = V[t][n] + (N V)[t][n]
    {
        float acc[4][4] = {};
        for (int jj = 0; jj < 64; jj++) {
            float nt[4], vv[4];
            #pragma unroll
            for (int i = 0; i < 4; i++) nt[i] = Nn[(t0+i)*68 + jj];
            #pragma unroll
            for (int j = 0; j < 4; j++) vv[j] = Vs[jj*68 + j0+j];
            #pragma unroll
            for (int i = 0; i < 4; i++)
                #pragma unroll
                for (int j = 0; j < 4; j++) acc[i][j] = fmaf(nt[i], vv[j], acc[i][j]);
        }
        #pragma unroll
        for (int i = 0; i < 4; i++)
            #pragma unroll
            for (int j = 0; j < 4; j++)
                g_TVT[(size_t)tile*4096 + (j0+j)*64 + (t0+i)] =
                    Vs[(t0+i)*68 + j0+j] + acc[i][j];
    }
}

// ---------------------------------------------------------------------------
// k_wy: sequential chunk recurrence. 64 blocks = 8 batches x 8 n-groups(8).
// smem: TKQ[2] (TK[64][68]+Q[64][68]) | M[64][68] | K[64][68] | TV[8][68]
//       | S2[8][66] | D[8][66].   S lives in registers (1 f32x2/thread).
// ---------------------------------------------------------------------------
__global__ void __launch_bounds__(256, 1) k_wy()
{
    extern __shared__ float sm[];
    const int tid = threadIdx.x;
    const int b  = blockIdx.x >> 3;
    const int n0 = (blockIdx.x & 7) * 8;
    const int tt = tid >> 4, mh = (tid >> 3) & 1, tn = tid & 7;
    const int t0 = tt * 4;
    const int cn = tid >> 5, cm2 = tid & 31;

    float* Ms  = sm + 17408;
    float* Kc  = sm + 21760;
    float* TVs = sm + 26112;
    float* S2  = sm + 26656;
    float* Ds  = sm + 27184;
    const unsigned sb = (unsigned)__cvta_generic_to_shared(sm);

    ull sreg = 0ull;

    for (int i = tid; i < 1024; i += 256) {   // prologue: TKQ(0)
        int t = i >> 4, q = (i & 15) * 4;
        asm volatile("cp.async.cg.shared.global [%0], [%1], 16;" ::
            "r"(sb + (unsigned)((t*68 + q) * 4)),
            "l"(g_TK + (size_t)(0*8+b)*4096 + t*64 + q));
        asm volatile("cp.async.cg.shared.global [%0], [%1], 16;" ::
            "r"(sb + (unsigned)((4352 + t*68 + q) * 4)),
            "l"(g_KVQZ + ((size_t)((0*64+t)*8+b))*256 + 128 + q));
    }
    asm volatile("cp.async.commit_group;" ::);

    for (int c = 0; c < NCH; c++) {
        __syncthreads();                       // prev chunk fully done
        *(ull*)(S2 + cn*66 + 2*cm2) = sreg;    // S0 -> smem

        // issue B(c): M, K, TVsub
        for (int i = tid; i < 1024; i += 256) {
            int t = i >> 4, q = (i & 15) * 4;
            asm volatile("cp.async.cg.shared.global [%0], [%1], 16;" ::
                "r"(sb + (unsigned)((17408 + t*68 + q) * 4)),
                "l"(g_M + (size_t)(c*8+b)*4096 + t*64 + q));
            asm volatile("cp.async.cg.shared.global [%0], [%1], 16;" ::
                "r"(sb + (unsigned)((21760 + t*68 + q) * 4)),
                "l"(g_KVQZ + ((size_t)((c*64+t)*8+b))*256 + q));
        }
        if (tid < 128) {
            int nn = tid >> 4, q = (tid & 15) * 4;
            asm volatile("cp.async.cg.shared.global [%0], [%1], 16;" ::
                "r"(sb + (unsigned)((26112 + nn*68 + q) * 4)),
                "l"(g_TVT + (size_t)(c*8+b)*4096 + (n0+nn)*64 + q));
        }
        asm volatile("cp.async.commit_group;" ::);

        if (c + 1 < NCH) {                     // issue TKQ(c+1)
            int base = ((c+1) & 1) * 8704;
            for (int i = tid; i < 1024; i += 256) {
                int t = i >> 4, q = (i & 15) * 4;
                asm volatile("cp.async.cg.shared.global [%0], [%1], 16;" ::
                    "r"(sb + (unsigned)((base + t*68 + q) * 4)),
                    "l"(g_TK + (size_t)((c+1)*8+b)*4096 + t*64 + q));
                asm volatile("cp.async.cg.shared.global [%0], [%1], 16;" ::
                    "r"(sb + (unsigned)((base + 4352 + t*68 + q) * 4)),
                    "l"(g_KVQZ + ((size_t)(((c+1)*64+t)*8+b))*256 + 128 + q));
            }
        }
        asm volatile("cp.async.commit_group;" ::);
        asm volatile("cp.async.wait_group 2;" ::);   // TKQ(c) done
        __syncthreads();

        const float* TKs = sm + (c & 1) * 8704;
        const float* Qs  = TKs + 4352;

        // Phase A: W1 = TK S0^T, dqA = Q S0^T (m split by mh, interleaved)
        ull w1a[4] = {0,0,0,0}, dqa[4] = {0,0,0,0};
        #pragma unroll
        for (int mi = 0; mi < 16; mi++) {
            int m2 = 2*mi + mh;
            ull s2 = *(const ull*)(S2 + tn*66 + 2*m2);
            #pragma unroll
            for (int i = 0; i < 4; i++) {
                ull tk = *(const ull*)(TKs + (t0+i)*68 + 2*m2);
                ull qq = *(const ull*)(Qs  + (t0+i)*68 + 2*m2);
                w1a[i] = fma2(tk, s2, w1a[i]);
                dqa[i] = fma2(qq, s2, dqa[i]);
            }
        }
        float w1[4], dqp[4];
        #pragma unroll
        for (int i = 0; i < 4; i++) {
            float lo, hi; unpk2(w1a[i], lo, hi);
            float w = lo + hi;
            w += __shfl_xor_sync(0xffffffffu, w, 8);
            w1[i] = w;
            unpk2(dqa[i], lo, hi);
            dqp[i] = lo + hi;
        }

        asm volatile("cp.async.wait_group 1;" ::);   // B(c) done
        __syncthreads();

        if (mh == 0) {
            #pragma unroll
            for (int i = 0; i < 4; i++)
                Ds[tn*66 + t0+i] = TVs[tn*68 + t0+i] - w1[i];
        }
        __syncthreads();

        // Phase B: dq = dqA + M * Delta  (j split by mh)
        ull mb[4] = {0,0,0,0};
        #pragma unroll
        for (int ji = 0; ji < 16; ji++) {
            int j2 = 2*ji + mh;
            ull dv = *(const ull*)(Ds + tn*66 + 2*j2);
            #pragma unroll
            for (int i = 0; i < 4; i++) {
                ull mm = *(const ull*)(Ms + (t0+i)*68 + 2*j2);
                mb[i] = fma2(mm, dv, mb[i]);
            }
        }
        #pragma unroll
        for (int i = 0; i < 4; i++) {
            float lo, hi; unpk2(mb[i], lo, hi);
            float d = dqp[i] + lo + hi;
            d += __shfl_xor_sync(0xffffffffu, d, 8);
            if (mh == 0)
                g_Y[((size_t)((c*64 + t0+i)*8 + b))*64 + n0 + tn] = d;
        }

        // Phase C: S += Delta^T K
        #pragma unroll 4
        for (int t = 0; t < 64; t++) {
            float d = Ds[cn*66 + t];
            ull k2 = *(const ull*)(Kc + t*68 + 2*cm2);
            sreg = fma2(pk2(d, d), k2, sreg);
        }
    }
}

// ---------------------------------------------------------------------------
__global__ void __launch_bounds__(256) k_act()
{
    const int i = blockIdx.x * 256 + threadIdx.x;
    const int m = i >> 4, n4 = (i & 15) * 4;
    float4 dq = *(const float4*)(g_Y + (size_t)m * NS + n4);
    float4 z  = *(const float4*)(g_KVQZ + (size_t)m * 256 + 192 + n4);
    float o[4]; float dqa[4] = {dq.x, dq.y, dq.z, dq.w};
    float za[4] = {z.x, z.y, z.z, z.w};
    #pragma unroll
    for (int j = 0; j < 4; j++) {
        float ax = fabsf(dqa[j]);
        float e  = __expf(-2.f * ax);
        float th = __fdividef(1.f - e, 1.f + e);
        th = copysignf(th, dqa[j]);
        float sg = __fdividef(1.f, 1.f + __expf(-za[j]));
        o[j] = th * sg;
    }
    *(float4*)(g_Y + (size_t)m * NS + n4) = make_float4(o[0], o[1], o[2], o[3]);
}

// ---------------------------------------------------------------------------
__global__ void __launch_bounds__(256, 2) k_out(
    const float* __restrict__ Wout, float* __restrict__ Out)
{
    __shared__ __align__(16) float As[8][132];
    __shared__ __align__(16) float Bs[8][132];
    const int d0 = blockIdx.x * 128, m0 = blockIdx.y * 128;
    const int t = threadIdx.x, tx = t & 15, ty = t >> 4;
    ull acc2[8][4];
    #pragma unroll
    for (int i = 0; i < 8; i++)
        #pragma unroll
        for (int j = 0; j < 4; j++) acc2[i][j] = 0ull;
    const int lm = t >> 1, lk = (t & 1) * 4;
    const int bd = t >> 1, bk = (t & 1) * 4;
    for (int k0 = 0; k0 < NS; k0 += 8) {
        float4 a = *(const float4*)(g_Y + (size_t)(m0 + lm) * NS + k0 + lk);
        As[lk+0][lm] = a.x; As[lk+1][lm] = a.y; As[lk+2][lm] = a.z; As[lk+3][lm] = a.w;
        float4 w = *(const float4*)(Wout + (size_t)(d0 + bd) * NS + k0 + bk);
        Bs[bk+0][bd] = w.x; Bs[bk+1][bd] = w.y; Bs[bk+2][bd] = w.z; Bs[bk+3][bd] = w.w;
        __syncthreads();
        #pragma unroll
        for (int k = 0; k < 8; k++) {
            float av[8];
            *(float4*)&av[0] = *(const float4*)&As[k][ty*8];
            *(float4*)&av[4] = *(const float4*)&As[k][ty*8 + 4];
            const ulonglong2* bq = (const ulonglong2*)&Bs[k][tx*8];
            ulonglong2 b01 = bq[0], b23 = bq[1];
            ull bp[4] = {b01.x, b01.y, b23.x, b23.y};
            #pragma unroll
            for (int i = 0; i < 8; i++) {
                ull ai = pk2(av[i], av[i]);
                #pragma unroll
                for (int j = 0; j < 4; j++)
                    acc2[i][j] = fma2(ai, bp[j], acc2[i][j]);
            }
        }
        __syncthreads();
    }
    #pragma unroll
    for (int i = 0; i < 8; i++) {
        float o[8];
        #pragma unroll
        for (int j = 0; j < 4; j++) unpk2(acc2[i][j], o[2*j], o[2*j+1]);
        float* outp = Out + (size_t)(m0 + ty*8 + i) * DM + d0 + tx*8;
        *(float4*)(outp)     = make_float4(o[0], o[1], o[2], o[3]);
        *(float4*)(outp + 4) = make_float4(o[4], o[5], o[6], o[7]);
    }
}

// ---------------------------------------------------------------------------
extern "C" void kernel_launch(void* const* d_in, const int* in_sizes, int n_in,
                              void* d_out, int out_size)
{
    const float* x    = (const float*)d_in[0];
    const float* Win  = (const float*)d_in[1];
    const float* Wk   = (const float*)d_in[2];
    const float* Wv   = (const float*)d_in[3];
    const float* Wq   = (const float*)d_in[4];
    const float* Wz   = (const float*)d_in[5];
    const float* Wout = (const float*)d_in[6];
    float* out = (float*)d_out;

    static int attrs_set = 0;
    if (!attrs_set) {
        cudaFuncSetAttribute(k_pre, cudaFuncAttributeMaxDynamicSharedMemorySize, 87040);
        cudaFuncSetAttribute(k_wy,  cudaFuncAttributeMaxDynamicSharedMemorySize, 110848);
        attrs_set = 1;
    }

    k_fuse<<<dim3(16, 4),  256>>>(Win, Wk, Wv, Wq, Wz);
    k_proj<<<dim3(2, 128), 256>>>(x);
    k_norm<<<2048,         256>>>();
    k_pre <<<256,          256, 87040>>>();
    k_wy  <<<64,           256, 110848>>>();
    k_act <<<1024,         256>>>();
    k_out <<<dim3(8, 128), 256>>>(Wout, out);
}

// round 8
// speedup vs baseline: 2.0652x; 1.1307x over previous
#include <cuda_runtime.h>
#include <math.h>

#define TT 2048
#define BB 8
#define DM 1024
#define DI 2048
#define NS 64
#define MTOT (TT*BB)
#define NCH 32
#define NTILE 256

__device__ float g_WfT[DM * 256];
__device__ float g_KVQZ[(size_t)MTOT * 256];   // 0-63 k, 64-127 v, 128-191 q, 192-255 z
__device__ float g_Y[(size_t)MTOT * NS];       // raw dq, activated in place
__device__ float g_TK [(size_t)NTILE * 4096];  // [tile][t*64+m]   T*K
__device__ float g_TVT[(size_t)NTILE * 4096];  // [tile][n*64+t]   (T*V)^T
__device__ float g_M  [(size_t)NTILE * 4096];  // [tile][t*64+j]   tril(QK^T) incl diag

typedef unsigned long long ull;
__device__ __forceinline__ ull pk2(float lo, float hi) {
    ull r; asm("mov.b64 %0, {%1, %2};" : "=l"(r) : "f"(lo), "f"(hi)); return r;
}
__device__ __forceinline__ void unpk2(ull v, float& lo, float& hi) {
    asm("mov.b64 {%0, %1}, %2;" : "=f"(lo), "=f"(hi) : "l"(v));
}
__device__ __forceinline__ ull fma2(ull a, ull b, ull c) {
    ull d; asm("fma.rn.f32x2 %0, %1, %2, %3;" : "=l"(d) : "l"(a), "l"(b), "l"(c)); return d;
}

// ---------------------------------------------------------------------------
// k_fuse: WfT[d][r] = sum_i Wsel[r][i]*Win[i][d].  Pipelined, f32x2.
// Tile 64(m) x 64(d), thread 4x4, K-chunk 16.
// ---------------------------------------------------------------------------
__global__ void __launch_bounds__(256) k_fuse(
    const float* __restrict__ Win, const float* __restrict__ Wk,
    const float* __restrict__ Wv,  const float* __restrict__ Wq,
    const float* __restrict__ Wz)
{
    __shared__ __align__(16) float As[2][16][65];
    __shared__ __align__(16) float Bs[2][16][68];
    const int d0 = blockIdx.x * 64, m0 = blockIdx.y * 64;
    const int t = threadIdx.x, tx = t & 15, ty = t >> 4;
    ull acc2[4][2];
    #pragma unroll
    for (int i = 0; i < 4; i++) { acc2[i][0] = 0ull; acc2[i][1] = 0ull; }

    const int lm = t >> 2, lk = (t & 3) * 4;
    const int r = m0 + lm;
    const float* W = (r < 64) ? Wk : (r < 128) ? Wv : (r < 192) ? Wq : Wz;
    const float* arow = W + (size_t)(r & 63) * DI + lk;
    const int bk = t >> 4, bd = (t & 15) * 4;
    const float* bsrc = Win + (size_t)bk * DM + d0 + bd;
    unsigned bdst[2];
    bdst[0] = (unsigned)__cvta_generic_to_shared(&Bs[0][bk][bd]);
    bdst[1] = (unsigned)__cvta_generic_to_shared(&Bs[1][bk][bd]);

    float4 a = *(const float4*)(arow);
    asm volatile("cp.async.cg.shared.global [%0], [%1], 16;" :: "r"(bdst[0]), "l"(bsrc));
    asm volatile("cp.async.commit_group;" ::);

    for (int c = 0; c < DI / 16; c++) {
        const int buf = c & 1;
        As[buf][lk+0][lm] = a.x; As[buf][lk+1][lm] = a.y;
        As[buf][lk+2][lm] = a.z; As[buf][lk+3][lm] = a.w;
        if (c + 1 < DI / 16) a = *(const float4*)(arow + (c + 1) * 16);
        asm volatile("cp.async.wait_group 0;" ::);
        __syncthreads();
        if (c + 1 < DI / 16) {
            asm volatile("cp.async.cg.shared.global [%0], [%1], 16;" ::
                "r"(bdst[buf ^ 1]), "l"(bsrc + (size_t)(c + 1) * 16 * DM));
            asm volatile("cp.async.commit_group;" ::);
        }
        #pragma unroll
        for (int k = 0; k < 16; k++) {
            float av[4];
            #pragma unroll
            for (int i = 0; i < 4; i++) av[i] = As[buf][k][ty*4 + i];
            const ull* bq = (const ull*)&Bs[buf][k][tx*4];
            ull b0 = bq[0], b1 = bq[1];
            #pragma unroll
            for (int i = 0; i < 4; i++) {
                ull ai = pk2(av[i], av[i]);
                acc2[i][0] = fma2(ai, b0, acc2[i][0]);
                acc2[i][1] = fma2(ai, b1, acc2[i][1]);
            }
        }
    }
    #pragma unroll
    for (int i = 0; i < 4; i++) {
        float o[4];
        unpk2(acc2[i][0], o[0], o[1]);
        unpk2(acc2[i][1], o[2], o[3]);
        #pragma unroll
        for (int j = 0; j < 4; j++)
            g_WfT[(size_t)(d0 + tx*4 + j) * 256 + (m0 + ty*4 + i)] = o[j];
    }
}

// ---------------------------------------------------------------------------
// k_proj: KVQZ = X @ WfT.  M=16384, N=256, K=1024.  Pipelined cp.async, f32x2.
// ---------------------------------------------------------------------------
__global__ void __launch_bounds__(256, 2) k_proj(const float* __restrict__ X)
{
    __shared__ __align__(16) float As[2][8][132];
    __shared__ __align__(16) float Bs[2][8][132];
    const int n0 = blockIdx.x * 128, m0 = blockIdx.y * 128;
    const int t = threadIdx.x, tx = t & 15, ty = t >> 4;
    ull acc2[8][4];
    #pragma unroll
    for (int i = 0; i < 8; i++)
        #pragma unroll
        for (int j = 0; j < 4; j++) acc2[i][j] = 0ull;

    const int lm = t >> 1, lk = (t & 1) * 4;
    const int bk = t >> 5, bn = (t & 31) * 4;
    const float* arow = X + (size_t)(m0 + lm) * DM + lk;
    const float* brow = g_WfT + (size_t)bk * 256 + n0 + bn;
    unsigned bdst[2];
    bdst[0] = (unsigned)__cvta_generic_to_shared(&Bs[0][bk][bn]);
    bdst[1] = (unsigned)__cvta_generic_to_shared(&Bs[1][bk][bn]);

    float4 a = *(const float4*)(arow);
    asm volatile("cp.async.cg.shared.global [%0], [%1], 16;" :: "r"(bdst[0]), "l"(brow));
    asm volatile("cp.async.commit_group;" ::);

    for (int c = 0; c < DM / 8; c++) {
        const int buf = c & 1;
        As[buf][lk+0][lm] = a.x; As[buf][lk+1][lm] = a.y;
        As[buf][lk+2][lm] = a.z; As[buf][lk+3][lm] = a.w;
        if (c + 1 < DM / 8) a = *(const float4*)(arow + (c + 1) * 8);
        asm volatile("cp.async.wait_group 0;" ::);
        __syncthreads();
        if (c + 1 < DM / 8) {
            asm volatile("cp.async.cg.shared.global [%0], [%1], 16;" ::
                "r"(bdst[buf ^ 1]), "l"(brow + (size_t)(c + 1) * 8 * 256));
            asm volatile("cp.async.commit_group;" ::);
        }
        #pragma unroll
        for (int k = 0; k < 8; k++) {
            float av[8];
            *(float4*)&av[0] = *(const float4*)&As[buf][k][ty*8];
            *(float4*)&av[4] = *(const float4*)&As[buf][k][ty*8 + 4];
            const ulonglong2* bq = (const ulonglong2*)&Bs[buf][k][tx*8];
            ulonglong2 b01 = bq[0], b23 = bq[1];
            ull bp[4] = {b01.x, b01.y, b23.x, b23.y};
            #pragma unroll
            for (int i = 0; i < 8; i++) {
                ull ai = pk2(av[i], av[i]);
                #pragma unroll
                for (int j = 0; j < 4; j++)
                    acc2[i][j] = fma2(ai, bp[j], acc2[i][j]);
            }
        }
    }
    #pragma unroll
    for (int i = 0; i < 8; i++) {
        float o[8];
        #pragma unroll
        for (int j = 0; j < 4; j++) unpk2(acc2[i][j], o[2*j], o[2*j+1]);
        float* outp = g_KVQZ + (size_t)(m0 + ty*8 + i) * 256 + n0 + tx*8;
        *(float4*)(outp)     = make_float4(o[0], o[1], o[2], o[3]);
        *(float4*)(outp + 4) = make_float4(o[4], o[5], o[6], o[7]);
    }
}

// ---------------------------------------------------------------------------
__global__ void __launch_bounds__(256) k_norm()
{
    const int row = blockIdx.x * 8 + (threadIdx.x >> 5);
    const int lane = threadIdx.x & 31;
    float* kr = g_KVQZ + (size_t)row * 256 + lane * 2;
    float2 v = *(float2*)kr;
    float ss = v.x * v.x + v.y * v.y;
    #pragma unroll
    for (int m = 16; m >= 1; m >>= 1)
        ss += __shfl_xor_sync(0xffffffffu, ss, m);
    float inv = __fdividef(1.f, sqrtf(ss) + 1e-6f);
    v.x *= inv; v.y *= inv;
    *(float2*)kr = v;
}

// ---------------------------------------------------------------------------
// k_pre: per (batch,chunk) WY precompute, fully parallel over 256 tiles.
// ---------------------------------------------------------------------------
__global__ void __launch_bounds__(256) k_pre()
{
    extern __shared__ float sm[];
    float* Ks = sm;
    float* Vs = sm + 4352;
    float* Qs = sm + 8704;
    float* Aa = sm + 13056;
    float* Nn = sm + 17408;

    const int tile = blockIdx.x;
    const int b = tile & 7, c = tile >> 3;
    const int tid = threadIdx.x;

    for (int i = tid; i < 3072; i += 256) {
        int mat = i >> 10, rr = i & 1023, t = rr >> 4, q = (rr & 15) * 4;
        const float* src = g_KVQZ + ((size_t)((c*64+t)*8+b)) * 256 + mat * 64 + q;
        float* dst = (mat == 0 ? Ks : mat == 1 ? Vs : Qs) + t * 68 + q;
        *(float4*)dst = *(const float4*)src;
    }
    for (int i = tid; i < 4352; i += 256) Nn[i] = 0.f;
    __syncthreads();

    const int ty = tid >> 4, tx = tid & 15;
    const int t0 = ty * 4, j0 = tx * 4;

    // A = K K^T
    {
        ull acc[4][4];
        #pragma unroll
        for (int i = 0; i < 4; i++)
            #pragma unroll
            for (int j = 0; j < 4; j++) acc[i][j] = 0ull;
        for (int m2 = 0; m2 < 32; m2++) {
            ull kt[4], kj[4];
            #pragma unroll
            for (int i = 0; i < 4; i++) kt[i] = *(const ull*)(Ks + (t0+i)*68 + 2*m2);
            #pragma unroll
            for (int j = 0; j < 4; j++) kj[j] = *(const ull*)(Ks + (j0+j)*68 + 2*m2);
            #pragma unroll
            for (int i = 0; i < 4; i++)
                #pragma unroll
                for (int j = 0; j < 4; j++) acc[i][j] = fma2(kt[i], kj[j], acc[i][j]);
        }
        #pragma unroll
        for (int i = 0; i < 4; i++)
            #pragma unroll
            for (int j = 0; j < 4; j++) {
                float lo, hi; unpk2(acc[i][j], lo, hi);
                Aa[(t0+i)*68 + j0+j] = lo + hi;
            }
    }
    // M = tril(Q K^T) incl diag -> global
    {
        ull acc[4][4];
        #pragma unroll
        for (int i = 0; i < 4; i++)
            #pragma unroll
            for (int j = 0; j < 4; j++) acc[i][j] = 0ull;
        for (int m2 = 0; m2 < 32; m2++) {
            ull qt[4], kj[4];
            #pragma unroll
            for (int i = 0; i < 4; i++) qt[i] = *(const ull*)(Qs + (t0+i)*68 + 2*m2);
            #pragma unroll
            for (int j = 0; j < 4; j++) kj[j] = *(const ull*)(Ks + (j0+j)*68 + 2*m2);
            #pragma unroll
            for (int i = 0; i < 4; i++)
                #pragma unroll
                for (int j = 0; j < 4; j++) acc[i][j] = fma2(qt[i], kj[j], acc[i][j]);
        }
        #pragma unroll
        for (int i = 0; i < 4; i++)
            #pragma unroll
            for (int j = 0; j < 4; j++) {
                float lo, hi; unpk2(acc[i][j], lo, hi);
                g_M[(size_t)tile*4096 + (t0+i)*64 + j0+j] =
                    (j0+j <= t0+i) ? (lo + hi) : 0.f;
            }
    }
    __syncthreads();

    // N: (I+L)^{-1} = I + N, forward substitution (split dep chain)
    for (int i = 1; i < 64; i++) {
        if (tid < i) {
            float s0 = -Aa[i*68 + tid], s1 = 0.f;
            int p = tid + 1;
            for (; p + 1 < i; p += 2) {
                s0 = fmaf(-Aa[i*68 + p],     Nn[p*68 + tid],     s0);
                s1 = fmaf(-Aa[i*68 + p + 1], Nn[(p+1)*68 + tid], s1);
            }
            if (p < i) s0 = fmaf(-Aa[i*68 + p], Nn[p*68 + tid], s0);
            Nn[i*68 + tid] = s0 + s1;
        }
        __syncthreads();
    }

    // TK = K + N K   (f32x2)
    {
        ull acc[4][2];
        #pragma unroll
        for (int i = 0; i < 4; i++) { acc[i][0] = 0ull; acc[i][1] = 0ull; }
        for (int jj = 0; jj < 64; jj++) {
            float nt[4];
            #pragma unroll
            for (int i = 0; i < 4; i++) nt[i] = Nn[(t0+i)*68 + jj];
            const ull* kq = (const ull*)(Ks + jj*68 + j0);
            ull k0 = kq[0], k1 = kq[1];
            #pragma unroll
            for (int i = 0; i < 4; i++) {
                ull ni = pk2(nt[i], nt[i]);
                acc[i][0] = fma2(ni, k0, acc[i][0]);
                acc[i][1] = fma2(ni, k1, acc[i][1]);
            }
        }
        #pragma unroll
        for (int i = 0; i < 4; i++) {
            float o[4];
            unpk2(acc[i][0], o[0], o[1]);
            unpk2(acc[i][1], o[2], o[3]);
            #pragma unroll
            for (int j = 0; j < 4; j++)
                g_TK[(size_t)tile*4096 + (t0+i)*64 + j0+j] =
                    Ks[(t0+i)*68 + j0+j] + o[j];
        }
    }
    // TVT[n][t] = V[t][n] + (N V)[t][n]   (f32x2)
    {
        ull acc[4][2];
        #pragma unroll
        for (int i = 0; i < 4; i++) { acc[i][0] = 0ull; acc[i][1] = 0ull; }
        for (int jj = 0; jj < 64; jj++) {
            float nt[4];
            #pragma unroll
            for (int i = 0; i < 4; i++) nt[i] = Nn[(t0+i)*68 + jj];
            const ull* vq = (const ull*)(Vs + jj*68 + j0);
            ull v0 = vq[0], v1 = vq[1];
            #pragma unroll
            for (int i = 0; i < 4; i++) {
                ull ni = pk2(nt[i], nt[i]);
                acc[i][0] = fma2(ni, v0, acc[i][0]);
                acc[i][1] = fma2(ni, v1, acc[i][1]);
            }
        }
        #pragma unroll
        for (int i = 0; i < 4; i++) {
            float o[4];
            unpk2(acc[i][0], o[0], o[1]);
            unpk2(acc[i][1], o[2], o[3]);
            #pragma unroll
            for (int j = 0; j < 4; j++)
                g_TVT[(size_t)tile*4096 + (j0+j)*64 + (t0+i)] =
                    Vs[(t0+i)*68 + j0+j] + o[j];
        }
    }
}

// ---------------------------------------------------------------------------
// k_wy: sequential chunk recurrence (unchanged from R7).
// ---------------------------------------------------------------------------
__global__ void __launch_bounds__(256, 1) k_wy()
{
    extern __shared__ float sm[];
    const int tid = threadIdx.x;
    const int b  = blockIdx.x >> 3;
    const int n0 = (blockIdx.x & 7) * 8;
    const int tt = tid >> 4, mh = (tid >> 3) & 1, tn = tid & 7;
    const int t0 = tt * 4;
    const int cn = tid >> 5, cm2 = tid & 31;

    float* Ms  = sm + 17408;
    float* Kc  = sm + 21760;
    float* TVs = sm + 26112;
    float* S2  = sm + 26656;
    float* Ds  = sm + 27184;
    const unsigned sb = (unsigned)__cvta_generic_to_shared(sm);

    ull sreg = 0ull;

    for (int i = tid; i < 1024; i += 256) {
        int t = i >> 4, q = (i & 15) * 4;
        asm volatile("cp.async.cg.shared.global [%0], [%1], 16;" ::
            "r"(sb + (unsigned)((t*68 + q) * 4)),
            "l"(g_TK + (size_t)(0*8+b)*4096 + t*64 + q));
        asm volatile("cp.async.cg.shared.global [%0], [%1], 16;" ::
            "r"(sb + (unsigned)((4352 + t*68 + q) * 4)),
            "l"(g_KVQZ + ((size_t)((0*64+t)*8+b))*256 + 128 + q));
    }
    asm volatile("cp.async.commit_group;" ::);

    for (int c = 0; c < NCH; c++) {
        __syncthreads();
        *(ull*)(S2 + cn*66 + 2*cm2) = sreg;

        for (int i = tid; i < 1024; i += 256) {
            int t = i >> 4, q = (i & 15) * 4;
            asm volatile("cp.async.cg.shared.global [%0], [%1], 16;" ::
                "r"(sb + (unsigned)((17408 + t*68 + q) * 4)),
                "l"(g_M + (size_t)(c*8+b)*4096 + t*64 + q));
            asm volatile("cp.async.cg.shared.global [%0], [%1], 16;" ::
                "r"(sb + (unsigned)((21760 + t*68 + q) * 4)),
                "l"(g_KVQZ + ((size_t)((c*64+t)*8+b))*256 + q));
        }
        if (tid < 128) {
            int nn = tid >> 4, q = (tid & 15) * 4;
            asm volatile("cp.async.cg.shared.global [%0], [%1], 16;" ::
                "r"(sb + (unsigned)((26112 + nn*68 + q) * 4)),
                "l"(g_TVT + (size_t)(c*8+b)*4096 + (n0+nn)*64 + q));
        }
        asm volatile("cp.async.commit_group;" ::);

        if (c + 1 < NCH) {
            int base = ((c+1) & 1) * 8704;
            for (int i = tid; i < 1024; i += 256) {
                int t = i >> 4, q = (i & 15) * 4;
                asm volatile("cp.async.cg.shared.global [%0], [%1], 16;" ::
                    "r"(sb + (unsigned)((base + t*68 + q) * 4)),
                    "l"(g_TK + (size_t)((c+1)*8+b)*4096 + t*64 + q));
                asm volatile("cp.async.cg.shared.global [%0], [%1], 16;" ::
                    "r"(sb + (unsigned)((base + 4352 + t*68 + q) * 4)),
                    "l"(g_KVQZ + ((size_t)(((c+1)*64+t)*8+b))*256 + 128 + q));
            }
        }
        asm volatile("cp.async.commit_group;" ::);
        asm volatile("cp.async.wait_group 2;" ::);
        __syncthreads();

        const float* TKs = sm + (c & 1) * 8704;
        const float* Qs  = TKs + 4352;

        ull w1a[4] = {0,0,0,0}, dqa[4] = {0,0,0,0};
        #pragma unroll
        for (int mi = 0; mi < 16; mi++) {
            int m2 = 2*mi + mh;
            ull s2 = *(const ull*)(S2 + tn*66 + 2*m2);
            #pragma unroll
            for (int i = 0; i < 4; i++) {
                ull tk = *(const ull*)(TKs + (t0+i)*68 + 2*m2);
                ull qq = *(const ull*)(Qs  + (t0+i)*68 + 2*m2);
                w1a[i] = fma2(tk, s2, w1a[i]);
                dqa[i] = fma2(qq, s2, dqa[i]);
            }
        }
        float w1[4], dqp[4];
        #pragma unroll
        for (int i = 0; i < 4; i++) {
            float lo, hi; unpk2(w1a[i], lo, hi);
            float w = lo + hi;
            w += __shfl_xor_sync(0xffffffffu, w, 8);
            w1[i] = w;
            unpk2(dqa[i], lo, hi);
            dqp[i] = lo + hi;
        }

        asm volatile("cp.async.wait_group 1;" ::);
        __syncthreads();

        if (mh == 0) {
            #pragma unroll
            for (int i = 0; i < 4; i++)
                Ds[tn*66 + t0+i] = TVs[tn*68 + t0+i] - w1[i];
        }
        __syncthreads();

        ull mb[4] = {0,0,0,0};
        #pragma unroll
        for (int ji = 0; ji < 16; ji++) {
            int j2 = 2*ji + mh;
            ull dv = *(const ull*)(Ds + tn*66 + 2*j2);
            #pragma unroll
            for (int i = 0; i < 4; i++) {
                ull mm = *(const ull*)(Ms + (t0+i)*68 + 2*j2);
                mb[i] = fma2(mm, dv, mb[i]);
            }
        }
        #pragma unroll
        for (int i = 0; i < 4; i++) {
            float lo, hi; unpk2(mb[i], lo, hi);
            float d = dqp[i] + lo + hi;
            d += __shfl_xor_sync(0xffffffffu, d, 8);
            if (mh == 0)
                g_Y[((size_t)((c*64 + t0+i)*8 + b))*64 + n0 + tn] = d;
        }

        #pragma unroll 4
        for (int t = 0; t < 64; t++) {
            float d = Ds[cn*66 + t];
            ull k2 = *(const ull*)(Kc + t*68 + 2*cm2);
            sreg = fma2(pk2(d, d), k2, sreg);
        }
    }
}

// ---------------------------------------------------------------------------
__global__ void __launch_bounds__(256) k_act()
{
    const int i = blockIdx.x * 256 + threadIdx.x;
    const int m = i >> 4, n4 = (i & 15) * 4;
    float4 dq = *(const float4*)(g_Y + (size_t)m * NS + n4);
    float4 z  = *(const float4*)(g_KVQZ + (size_t)m * 256 + 192 + n4);
    float o[4]; float dqa[4] = {dq.x, dq.y, dq.z, dq.w};
    float za[4] = {z.x, z.y, z.z, z.w};
    #pragma unroll
    for (int j = 0; j < 4; j++) {
        float ax = fabsf(dqa[j]);
        float e  = __expf(-2.f * ax);
        float th = __fdividef(1.f - e, 1.f + e);
        th = copysignf(th, dqa[j]);
        float sg = __fdividef(1.f, 1.f + __expf(-za[j]));
        o[j] = th * sg;
    }
    *(float4*)(g_Y + (size_t)m * NS + n4) = make_float4(o[0], o[1], o[2], o[3]);
}

// ---------------------------------------------------------------------------
__global__ void __launch_bounds__(256, 2) k_out(
    const float* __restrict__ Wout, float* __restrict__ Out)
{
    __shared__ __align__(16) float As[8][132];
    __shared__ __align__(16) float Bs[8][132];
    const int d0 = blockIdx.x * 128, m0 = blockIdx.y * 128;
    const int t = threadIdx.x, tx = t & 15, ty = t >> 4;
    ull acc2[8][4];
    #pragma unroll
    for (int i = 0; i < 8; i++)
        #pragma unroll
        for (int j = 0; j < 4; j++) acc2[i][j] = 0ull;
    const int lm = t >> 1, lk = (t & 1) * 4;
    const int bd = t >> 1, bk = (t & 1) * 4;
    for (int k0 = 0; k0 < NS; k0 += 8) {
        float4 a = *(const float4*)(g_Y + (size_t)(m0 + lm) * NS + k0 + lk);
        As[lk+0][lm] = a.x; As[lk+1][lm] = a.y; As[lk+2][lm] = a.z; As[lk+3][lm] = a.w;
        float4 w = *(const float4*)(Wout + (size_t)(d0 + bd) * NS + k0 + bk);
        Bs[bk+0][bd] = w.x; Bs[bk+1][bd] = w.y; Bs[bk+2][bd] = w.z; Bs[bk+3][bd] = w.w;
        __syncthreads();
        #pragma unroll
        for (int k = 0; k < 8; k++) {
            float av[8];
            *(float4*)&av[0] = *(const float4*)&As[k][ty*8];
            *(float4*)&av[4] = *(const float4*)&As[k][ty*8 + 4];
            const ulonglong2* bq = (const ulonglong2*)&Bs[k][tx*8];
            ulonglong2 b01 = bq[0], b23 = bq[1];
            ull bp[4] = {b01.x, b01.y, b23.x, b23.y};
            #pragma unroll
            for (int i = 0; i < 8; i++) {
                ull ai = pk2(av[i], av[i]);
                #pragma unroll
                for (int j = 0; j < 4; j++)
                    acc2[i][j] = fma2(ai, bp[j], acc2[i][j]);
            }
        }
        __syncthreads();
    }
    #pragma unroll
    for (int i = 0; i < 8; i++) {
        float o[8];
        #pragma unroll
        for (int j = 0; j < 4; j++) unpk2(acc2[i][j], o[2*j], o[2*j+1]);
        float* outp = Out + (size_t)(m0 + ty*8 + i) * DM + d0 + tx*8;
        *(float4*)(outp)     = make_float4(o[0], o[1], o[2], o[3]);
        *(float4*)(outp + 4) = make_float4(o[4], o[5], o[6], o[7]);
    }
}

// ---------------------------------------------------------------------------
extern "C" void kernel_launch(void* const* d_in, const int* in_sizes, int n_in,
                              void* d_out, int out_size)
{
    const float* x    = (const float*)d_in[0];
    const float* Win  = (const float*)d_in[1];
    const float* Wk   = (const float*)d_in[2];
    const float* Wv   = (const float*)d_in[3];
    const float* Wq   = (const float*)d_in[4];
    const float* Wz   = (const float*)d_in[5];
    const float* Wout = (const float*)d_in[6];
    float* out = (float*)d_out;

    cudaFuncSetAttribute(k_pre, cudaFuncAttributeMaxDynamicSharedMemorySize, 87040);
    cudaFuncSetAttribute(k_wy,  cudaFuncAttributeMaxDynamicSharedMemorySize, 110848);

    k_fuse<<<dim3(16, 4),  256>>>(Win, Wk, Wv, Wq, Wz);
    k_proj<<<dim3(2, 128), 256>>>(x);
    k_norm<<<2048,         256>>>();
    k_pre <<<256,          256, 87040>>>();
    k_wy  <<<64,           256, 110848>>>();
    k_act <<<1024,         256>>>();
    k_out <<<dim3(8, 128), 256>>>(Wout, out);
}

// round 10
// speedup vs baseline: 2.1111x; 1.0222x over previous
#include <cuda_runtime.h>
#include <math.h>

#define TT 2048
#define BB 8
#define DM 1024
#define DI 2048
#define NS 64
#define MTOT (TT*BB)
#define NCH 32
#define NTILE 256

__device__ float g_WfT[DM * 256];
__device__ float g_KVQZ[(size_t)MTOT * 256];   // 0-63 k, 64-127 v, 128-191 q, 192-255 z
__device__ float g_Y[(size_t)MTOT * NS];       // activated y
__device__ float g_TK [(size_t)NTILE * 4096];  // [tile][t*64+m]
__device__ float g_TVT[(size_t)NTILE * 4096];  // [tile][n*64+t]
__device__ float g_M  [(size_t)NTILE * 4096];  // [tile][t*64+j]

typedef unsigned long long ull;
__device__ __forceinline__ ull pk2(float lo, float hi) {
    ull r; asm("mov.b64 %0, {%1, %2};" : "=l"(r) : "f"(lo), "f"(hi)); return r;
}
__device__ __forceinline__ void unpk2(ull v, float& lo, float& hi) {
    asm("mov.b64 {%0, %1}, %2;" : "=f"(lo), "=f"(hi) : "l"(v));
}
__device__ __forceinline__ ull fma2(ull a, ull b, ull c) {
    ull d; asm("fma.rn.f32x2 %0, %1, %2, %3;" : "=l"(d) : "l"(a), "l"(b), "l"(c)); return d;
}
__device__ __forceinline__ float rsum(ull v) { float lo, hi; unpk2(v, lo, hi); return lo + hi; }
#define CP16(dst, src) asm volatile("cp.async.cg.shared.global [%0], [%1], 16;" :: "r"(dst), "l"(src))
#define CPCOMMIT() asm volatile("cp.async.commit_group;" ::)
#define CPWAIT(n) asm volatile("cp.async.wait_group %0;" :: "n"(n))

// ---------------------------------------------------------------------------
__global__ void __launch_bounds__(256) k_fuse(
    const float* __restrict__ Win, const float* __restrict__ Wk,
    const float* __restrict__ Wv,  const float* __restrict__ Wq,
    const float* __restrict__ Wz)
{
    __shared__ __align__(16) float As[2][16][65];
    __shared__ __align__(16) float Bs[2][16][68];
    const int d0 = blockIdx.x * 64, m0 = blockIdx.y * 64;
    const int t = threadIdx.x, tx = t & 15, ty = t >> 4;
    ull acc2[4][2];
    #pragma unroll
    for (int i = 0; i < 4; i++) { acc2[i][0] = 0ull; acc2[i][1] = 0ull; }

    const int lm = t >> 2, lk = (t & 3) * 4;
    const int r = m0 + lm;
    const float* W = (r < 64) ? Wk : (r < 128) ? Wv : (r < 192) ? Wq : Wz;
    const float* arow = W + (size_t)(r & 63) * DI + lk;
    const int bk = t >> 4, bd = (t & 15) * 4;
    const float* bsrc = Win + (size_t)bk * DM + d0 + bd;
    unsigned bdst[2];
    bdst[0] = (unsigned)__cvta_generic_to_shared(&Bs[0][bk][bd]);
    bdst[1] = (unsigned)__cvta_generic_to_shared(&Bs[1][bk][bd]);

    float4 a = *(const float4*)(arow);
    CP16(bdst[0], bsrc); CPCOMMIT();

    for (int c = 0; c < DI / 16; c++) {
        const int buf = c & 1;
        As[buf][lk+0][lm] = a.x; As[buf][lk+1][lm] = a.y;
        As[buf][lk+2][lm] = a.z; As[buf][lk+3][lm] = a.w;
        if (c + 1 < DI / 16) a = *(const float4*)(arow + (c + 1) * 16);
        CPWAIT(0);
        __syncthreads();
        if (c + 1 < DI / 16) {
            CP16(bdst[buf ^ 1], bsrc + (size_t)(c + 1) * 16 * DM); CPCOMMIT();
        }
        #pragma unroll
        for (int k = 0; k < 16; k++) {
            float av[4];
            #pragma unroll
            for (int i = 0; i < 4; i++) av[i] = As[buf][k][ty*4 + i];
            const ull* bq = (const ull*)&Bs[buf][k][tx*4];
            ull b0 = bq[0], b1 = bq[1];
            #pragma unroll
            for (int i = 0; i < 4; i++) {
                ull ai = pk2(av[i], av[i]);
                acc2[i][0] = fma2(ai, b0, acc2[i][0]);
                acc2[i][1] = fma2(ai, b1, acc2[i][1]);
            }
        }
    }
    #pragma unroll
    for (int i = 0; i < 4; i++) {
        float o[4];
        unpk2(acc2[i][0], o[0], o[1]);
        unpk2(acc2[i][1], o[2], o[3]);
        #pragma unroll
        for (int j = 0; j < 4; j++)
            g_WfT[(size_t)(d0 + tx*4 + j) * 256 + (m0 + ty*4 + i)] = o[j];
    }
}

// ---------------------------------------------------------------------------
// k_proj with fused k-normalization (blocks with n0==0 hold k cols 0-63).
// ---------------------------------------------------------------------------
__global__ void __launch_bounds__(256, 2) k_proj(const float* __restrict__ X)
{
    __shared__ __align__(16) float As[2][8][132];
    __shared__ __align__(16) float Bs[2][8][132];
    const int n0 = blockIdx.x * 128, m0 = blockIdx.y * 128;
    const int t = threadIdx.x, tx = t & 15, ty = t >> 4;
    ull acc2[8][4];
    #pragma unroll
    for (int i = 0; i < 8; i++)
        #pragma unroll
        for (int j = 0; j < 4; j++) acc2[i][j] = 0ull;

    const int lm = t >> 1, lk = (t & 1) * 4;
    const int bk = t >> 5, bn = (t & 31) * 4;
    const float* arow = X + (size_t)(m0 + lm) * DM + lk;
    const float* brow = g_WfT + (size_t)bk * 256 + n0 + bn;
    unsigned bdst[2];
    bdst[0] = (unsigned)__cvta_generic_to_shared(&Bs[0][bk][bn]);
    bdst[1] = (unsigned)__cvta_generic_to_shared(&Bs[1][bk][bn]);

    float4 a = *(const float4*)(arow);
    CP16(bdst[0], brow); CPCOMMIT();

    for (int c = 0; c < DM / 8; c++) {
        const int buf = c & 1;
        As[buf][lk+0][lm] = a.x; As[buf][lk+1][lm] = a.y;
        As[buf][lk+2][lm] = a.z; As[buf][lk+3][lm] = a.w;
        if (c + 1 < DM / 8) a = *(const float4*)(arow + (c + 1) * 8);
        CPWAIT(0);
        __syncthreads();
        if (c + 1 < DM / 8) {
            CP16(bdst[buf ^ 1], brow + (size_t)(c + 1) * 8 * 256); CPCOMMIT();
        }
        #pragma unroll
        for (int k = 0; k < 8; k++) {
            float av[8];
            *(float4*)&av[0] = *(const float4*)&As[buf][k][ty*8];
            *(float4*)&av[4] = *(const float4*)&As[buf][k][ty*8 + 4];
            const ulonglong2* bq = (const ulonglong2*)&Bs[buf][k][tx*8];
            ulonglong2 b01 = bq[0], b23 = bq[1];
            ull bp[4] = {b01.x, b01.y, b23.x, b23.y};
            #pragma unroll
            for (int i = 0; i < 8; i++) {
                ull ai = pk2(av[i], av[i]);
                #pragma unroll
                for (int j = 0; j < 4; j++)
                    acc2[i][j] = fma2(ai, bp[j], acc2[i][j]);
            }
        }
    }
    #pragma unroll
    for (int i = 0; i < 8; i++) {
        float o[8];
        #pragma unroll
        for (int j = 0; j < 4; j++) unpk2(acc2[i][j], o[2*j], o[2*j+1]);
        if (n0 == 0) {
            float ss = 0.f;
            #pragma unroll
            for (int j = 0; j < 8; j++) ss = fmaf(o[j], o[j], ss);
            ss += __shfl_xor_sync(0xffffffffu, ss, 1);
            ss += __shfl_xor_sync(0xffffffffu, ss, 2);
            ss += __shfl_xor_sync(0xffffffffu, ss, 4);
            if (tx < 8) {
                float inv = __fdividef(1.f, sqrtf(ss) + 1e-6f);
                #pragma unroll
                for (int j = 0; j < 8; j++) o[j] *= inv;
            }
        }
        float* outp = g_KVQZ + (size_t)(m0 + ty*8 + i) * 256 + n0 + tx*8;
        *(float4*)(outp)     = make_float4(o[0], o[1], o[2], o[3]);
        *(float4*)(outp + 4) = make_float4(o[4], o[5], o[6], o[7]);
    }
}

// ---------------------------------------------------------------------------
// k_pre: per (batch,chunk) WY precompute.
// ---------------------------------------------------------------------------
__global__ void __launch_bounds__(256) k_pre()
{
    extern __shared__ float sm[];
    float* Ks = sm;
    float* Vs = sm + 4352;
    float* Qs = sm + 8704;
    float* Aa = sm + 13056;
    float* Nn = sm + 17408;

    const int tile = blockIdx.x;
    const int b = tile & 7, c = tile >> 3;
    const int tid = threadIdx.x;

    for (int i = tid; i < 3072; i += 256) {
        int mat = i >> 10, rr = i & 1023, t = rr >> 4, q = (rr & 15) * 4;
        const float* src = g_KVQZ + ((size_t)((c*64+t)*8+b)) * 256 + mat * 64 + q;
        float* dst = (mat == 0 ? Ks : mat == 1 ? Vs : Qs) + t * 68 + q;
        *(float4*)dst = *(const float4*)src;
    }
    for (int i = tid; i < 4352; i += 256) Nn[i] = 0.f;
    __syncthreads();

    const int ty = tid >> 4, tx = tid & 15;
    const int t0 = ty * 4, j0 = tx * 4;

    {   // A = K K^T
        ull acc[4][4];
        #pragma unroll
        for (int i = 0; i < 4; i++)
            #pragma unroll
            for (int j = 0; j < 4; j++) acc[i][j] = 0ull;
        for (int m2 = 0; m2 < 32; m2++) {
            ull kt[4], kj[4];
            #pragma unroll
            for (int i = 0; i < 4; i++) kt[i] = *(const ull*)(Ks + (t0+i)*68 + 2*m2);
            #pragma unroll
            for (int j = 0; j < 4; j++) kj[j] = *(const ull*)(Ks + (j0+j)*68 + 2*m2);
            #pragma unroll
            for (int i = 0; i < 4; i++)
                #pragma unroll
                for (int j = 0; j < 4; j++) acc[i][j] = fma2(kt[i], kj[j], acc[i][j]);
        }
        #pragma unroll
        for (int i = 0; i < 4; i++)
            #pragma unroll
            for (int j = 0; j < 4; j++) Aa[(t0+i)*68 + j0+j] = rsum(acc[i][j]);
    }
    {   // M = tril(Q K^T)
        ull acc[4][4];
        #pragma unroll
        for (int i = 0; i < 4; i++)
            #pragma unroll
            for (int j = 0; j < 4; j++) acc[i][j] = 0ull;
        for (int m2 = 0; m2 < 32; m2++) {
            ull qt[4], kj[4];
            #pragma unroll
            for (int i = 0; i < 4; i++) qt[i] = *(const ull*)(Qs + (t0+i)*68 + 2*m2);
            #pragma unroll
            for (int j = 0; j < 4; j++) kj[j] = *(const ull*)(Ks + (j0+j)*68 + 2*m2);
            #pragma unroll
            for (int i = 0; i < 4; i++)
                #pragma unroll
                for (int j = 0; j < 4; j++) acc[i][j] = fma2(qt[i], kj[j], acc[i][j]);
        }
        #pragma unroll
        for (int i = 0; i < 4; i++)
            #pragma unroll
            for (int j = 0; j < 4; j++)
                g_M[(size_t)tile*4096 + (t0+i)*64 + j0+j] =
                    (j0+j <= t0+i) ? rsum(acc[i][j]) : 0.f;
    }
    __syncthreads();

    // forward substitution: N = (I+L)^{-1} - I
    for (int i = 1; i < 64; i++) {
        if (tid < i) {
            float s = -Aa[i*68 + tid];
            for (int p = tid + 1; p < i; p++)
                s = fmaf(-Aa[i*68 + p], Nn[p*68 + tid], s);
            Nn[i*68 + tid] = s;
        }
        __syncthreads();
    }

    {   // TK = K + N K
        ull acc[4][2];
        #pragma unroll
        for (int i = 0; i < 4; i++) { acc[i][0] = 0ull; acc[i][1] = 0ull; }
        for (int jj = 0; jj < 64; jj++) {
            float nt[4];
            #pragma unroll
            for (int i = 0; i < 4; i++) nt[i] = Nn[(t0+i)*68 + jj];
            const ull* kq = (const ull*)(Ks + jj*68 + j0);
            ull k0 = kq[0], k1 = kq[1];
            #pragma unroll
            for (int i = 0; i < 4; i++) {
                ull ni = pk2(nt[i], nt[i]);
                acc[i][0] = fma2(ni, k0, acc[i][0]);
                acc[i][1] = fma2(ni, k1, acc[i][1]);
            }
        }
        #pragma unroll
        for (int i = 0; i < 4; i++) {
            float o[4];
            unpk2(acc[i][0], o[0], o[1]);
            unpk2(acc[i][1], o[2], o[3]);
            #pragma unroll
            for (int j = 0; j < 4; j++)
                g_TK[(size_t)tile*4096 + (t0+i)*64 + j0+j] = Ks[(t0+i)*68 + j0+j] + o[j];
        }
    }
    {   // TVT = (V + N V)^T
        ull acc[4][2];
        #pragma unroll
        for (int i = 0; i < 4; i++) { acc[i][0] = 0ull; acc[i][1] = 0ull; }
        for (int jj = 0; jj < 64; jj++) {
            float nt[4];
            #pragma unroll
            for (int i = 0; i < 4; i++) nt[i] = Nn[(t0+i)*68 + jj];
            const ull* vq = (const ull*)(Vs + jj*68 + j0);
            ull v0 = vq[0], v1 = vq[1];
            #pragma unroll
            for (int i = 0; i < 4; i++) {
                ull ni = pk2(nt[i], nt[i]);
                acc[i][0] = fma2(ni, v0, acc[i][0]);
                acc[i][1] = fma2(ni, v1, acc[i][1]);
            }
        }
        #pragma unroll
        for (int i = 0; i < 4; i++) {
            float o[4];
            unpk2(acc[i][0], o[0], o[1]);
            unpk2(acc[i][1], o[2], o[3]);
            #pragma unroll
            for (int j = 0; j < 4; j++)
                g_TVT[(size_t)tile*4096 + (j0+j)*64 + (t0+i)] = Vs[(t0+i)*68 + j0+j] + o[j];
        }
    }
}

// ---------------------------------------------------------------------------
// k_wy: sequential chunk recurrence, register-tiled (2t x 2n x 4 m-split),
// fused activation.  128 blocks = 8 batches x 16 n-groups(4 rows).
// ---------------------------------------------------------------------------
__global__ void __launch_bounds__(256, 1) k_wy()
{
    extern __shared__ float sm[];
    const int tid = threadIdx.x;
    const int b  = blockIdx.x >> 4;
    const int n0 = (blockIdx.x & 15) * 4;
    const int t0 = (tid >> 3) * 2;           // token pair base
    const int nb = ((tid >> 2) & 1) * 2;     // n pair base
    const int ms = tid & 3;                  // m-split
    const int nn = (tid >> 4) & 3, mo = tid & 15;  // phase C (tid<64)

    float* Ms  = sm + 17408;
    float* Kc  = sm + 21760;
    float* TVs = sm + 26112;
    float* zs  = sm + 26384;
    float* S2  = sm + 26640;
    float* Ds  = sm + 26912;
    const unsigned sb = (unsigned)__cvta_generic_to_shared(sm);

    ull s0r = 0ull, s1r = 0ull;

    for (int i = tid; i < 1024; i += 256) {   // prologue TKQ(0)
        int t = i >> 4, q = (i & 15) * 4;
        CP16(sb + (unsigned)((t*68 + q) * 4), g_TK + (size_t)b*4096 + t*64 + q);
        CP16(sb + (unsigned)((4352 + t*68 + q) * 4),
             g_KVQZ + ((size_t)(t*8+b))*256 + 128 + q);
    }
    CPCOMMIT();

    for (int c = 0; c < NCH; c++) {
        __syncthreads();
        if (tid < 64) {
            ulonglong2 w; w.x = s0r; w.y = s1r;
            *(ulonglong2*)(S2 + nn*68 + 4*mo) = w;
        }

        for (int i = tid; i < 1024; i += 256) {   // B(c): M, K
            int t = i >> 4, q = (i & 15) * 4;
            CP16(sb + (unsigned)((17408 + t*68 + q) * 4),
                 g_M + (size_t)(c*8+b)*4096 + t*64 + q);
            CP16(sb + (unsigned)((21760 + t*68 + q) * 4),
                 g_KVQZ + ((size_t)((c*64+t)*8+b))*256 + q);
        }
        if (tid < 64) {
            CP16(sb + (unsigned)((26384 + tid*4) * 4),
                 g_KVQZ + ((size_t)((c*64+tid)*8+b))*256 + 192 + n0);
            // TVs: 4 rows x 64 floats = 64 float4 (FIXED: was 16 thr x 4 floats)
            int n2 = tid >> 4, q = (tid & 15) * 4;
            CP16(sb + (unsigned)((26112 + n2*68 + q) * 4),
                 g_TVT + (size_t)(c*8+b)*4096 + (n0+n2)*64 + q);
        }
        CPCOMMIT();

        if (c + 1 < NCH) {                        // TKQ(c+1)
            int base = ((c+1) & 1) * 8704;
            for (int i = tid; i < 1024; i += 256) {
                int t = i >> 4, q = (i & 15) * 4;
                CP16(sb + (unsigned)((base + t*68 + q) * 4),
                     g_TK + (size_t)((c+1)*8+b)*4096 + t*64 + q);
                CP16(sb + (unsigned)((base + 4352 + t*68 + q) * 4),
                     g_KVQZ + ((size_t)(((c+1)*64+t)*8+b))*256 + 128 + q);
            }
        }
        CPCOMMIT();
        CPWAIT(2);                                // TKQ(c) ready
        __syncthreads();

        const float* TKs = sm + (c & 1) * 8704;
        const float* Qs  = TKs + 4352;

        // Phase A: W1 = TK S0^T, dqA = Q S0^T
        ull w2[2][2], d2[2][2];
        w2[0][0]=w2[0][1]=w2[1][0]=w2[1][1]=0ull;
        d2[0][0]=d2[0][1]=d2[1][0]=d2[1][1]=0ull;
        #pragma unroll
        for (int mm = 0; mm < 8; mm++) {
            int m2 = ms*8 + mm;
            ull tk0 = *(const ull*)(TKs + t0*68 + 2*m2);
            ull tk1 = *(const ull*)(TKs + (t0+1)*68 + 2*m2);
            ull q0  = *(const ull*)(Qs  + t0*68 + 2*m2);
            ull q1  = *(const ull*)(Qs  + (t0+1)*68 + 2*m2);
            ull sa  = *(const ull*)(S2 + nb*68 + 2*m2);
            ull sc  = *(const ull*)(S2 + (nb+1)*68 + 2*m2);
            w2[0][0]=fma2(tk0,sa,w2[0][0]); w2[0][1]=fma2(tk0,sc,w2[0][1]);
            w2[1][0]=fma2(tk1,sa,w2[1][0]); w2[1][1]=fma2(tk1,sc,w2[1][1]);
            d2[0][0]=fma2(q0,sa,d2[0][0]);  d2[0][1]=fma2(q0,sc,d2[0][1]);
            d2[1][0]=fma2(q1,sa,d2[1][0]);  d2[1][1]=fma2(q1,sc,d2[1][1]);
        }
        float w1[2][2], dqa[2][2];
        #pragma unroll
        for (int i = 0; i < 2; i++)
            #pragma unroll
            for (int j = 0; j < 2; j++) {
                float w = rsum(w2[i][j]);
                w += __shfl_xor_sync(0xffffffffu, w, 1);
                w += __shfl_xor_sync(0xffffffffu, w, 2);
                w1[i][j] = w;
                float d = rsum(d2[i][j]);
                d += __shfl_xor_sync(0xffffffffu, d, 1);
                d += __shfl_xor_sync(0xffffffffu, d, 2);
                dqa[i][j] = d;
            }

        CPWAIT(1);                                // B(c) ready
        __syncthreads();

        if (ms == 0) {
            #pragma unroll
            for (int i = 0; i < 2; i++)
                #pragma unroll
                for (int j = 0; j < 2; j++)
                    Ds[(nb+j)*68 + t0+i] = TVs[(nb+j)*68 + t0+i] - w1[i][j];
        }
        __syncthreads();

        // Phase B: dq = dqA + M * Delta, activation, store
        ull m2a[2][2];
        m2a[0][0]=m2a[0][1]=m2a[1][0]=m2a[1][1]=0ull;
        #pragma unroll
        for (int jj = 0; jj < 8; jj++) {
            int j2 = ms*8 + jj;
            ull ma = *(const ull*)(Ms + t0*68 + 2*j2);
            ull mb = *(const ull*)(Ms + (t0+1)*68 + 2*j2);
            ull da = *(const ull*)(Ds + nb*68 + 2*j2);
            ull db = *(const ull*)(Ds + (nb+1)*68 + 2*j2);
            m2a[0][0]=fma2(ma,da,m2a[0][0]); m2a[0][1]=fma2(ma,db,m2a[0][1]);
            m2a[1][0]=fma2(mb,da,m2a[1][0]); m2a[1][1]=fma2(mb,db,m2a[1][1]);
        }
        #pragma unroll
        for (int i = 0; i < 2; i++)
            #pragma unroll
            for (int j = 0; j < 2; j++) {
                float v = rsum(m2a[i][j]);
                v += __shfl_xor_sync(0xffffffffu, v, 1);
                v += __shfl_xor_sync(0xffffffffu, v, 2);
                if (ms == 0) {
                    float d = dqa[i][j] + v;
                    float z = zs[(t0+i)*4 + nb + j];
                    float ax = fabsf(d);
                    float e  = __expf(-2.f * ax);
                    float th = __fdividef(1.f - e, 1.f + e);
                    th = copysignf(th, d);
                    float sg = __fdividef(1.f, 1.f + __expf(-z));
                    g_Y[((size_t)((c*64 + t0+i)*8 + b))*64 + n0 + nb + j] = th * sg;
                }
            }

        // Phase C: S += Delta^T K  (tid<64 own S: [nn][4mo..4mo+3])
        if (tid < 64) {
            #pragma unroll 8
            for (int t = 0; t < 64; t++) {
                float d = Ds[nn*68 + t];
                ull dd = pk2(d, d);
                ull k0 = *(const ull*)(Kc + t*68 + 4*mo);
                ull k1 = *(const ull*)(Kc + t*68 + 4*mo + 2);
                s0r = fma2(dd, k0, s0r);
                s1r = fma2(dd, k1, s1r);
            }
        }
    }
}

// ---------------------------------------------------------------------------
// k_out: Out = Y @ Wout^T.  B panel resident.
// ---------------------------------------------------------------------------
__global__ void __launch_bounds__(256, 2) k_out(
    const float* __restrict__ Wout, float* __restrict__ Out)
{
    __shared__ __align__(16) float Ball[64][132];
    __shared__ __align__(16) float As[2][8][132];
    const int d0 = blockIdx.x * 128, m0 = blockIdx.y * 128;
    const int t = threadIdx.x, tx = t & 15, ty = t >> 4;
    ull acc2[8][4];
    #pragma unroll
    for (int i = 0; i < 8; i++)
        #pragma unroll
        for (int j = 0; j < 4; j++) acc2[i][j] = 0ull;

    for (int i = t; i < 2048; i += 256) {
        int d = i >> 4, kq = (i & 15) * 4;
        float4 w = *(const float4*)(Wout + (size_t)(d0 + d) * NS + kq);
        Ball[kq+0][d] = w.x; Ball[kq+1][d] = w.y;
        Ball[kq+2][d] = w.z; Ball[kq+3][d] = w.w;
    }

    const int lm = t >> 1, lk = (t & 1) * 4;
    const float* arow = g_Y + (size_t)(m0 + lm) * NS + lk;
    float4 a = *(const float4*)(arow);

    for (int c = 0; c < 8; c++) {
        const int buf = c & 1;
        As[buf][lk+0][lm] = a.x; As[buf][lk+1][lm] = a.y;
        As[buf][lk+2][lm] = a.z; As[buf][lk+3][lm] = a.w;
        if (c + 1 < 8) a = *(const float4*)(arow + (c + 1) * 8);
        __syncthreads();
        #pragma unroll
        for (int k = 0; k < 8; k++) {
            float av[8];
            *(float4*)&av[0] = *(const float4*)&As[buf][k][ty*8];
            *(float4*)&av[4] = *(const float4*)&As[buf][k][ty*8 + 4];
            const ulonglong2* bq = (const ulonglong2*)&Ball[c*8 + k][tx*8];
            ulonglong2 b01 = bq[0], b23 = bq[1];
            ull bp[4] = {b01.x, b01.y, b23.x, b23.y};
            #pragma unroll
            for (int i = 0; i < 8; i++) {
                ull ai = pk2(av[i], av[i]);
                #pragma unroll
                for (int j = 0; j < 4; j++)
                    acc2[i][j] = fma2(ai, bp[j], acc2[i][j]);
            }
        }
    }
    #pragma unroll
    for (int i = 0; i < 8; i++) {
        float o[8];
        #pragma unroll
        for (int j = 0; j < 4; j++) unpk2(acc2[i][j], o[2*j], o[2*j+1]);
        float* outp = Out + (size_t)(m0 + ty*8 + i) * DM + d0 + tx*8;
        *(float4*)(outp)     = make_float4(o[0], o[1], o[2], o[3]);
        *(float4*)(outp + 4) = make_float4(o[4], o[5], o[6], o[7]);
    }
}

// ---------------------------------------------------------------------------
extern "C" void kernel_launch(void* const* d_in, const int* in_sizes, int n_in,
                              void* d_out, int out_size)
{
    const float* x    = (const float*)d_in[0];
    const float* Win  = (const float*)d_in[1];
    const float* Wk   = (const float*)d_in[2];
    const float* Wv   = (const float*)d_in[3];
    const float* Wq   = (const float*)d_in[4];
    const float* Wz   = (const float*)d_in[5];
    const float* Wout = (const float*)d_in[6];
    float* out = (float*)d_out;

    cudaFuncSetAttribute(k_pre, cudaFuncAttributeMaxDynamicSharedMemorySize, 87040);
    cudaFuncSetAttribute(k_wy,  cudaFuncAttributeMaxDynamicSharedMemorySize, 108736);

    k_fuse<<<dim3(16, 4),  256>>>(Win, Wk, Wv, Wq, Wz);
    k_proj<<<dim3(2, 128), 256>>>(x);
    k_pre <<<256,          256, 87040>>>();
    k_wy  <<<128,          256, 108736>>>();
    k_out <<<dim3(8, 128), 256>>>(Wout, out);
}

// round 11
// speedup vs baseline: 2.2438x; 1.0629x over previous
#include <cuda_runtime.h>
#include <math.h>

#define TT 2048
#define BB 8
#define DM 1024
#define DI 2048
#define NS 64
#define MTOT (TT*BB)
#define NCH 32
#define NTILE 256

__device__ float g_WfT[DM * 256];
__device__ float g_KVQZ[(size_t)MTOT * 256];   // 0-63 k, 64-127 v, 128-191 q, 192-255 z
__device__ float g_Y[(size_t)MTOT * NS];       // activated y
__device__ float g_TK [(size_t)NTILE * 4096];  // [tile][t*64+m]
__device__ float g_TVT[(size_t)NTILE * 4096];  // [tile][n*64+t]
__device__ float g_M  [(size_t)NTILE * 4096];  // [tile][t*64+j]

typedef unsigned long long ull;
__device__ __forceinline__ ull pk2(float lo, float hi) {
    ull r; asm("mov.b64 %0, {%1, %2};" : "=l"(r) : "f"(lo), "f"(hi)); return r;
}
__device__ __forceinline__ void unpk2(ull v, float& lo, float& hi) {
    asm("mov.b64 {%0, %1}, %2;" : "=f"(lo), "=f"(hi) : "l"(v));
}
__device__ __forceinline__ ull fma2(ull a, ull b, ull c) {
    ull d; asm("fma.rn.f32x2 %0, %1, %2, %3;" : "=l"(d) : "l"(a), "l"(b), "l"(c)); return d;
}
__device__ __forceinline__ float rsum(ull v) { float lo, hi; unpk2(v, lo, hi); return lo + hi; }
#define CP16(dst, src) asm volatile("cp.async.cg.shared.global [%0], [%1], 16;" :: "r"(dst), "l"(src))
#define CPCOMMIT() asm volatile("cp.async.commit_group;" ::)
#define CPWAIT(n) asm volatile("cp.async.wait_group %0;" :: "n"(n))

// ---------------------------------------------------------------------------
__global__ void __launch_bounds__(256) k_fuse(
    const float* __restrict__ Win, const float* __restrict__ Wk,
    const float* __restrict__ Wv,  const float* __restrict__ Wq,
    const float* __restrict__ Wz)
{
    __shared__ __align__(16) float As[2][16][65];
    __shared__ __align__(16) float Bs[2][16][68];
    const int d0 = blockIdx.x * 64, m0 = blockIdx.y * 64;
    const int t = threadIdx.x, tx = t & 15, ty = t >> 4;
    ull acc2[4][2];
    #pragma unroll
    for (int i = 0; i < 4; i++) { acc2[i][0] = 0ull; acc2[i][1] = 0ull; }

    const int lm = t >> 2, lk = (t & 3) * 4;
    const int r = m0 + lm;
    const float* W = (r < 64) ? Wk : (r < 128) ? Wv : (r < 192) ? Wq : Wz;
    const float* arow = W + (size_t)(r & 63) * DI + lk;
    const int bk = t >> 4, bd = (t & 15) * 4;
    const float* bsrc = Win + (size_t)bk * DM + d0 + bd;
    unsigned bdst[2];
    bdst[0] = (unsigned)__cvta_generic_to_shared(&Bs[0][bk][bd]);
    bdst[1] = (unsigned)__cvta_generic_to_shared(&Bs[1][bk][bd]);

    float4 a = *(const float4*)(arow);
    CP16(bdst[0], bsrc); CPCOMMIT();

    for (int c = 0; c < DI / 16; c++) {
        const int buf = c & 1;
        As[buf][lk+0][lm] = a.x; As[buf][lk+1][lm] = a.y;
        As[buf][lk+2][lm] = a.z; As[buf][lk+3][lm] = a.w;
        if (c + 1 < DI / 16) a = *(const float4*)(arow + (c + 1) * 16);
        CPWAIT(0);
        __syncthreads();
        if (c + 1 < DI / 16) {
            CP16(bdst[buf ^ 1], bsrc + (size_t)(c + 1) * 16 * DM); CPCOMMIT();
        }
        #pragma unroll
        for (int k = 0; k < 16; k++) {
            float av[4];
            #pragma unroll
            for (int i = 0; i < 4; i++) av[i] = As[buf][k][ty*4 + i];
            const ull* bq = (const ull*)&Bs[buf][k][tx*4];
            ull b0 = bq[0], b1 = bq[1];
            #pragma unroll
            for (int i = 0; i < 4; i++) {
                ull ai = pk2(av[i], av[i]);
                acc2[i][0] = fma2(ai, b0, acc2[i][0]);
                acc2[i][1] = fma2(ai, b1, acc2[i][1]);
            }
        }
    }
    #pragma unroll
    for (int i = 0; i < 4; i++) {
        float o[4];
        unpk2(acc2[i][0], o[0], o[1]);
        unpk2(acc2[i][1], o[2], o[3]);
        #pragma unroll
        for (int j = 0; j < 4; j++)
            g_WfT[(size_t)(d0 + tx*4 + j) * 256 + (m0 + ty*4 + i)] = o[j];
    }
}

// ---------------------------------------------------------------------------
__global__ void __launch_bounds__(256, 2) k_proj(const float* __restrict__ X)
{
    __shared__ __align__(16) float As[2][8][132];
    __shared__ __align__(16) float Bs[2][8][132];
    const int n0 = blockIdx.x * 128, m0 = blockIdx.y * 128;
    const int t = threadIdx.x, tx = t & 15, ty = t >> 4;
    ull acc2[8][4];
    #pragma unroll
    for (int i = 0; i < 8; i++)
        #pragma unroll
        for (int j = 0; j < 4; j++) acc2[i][j] = 0ull;

    const int lm = t >> 1, lk = (t & 1) * 4;
    const int bk = t >> 5, bn = (t & 31) * 4;
    const float* arow = X + (size_t)(m0 + lm) * DM + lk;
    const float* brow = g_WfT + (size_t)bk * 256 + n0 + bn;
    unsigned bdst[2];
    bdst[0] = (unsigned)__cvta_generic_to_shared(&Bs[0][bk][bn]);
    bdst[1] = (unsigned)__cvta_generic_to_shared(&Bs[1][bk][bn]);

    float4 a = *(const float4*)(arow);
    CP16(bdst[0], brow); CPCOMMIT();

    for (int c = 0; c < DM / 8; c++) {
        const int buf = c & 1;
        As[buf][lk+0][lm] = a.x; As[buf][lk+1][lm] = a.y;
        As[buf][lk+2][lm] = a.z; As[buf][lk+3][lm] = a.w;
        if (c + 1 < DM / 8) a = *(const float4*)(arow + (c + 1) * 8);
        CPWAIT(0);
        __syncthreads();
        if (c + 1 < DM / 8) {
            CP16(bdst[buf ^ 1], brow + (size_t)(c + 1) * 8 * 256); CPCOMMIT();
        }
        #pragma unroll
        for (int k = 0; k < 8; k++) {
            float av[8];
            *(float4*)&av[0] = *(const float4*)&As[buf][k][ty*8];
            *(float4*)&av[4] = *(const float4*)&As[buf][k][ty*8 + 4];
            const ulonglong2* bq = (const ulonglong2*)&Bs[buf][k][tx*8];
            ulonglong2 b01 = bq[0], b23 = bq[1];
            ull bp[4] = {b01.x, b01.y, b23.x, b23.y};
            #pragma unroll
            for (int i = 0; i < 8; i++) {
                ull ai = pk2(av[i], av[i]);
                #pragma unroll
                for (int j = 0; j < 4; j++)
                    acc2[i][j] = fma2(ai, bp[j], acc2[i][j]);
            }
        }
    }
    #pragma unroll
    for (int i = 0; i < 8; i++) {
        float o[8];
        #pragma unroll
        for (int j = 0; j < 4; j++) unpk2(acc2[i][j], o[2*j], o[2*j+1]);
        if (n0 == 0) {
            float ss = 0.f;
            #pragma unroll
            for (int j = 0; j < 8; j++) ss = fmaf(o[j], o[j], ss);
            ss += __shfl_xor_sync(0xffffffffu, ss, 1);
            ss += __shfl_xor_sync(0xffffffffu, ss, 2);
            ss += __shfl_xor_sync(0xffffffffu, ss, 4);
            if (tx < 8) {
                float inv = __fdividef(1.f, sqrtf(ss) + 1e-6f);
                #pragma unroll
                for (int j = 0; j < 8; j++) o[j] *= inv;
            }
        }
        float* outp = g_KVQZ + (size_t)(m0 + ty*8 + i) * 256 + n0 + tx*8;
        *(float4*)(outp)     = make_float4(o[0], o[1], o[2], o[3]);
        *(float4*)(outp + 4) = make_float4(o[4], o[5], o[6], o[7]);
    }
}

// ---------------------------------------------------------------------------
__global__ void __launch_bounds__(256) k_pre()
{
    extern __shared__ float sm[];
    float* Ks = sm;
    float* Vs = sm + 4352;
    float* Qs = sm + 8704;
    float* Aa = sm + 13056;
    float* Nn = sm + 17408;

    const int tile = blockIdx.x;
    const int b = tile & 7, c = tile >> 3;
    const int tid = threadIdx.x;

    for (int i = tid; i < 3072; i += 256) {
        int mat = i >> 10, rr = i & 1023, t = rr >> 4, q = (rr & 15) * 4;
        const float* src = g_KVQZ + ((size_t)((c*64+t)*8+b)) * 256 + mat * 64 + q;
        float* dst = (mat == 0 ? Ks : mat == 1 ? Vs : Qs) + t * 68 + q;
        *(float4*)dst = *(const float4*)src;
    }
    for (int i = tid; i < 4352; i += 256) Nn[i] = 0.f;
    __syncthreads();

    const int ty = tid >> 4, tx = tid & 15;
    const int t0 = ty * 4, j0 = tx * 4;

    {   // A = K K^T
        ull acc[4][4];
        #pragma unroll
        for (int i = 0; i < 4; i++)
            #pragma unroll
            for (int j = 0; j < 4; j++) acc[i][j] = 0ull;
        for (int m2 = 0; m2 < 32; m2++) {
            ull kt[4], kj[4];
            #pragma unroll
            for (int i = 0; i < 4; i++) kt[i] = *(const ull*)(Ks + (t0+i)*68 + 2*m2);
            #pragma unroll
            for (int j = 0; j < 4; j++) kj[j] = *(const ull*)(Ks + (j0+j)*68 + 2*m2);
            #pragma unroll
            for (int i = 0; i < 4; i++)
                #pragma unroll
                for (int j = 0; j < 4; j++) acc[i][j] = fma2(kt[i], kj[j], acc[i][j]);
        }
        #pragma unroll
        for (int i = 0; i < 4; i++)
            #pragma unroll
            for (int j = 0; j < 4; j++) Aa[(t0+i)*68 + j0+j] = rsum(acc[i][j]);
    }
    {   // M = tril(Q K^T)
        ull acc[4][4];
        #pragma unroll
        for (int i = 0; i < 4; i++)
            #pragma unroll
            for (int j = 0; j < 4; j++) acc[i][j] = 0ull;
        for (int m2 = 0; m2 < 32; m2++) {
            ull qt[4], kj[4];
            #pragma unroll
            for (int i = 0; i < 4; i++) qt[i] = *(const ull*)(Qs + (t0+i)*68 + 2*m2);
            #pragma unroll
            for (int j = 0; j < 4; j++) kj[j] = *(const ull*)(Ks + (j0+j)*68 + 2*m2);
            #pragma unroll
            for (int i = 0; i < 4; i++)
                #pragma unroll
                for (int j = 0; j < 4; j++) acc[i][j] = fma2(qt[i], kj[j], acc[i][j]);
        }
        #pragma unroll
        for (int i = 0; i < 4; i++)
            #pragma unroll
            for (int j = 0; j < 4; j++)
                g_M[(size_t)tile*4096 + (t0+i)*64 + j0+j] =
                    (j0+j <= t0+i) ? rsum(acc[i][j]) : 0.f;
    }
    __syncthreads();

    // forward substitution: N = (I+L)^{-1} - I
    for (int i = 1; i < 64; i++) {
        if (tid < i) {
            float s = -Aa[i*68 + tid];
            for (int p = tid + 1; p < i; p++)
                s = fmaf(-Aa[i*68 + p], Nn[p*68 + tid], s);
            Nn[i*68 + tid] = s;
        }
        __syncthreads();
    }

    {   // TK = K + N K
        ull acc[4][2];
        #pragma unroll
        for (int i = 0; i < 4; i++) { acc[i][0] = 0ull; acc[i][1] = 0ull; }
        for (int jj = 0; jj < 64; jj++) {
            float nt[4];
            #pragma unroll
            for (int i = 0; i < 4; i++) nt[i] = Nn[(t0+i)*68 + jj];
            const ull* kq = (const ull*)(Ks + jj*68 + j0);
            ull k0 = kq[0], k1 = kq[1];
            #pragma unroll
            for (int i = 0; i < 4; i++) {
                ull ni = pk2(nt[i], nt[i]);
                acc[i][0] = fma2(ni, k0, acc[i][0]);
                acc[i][1] = fma2(ni, k1, acc[i][1]);
            }
        }
        #pragma unroll
        for (int i = 0; i < 4; i++) {
            float o[4];
            unpk2(acc[i][0], o[0], o[1]);
            unpk2(acc[i][1], o[2], o[3]);
            #pragma unroll
            for (int j = 0; j < 4; j++)
                g_TK[(size_t)tile*4096 + (t0+i)*64 + j0+j] = Ks[(t0+i)*68 + j0+j] + o[j];
        }
    }
    {   // TVT = (V + N V)^T
        ull acc[4][2];
        #pragma unroll
        for (int i = 0; i < 4; i++) { acc[i][0] = 0ull; acc[i][1] = 0ull; }
        for (int jj = 0; jj < 64; jj++) {
            float nt[4];
            #pragma unroll
            for (int i = 0; i < 4; i++) nt[i] = Nn[(t0+i)*68 + jj];
            const ull* vq = (const ull*)(Vs + jj*68 + j0);
            ull v0 = vq[0], v1 = vq[1];
            #pragma unroll
            for (int i = 0; i < 4; i++) {
                ull ni = pk2(nt[i], nt[i]);
                acc[i][0] = fma2(ni, v0, acc[i][0]);
                acc[i][1] = fma2(ni, v1, acc[i][1]);
            }
        }
        #pragma unroll
        for (int i = 0; i < 4; i++) {
            float o[4];
            unpk2(acc[i][0], o[0], o[1]);
            unpk2(acc[i][1], o[2], o[3]);
            #pragma unroll
            for (int j = 0; j < 4; j++)
                g_TVT[(size_t)tile*4096 + (j0+j)*64 + (t0+i)] = Vs[(t0+i)*68 + j0+j] + o[j];
        }
    }
}

// ---------------------------------------------------------------------------
// k_wy: broadcast-friendly layout.  128 blocks = 8 b x 16 n-groups(4).
// Phase A/B: thread=(t,n) computes full 64-length dots (no shfl).
// Phase C: all 256 threads; S kept as 4 per-quarter register partials,
// merged through smem each chunk top.
// smem floats: TKQ dbl 17408 | Ms 4352 | Kc 4352 | TVs 272 | zs 256
//              | S2 272 | Ds 272 | Sp 1088  = 28272 (113088 B)
// ---------------------------------------------------------------------------
__global__ void __launch_bounds__(256, 1) k_wy()
{
    extern __shared__ float sm[];
    const int tid = threadIdx.x;
    const int b  = blockIdx.x >> 4;
    const int n0 = (blockIdx.x & 15) * 4;
    const int tt = tid >> 2, na = tid & 3;          // phase A/B: (t, n)
    const int qq = tid >> 6;                        // phase C quarter
    const int nn = (tid >> 4) & 3, mo = tid & 15;   // phase C (row, col-quad)

    float* Ms  = sm + 17408;
    float* Kc  = sm + 21760;
    float* TVs = sm + 26112;
    float* zs  = sm + 26384;
    float* S2  = sm + 26640;
    float* Ds  = sm + 26912;
    float* Sp  = sm + 27184;
    const unsigned sb = (unsigned)__cvta_generic_to_shared(sm);

    ull s0r = 0ull, s1r = 0ull;                     // partial S over this quarter's t

    for (int i = tid; i < 1024; i += 256) {         // prologue TKQ(0)
        int t = i >> 4, q = (i & 15) * 4;
        CP16(sb + (unsigned)((t*68 + q) * 4), g_TK + (size_t)b*4096 + t*64 + q);
        CP16(sb + (unsigned)((4352 + t*68 + q) * 4),
             g_KVQZ + ((size_t)(t*8+b))*256 + 128 + q);
    }
    CPCOMMIT();

    for (int c = 0; c < NCH; c++) {
        // write per-quarter S partials (registers only; Sp untouched by cp.async)
        {
            ulonglong2 w; w.x = s0r; w.y = s1r;
            *(ulonglong2*)(Sp + qq*272 + nn*68 + 4*mo) = w;
        }
        __syncthreads();   // prev chunk's Kc/Ds reads done; Sp visible

        for (int i = tid; i < 1024; i += 256) {     // B(c): M, K
            int t = i >> 4, q = (i & 15) * 4;
            CP16(sb + (unsigned)((17408 + t*68 + q) * 4),
                 g_M + (size_t)(c*8+b)*4096 + t*64 + q);
            CP16(sb + (unsigned)((21760 + t*68 + q) * 4),
                 g_KVQZ + ((size_t)((c*64+t)*8+b))*256 + q);
        }
        if (tid < 64) {
            CP16(sb + (unsigned)((26384 + tid*4) * 4),
                 g_KVQZ + ((size_t)((c*64+tid)*8+b))*256 + 192 + n0);
            int n2 = tid >> 4, q = (tid & 15) * 4;
            CP16(sb + (unsigned)((26112 + n2*68 + q) * 4),
                 g_TVT + (size_t)(c*8+b)*4096 + (n0+n2)*64 + q);
        }
        CPCOMMIT();

        if (c + 1 < NCH) {                          // TKQ(c+1)
            int base = ((c+1) & 1) * 8704;
            for (int i = tid; i < 1024; i += 256) {
                int t = i >> 4, q = (i & 15) * 4;
                CP16(sb + (unsigned)((base + t*68 + q) * 4),
                     g_TK + (size_t)((c+1)*8+b)*4096 + t*64 + q);
                CP16(sb + (unsigned)((base + 4352 + t*68 + q) * 4),
                     g_KVQZ + ((size_t)(((c+1)*64+t)*8+b))*256 + 128 + q);
            }
        }
        CPCOMMIT();

        // merge Sp -> S2 (256 threads, 256 elements)
        {
            int nr = tid >> 6, m = tid & 63;
            float s = Sp[nr*68 + m] + Sp[272 + nr*68 + m]
                    + Sp[544 + nr*68 + m] + Sp[816 + nr*68 + m];
            S2[nr*68 + m] = s;
        }
        CPWAIT(2);                                  // TKQ(c) ready
        __syncthreads();                            // S2 visible

        const float* TKs = sm + (c & 1) * 8704;
        const float* Qs  = TKs + 4352;

        // Phase A: w1 = TK[t].S2[n], dqa = Q[t].S2[n]  (full dots, broadcast LDS)
        ull aw0 = 0ull, aw1 = 0ull, ad0 = 0ull, ad1 = 0ull;
        #pragma unroll
        for (int s = 0; s < 16; s++) {
            ulonglong2 tk = *(const ulonglong2*)(TKs + tt*68 + s*4);
            ulonglong2 qv = *(const ulonglong2*)(Qs  + tt*68 + s*4);
            ulonglong2 sv = *(const ulonglong2*)(S2  + na*68 + s*4);
            aw0 = fma2(tk.x, sv.x, aw0); aw1 = fma2(tk.y, sv.y, aw1);
            ad0 = fma2(qv.x, sv.x, ad0); ad1 = fma2(qv.y, sv.y, ad1);
        }
        float w1  = rsum(aw0) + rsum(aw1);
        float dqa = rsum(ad0) + rsum(ad1);

        CPWAIT(1);                                  // B(c) ready
        __syncthreads();

        // Delta: Ds[n][t] = TVs[n][t] - w1   (one element per thread)
        Ds[na*68 + tt] = TVs[na*68 + tt] - w1;
        __syncthreads();

        // Phase B: dq = dqa + M[t].Ds[n]; activation; store
        {
            ull ab0 = 0ull, ab1 = 0ull;
            #pragma unroll
            for (int s = 0; s < 16; s++) {
                ulonglong2 mv = *(const ulonglong2*)(Ms + tt*68 + s*4);
                ulonglong2 dv = *(const ulonglong2*)(Ds + na*68 + s*4);
                ab0 = fma2(mv.x, dv.x, ab0); ab1 = fma2(mv.y, dv.y, ab1);
            }
            float d = dqa + rsum(ab0) + rsum(ab1);
            float z = zs[tt*4 + na];
            float ax = fabsf(d);
            float e  = __expf(-2.f * ax);
            float th = __fdividef(1.f - e, 1.f + e);
            th = copysignf(th, d);
            float sg = __fdividef(1.f, 1.f + __expf(-z));
            g_Y[((size_t)((c*64 + tt)*8 + b))*64 + n0 + na] = th * sg;
        }

        // Phase C: partial S += Delta^T K over this quarter's t-range
        {
            const int tb = qq * 16;
            #pragma unroll 8
            for (int t = 0; t < 16; t++) {
                float d = Ds[nn*68 + (tb + t)];
                ull dd = pk2(d, d);
                ulonglong2 kk = *(const ulonglong2*)(Kc + (tb + t)*68 + 4*mo);
                s0r = fma2(dd, kk.x, s0r);
                s1r = fma2(dd, kk.y, s1r);
            }
        }
    }
}

// ---------------------------------------------------------------------------
__global__ void __launch_bounds__(256, 2) k_out(
    const float* __restrict__ Wout, float* __restrict__ Out)
{
    __shared__ __align__(16) float Ball[64][132];
    __shared__ __align__(16) float As[2][8][132];
    const int d0 = blockIdx.x * 128, m0 = blockIdx.y * 128;
    const int t = threadIdx.x, tx = t & 15, ty = t >> 4;
    ull acc2[8][4];
    #pragma unroll
    for (int i = 0; i < 8; i++)
        #pragma unroll
        for (int j = 0; j < 4; j++) acc2[i][j] = 0ull;

    for (int i = t; i < 2048; i += 256) {
        int d = i >> 4, kq = (i & 15) * 4;
        float4 w = *(const float4*)(Wout + (size_t)(d0 + d) * NS + kq);
        Ball[kq+0][d] = w.x; Ball[kq+1][d] = w.y;
        Ball[kq+2][d] = w.z; Ball[kq+3][d] = w.w;
    }

    const int lm = t >> 1, lk = (t & 1) * 4;
    const float* arow = g_Y + (size_t)(m0 + lm) * NS + lk;
    float4 a = *(const float4*)(arow);

    for (int c = 0; c < 8; c++) {
        const int buf = c & 1;
        As[buf][lk+0][lm] = a.x; As[buf][lk+1][lm] = a.y;
        As[buf][lk+2][lm] = a.z; As[buf][lk+3][lm] = a.w;
        if (c + 1 < 8) a = *(const float4*)(arow + (c + 1) * 8);
        __syncthreads();
        #pragma unroll
        for (int k = 0; k < 8; k++) {
            float av[8];
            *(float4*)&av[0] = *(const float4*)&As[buf][k][ty*8];
            *(float4*)&av[4] = *(const float4*)&As[buf][k][ty*8 + 4];
            const ulonglong2* bq = (const ulonglong2*)&Ball[c*8 + k][tx*8];
            ulonglong2 b01 = bq[0], b23 = bq[1];
            ull bp[4] = {b01.x, b01.y, b23.x, b23.y};
            #pragma unroll
            for (int i = 0; i < 8; i++) {
                ull ai = pk2(av[i], av[i]);
                #pragma unroll
                for (int j = 0; j < 4; j++)
                    acc2[i][j] = fma2(ai, bp[j], acc2[i][j]);
            }
        }
    }
    #pragma unroll
    for (int i = 0; i < 8; i++) {
        float o[8];
        #pragma unroll
        for (int j = 0; j < 4; j++) unpk2(acc2[i][j], o[2*j], o[2*j+1]);
        float* outp = Out + (size_t)(m0 + ty*8 + i) * DM + d0 + tx*8;
        *(float4*)(outp)     = make_float4(o[0], o[1], o[2], o[3]);
        *(float4*)(outp + 4) = make_float4(o[4], o[5], o[6], o[7]);
    }
}

// ---------------------------------------------------------------------------
extern "C" void kernel_launch(void* const* d_in, const int* in_sizes, int n_in,
                              void* d_out, int out_size)
{
    const float* x    = (const float*)d_in[0];
    const float* Win  = (const float*)d_in[1];
    const float* Wk   = (const float*)d_in[2];
    const float* Wv   = (const float*)d_in[3];
    const float* Wq   = (const float*)d_in[4];
    const float* Wz   = (const float*)d_in[5];
    const float* Wout = (const float*)d_in[6];
    float* out = (float*)d_out;

    cudaFuncSetAttribute(k_pre, cudaFuncAttributeMaxDynamicSharedMemorySize, 87040);
    cudaFuncSetAttribute(k_wy,  cudaFuncAttributeMaxDynamicSharedMemorySize, 113088);

    k_fuse<<<dim3(16, 4),  256>>>(Win, Wk, Wv, Wq, Wz);
    k_proj<<<dim3(2, 128), 256>>>(x);
    k_pre <<<256,          256, 87040>>>();
    k_wy  <<<128,          256, 113088>>>();
    k_out <<<dim3(8, 128), 256>>>(Wout, out);
}

// round 12
// speedup vs baseline: 2.2521x; 1.0037x over previous
#include <cuda_runtime.h>
#include <math.h>

#define TT 2048
#define BB 8
#define DM 1024
#define DI 2048
#define NS 64
#define MTOT (TT*BB)
#define NCH 32
#define NTILE 256

__device__ float g_WfT[DM * 256];
__device__ float g_KVQZ[(size_t)MTOT * 256];   // 0-63 k, 64-127 v, 128-191 q, 192-255 z
__device__ float g_Y[(size_t)MTOT * NS];       // activated y
__device__ float g_TK [(size_t)NTILE * 4096];  // [tile][t*64+m]
__device__ float g_TVT[(size_t)NTILE * 4096];  // [tile][n*64+t]
__device__ float g_M  [(size_t)NTILE * 4096];  // [tile][t*64+j]

typedef unsigned long long ull;
__device__ __forceinline__ ull pk2(float lo, float hi) {
    ull r; asm("mov.b64 %0, {%1, %2};" : "=l"(r) : "f"(lo), "f"(hi)); return r;
}
__device__ __forceinline__ void unpk2(ull v, float& lo, float& hi) {
    asm("mov.b64 {%0, %1}, %2;" : "=f"(lo), "=f"(hi) : "l"(v));
}
__device__ __forceinline__ ull fma2(ull a, ull b, ull c) {
    ull d; asm("fma.rn.f32x2 %0, %1, %2, %3;" : "=l"(d) : "l"(a), "l"(b), "l"(c)); return d;
}
__device__ __forceinline__ float rsum(ull v) { float lo, hi; unpk2(v, lo, hi); return lo + hi; }
#define CP16(dst, src) asm volatile("cp.async.cg.shared.global [%0], [%1], 16;" :: "r"(dst), "l"(src))
#define CPCOMMIT() asm volatile("cp.async.commit_group;" ::)
#define CPWAIT(n) asm volatile("cp.async.wait_group %0;" :: "n"(n))

// ---------------------------------------------------------------------------
__global__ void __launch_bounds__(256) k_fuse(
    const float* __restrict__ Win, const float* __restrict__ Wk,
    const float* __restrict__ Wv,  const float* __restrict__ Wq,
    const float* __restrict__ Wz)
{
    __shared__ __align__(16) float As[2][16][65];
    __shared__ __align__(16) float Bs[2][16][68];
    const int d0 = blockIdx.x * 64, m0 = blockIdx.y * 64;
    const int t = threadIdx.x, tx = t & 15, ty = t >> 4;
    ull acc2[4][2];
    #pragma unroll
    for (int i = 0; i < 4; i++) { acc2[i][0] = 0ull; acc2[i][1] = 0ull; }

    const int lm = t >> 2, lk = (t & 3) * 4;
    const int r = m0 + lm;
    const float* W = (r < 64) ? Wk : (r < 128) ? Wv : (r < 192) ? Wq : Wz;
    const float* arow = W + (size_t)(r & 63) * DI + lk;
    const int bk = t >> 4, bd = (t & 15) * 4;
    const float* bsrc = Win + (size_t)bk * DM + d0 + bd;
    unsigned bdst[2];
    bdst[0] = (unsigned)__cvta_generic_to_shared(&Bs[0][bk][bd]);
    bdst[1] = (unsigned)__cvta_generic_to_shared(&Bs[1][bk][bd]);

    float4 a = *(const float4*)(arow);
    CP16(bdst[0], bsrc); CPCOMMIT();

    for (int c = 0; c < DI / 16; c++) {
        const int buf = c & 1;
        As[buf][lk+0][lm] = a.x; As[buf][lk+1][lm] = a.y;
        As[buf][lk+2][lm] = a.z; As[buf][lk+3][lm] = a.w;
        if (c + 1 < DI / 16) a = *(const float4*)(arow + (c + 1) * 16);
        CPWAIT(0);
        __syncthreads();
        if (c + 1 < DI / 16) {
            CP16(bdst[buf ^ 1], bsrc + (size_t)(c + 1) * 16 * DM); CPCOMMIT();
        }
        #pragma unroll
        for (int k = 0; k < 16; k++) {
            float av[4];
            #pragma unroll
            for (int i = 0; i < 4; i++) av[i] = As[buf][k][ty*4 + i];
            const ull* bq = (const ull*)&Bs[buf][k][tx*4];
            ull b0 = bq[0], b1 = bq[1];
            #pragma unroll
            for (int i = 0; i < 4; i++) {
                ull ai = pk2(av[i], av[i]);
                acc2[i][0] = fma2(ai, b0, acc2[i][0]);
                acc2[i][1] = fma2(ai, b1, acc2[i][1]);
            }
        }
    }
    #pragma unroll
    for (int i = 0; i < 4; i++) {
        float o[4];
        unpk2(acc2[i][0], o[0], o[1]);
        unpk2(acc2[i][1], o[2], o[3]);
        #pragma unroll
        for (int j = 0; j < 4; j++)
            g_WfT[(size_t)(d0 + tx*4 + j) * 256 + (m0 + ty*4 + i)] = o[j];
    }
}

// ---------------------------------------------------------------------------
__global__ void __launch_bounds__(256, 2) k_proj(const float* __restrict__ X)
{
    __shared__ __align__(16) float As[2][8][132];
    __shared__ __align__(16) float Bs[2][8][132];
    const int n0 = blockIdx.x * 128, m0 = blockIdx.y * 128;
    const int t = threadIdx.x, tx = t & 15, ty = t >> 4;
    ull acc2[8][4];
    #pragma unroll
    for (int i = 0; i < 8; i++)
        #pragma unroll
        for (int j = 0; j < 4; j++) acc2[i][j] = 0ull;

    const int lm = t >> 1, lk = (t & 1) * 4;
    const int bk = t >> 5, bn = (t & 31) * 4;
    const float* arow = X + (size_t)(m0 + lm) * DM + lk;
    const float* brow = g_WfT + (size_t)bk * 256 + n0 + bn;
    unsigned bdst[2];
    bdst[0] = (unsigned)__cvta_generic_to_shared(&Bs[0][bk][bn]);
    bdst[1] = (unsigned)__cvta_generic_to_shared(&Bs[1][bk][bn]);

    float4 a = *(const float4*)(arow);
    CP16(bdst[0], brow); CPCOMMIT();

    for (int c = 0; c < DM / 8; c++) {
        const int buf = c & 1;
        As[buf][lk+0][lm] = a.x; As[buf][lk+1][lm] = a.y;
        As[buf][lk+2][lm] = a.z; As[buf][lk+3][lm] = a.w;
        if (c + 1 < DM / 8) a = *(const float4*)(arow + (c + 1) * 8);
        CPWAIT(0);
        __syncthreads();
        if (c + 1 < DM / 8) {
            CP16(bdst[buf ^ 1], brow + (size_t)(c + 1) * 8 * 256); CPCOMMIT();
        }
        #pragma unroll
        for (int k = 0; k < 8; k++) {
            float av[8];
            *(float4*)&av[0] = *(const float4*)&As[buf][k][ty*8];
            *(float4*)&av[4] = *(const float4*)&As[buf][k][ty*8 + 4];
            const ulonglong2* bq = (const ulonglong2*)&Bs[buf][k][tx*8];
            ulonglong2 b01 = bq[0], b23 = bq[1];
            ull bp[4] = {b01.x, b01.y, b23.x, b23.y};
            #pragma unroll
            for (int i = 0; i < 8; i++) {
                ull ai = pk2(av[i], av[i]);
                #pragma unroll
                for (int j = 0; j < 4; j++)
                    acc2[i][j] = fma2(ai, bp[j], acc2[i][j]);
            }
        }
    }
    #pragma unroll
    for (int i = 0; i < 8; i++) {
        float o[8];
        #pragma unroll
        for (int j = 0; j < 4; j++) unpk2(acc2[i][j], o[2*j], o[2*j+1]);
        if (n0 == 0) {
            float ss = 0.f;
            #pragma unroll
            for (int j = 0; j < 8; j++) ss = fmaf(o[j], o[j], ss);
            ss += __shfl_xor_sync(0xffffffffu, ss, 1);
            ss += __shfl_xor_sync(0xffffffffu, ss, 2);
            ss += __shfl_xor_sync(0xffffffffu, ss, 4);
            if (tx < 8) {
                float inv = __fdividef(1.f, sqrtf(ss) + 1e-6f);
                #pragma unroll
                for (int j = 0; j < 8; j++) o[j] *= inv;
            }
        }
        float* outp = g_KVQZ + (size_t)(m0 + ty*8 + i) * 256 + n0 + tx*8;
        *(float4*)(outp)     = make_float4(o[0], o[1], o[2], o[3]);
        *(float4*)(outp + 4) = make_float4(o[4], o[5], o[6], o[7]);
    }
}

// ---------------------------------------------------------------------------
__global__ void __launch_bounds__(256) k_pre()
{
    extern __shared__ float sm[];
    float* Ks = sm;
    float* Vs = sm + 4352;
    float* Qs = sm + 8704;
    float* Aa = sm + 13056;
    float* Nn = sm + 17408;

    const int tile = blockIdx.x;
    const int b = tile & 7, c = tile >> 3;
    const int tid = threadIdx.x;

    for (int i = tid; i < 3072; i += 256) {
        int mat = i >> 10, rr = i & 1023, t = rr >> 4, q = (rr & 15) * 4;
        const float* src = g_KVQZ + ((size_t)((c*64+t)*8+b)) * 256 + mat * 64 + q;
        float* dst = (mat == 0 ? Ks : mat == 1 ? Vs : Qs) + t * 68 + q;
        *(float4*)dst = *(const float4*)src;
    }
    for (int i = tid; i < 4352; i += 256) Nn[i] = 0.f;
    __syncthreads();

    const int ty = tid >> 4, tx = tid & 15;
    const int t0 = ty * 4, j0 = tx * 4;

    {   // A = K K^T
        ull acc[4][4];
        #pragma unroll
        for (int i = 0; i < 4; i++)
            #pragma unroll
            for (int j = 0; j < 4; j++) acc[i][j] = 0ull;
        for (int m2 = 0; m2 < 32; m2++) {
            ull kt[4], kj[4];
            #pragma unroll
            for (int i = 0; i < 4; i++) kt[i] = *(const ull*)(Ks + (t0+i)*68 + 2*m2);
            #pragma unroll
            for (int j = 0; j < 4; j++) kj[j] = *(const ull*)(Ks + (j0+j)*68 + 2*m2);
            #pragma unroll
            for (int i = 0; i < 4; i++)
                #pragma unroll
                for (int j = 0; j < 4; j++) acc[i][j] = fma2(kt[i], kj[j], acc[i][j]);
        }
        #pragma unroll
        for (int i = 0; i < 4; i++)
            #pragma unroll
            for (int j = 0; j < 4; j++) Aa[(t0+i)*68 + j0+j] = rsum(acc[i][j]);
    }
    {   // M = tril(Q K^T)
        ull acc[4][4];
        #pragma unroll
        for (int i = 0; i < 4; i++)
            #pragma unroll
            for (int j = 0; j < 4; j++) acc[i][j] = 0ull;
        for (int m2 = 0; m2 < 32; m2++) {
            ull qt[4], kj[4];
            #pragma unroll
            for (int i = 0; i < 4; i++) qt[i] = *(const ull*)(Qs + (t0+i)*68 + 2*m2);
            #pragma unroll
            for (int j = 0; j < 4; j++) kj[j] = *(const ull*)(Ks + (j0+j)*68 + 2*m2);
            #pragma unroll
            for (int i = 0; i < 4; i++)
                #pragma unroll
                for (int j = 0; j < 4; j++) acc[i][j] = fma2(qt[i], kj[j], acc[i][j]);
        }
        #pragma unroll
        for (int i = 0; i < 4; i++)
            #pragma unroll
            for (int j = 0; j < 4; j++)
                g_M[(size_t)tile*4096 + (t0+i)*64 + j0+j] =
                    (j0+j <= t0+i) ? rsum(acc[i][j]) : 0.f;
    }
    __syncthreads();

    // forward substitution: N = (I+L)^{-1} - I
    for (int i = 1; i < 64; i++) {
        if (tid < i) {
            float s = -Aa[i*68 + tid];
            for (int p = tid + 1; p < i; p++)
                s = fmaf(-Aa[i*68 + p], Nn[p*68 + tid], s);
            Nn[i*68 + tid] = s;
        }
        __syncthreads();
    }

    {   // TK = K + N K
        ull acc[4][2];
        #pragma unroll
        for (int i = 0; i < 4; i++) { acc[i][0] = 0ull; acc[i][1] = 0ull; }
        for (int jj = 0; jj < 64; jj++) {
            float nt[4];
            #pragma unroll
            for (int i = 0; i < 4; i++) nt[i] = Nn[(t0+i)*68 + jj];
            const ull* kq = (const ull*)(Ks + jj*68 + j0);
            ull k0 = kq[0], k1 = kq[1];
            #pragma unroll
            for (int i = 0; i < 4; i++) {
                ull ni = pk2(nt[i], nt[i]);
                acc[i][0] = fma2(ni, k0, acc[i][0]);
                acc[i][1] = fma2(ni, k1, acc[i][1]);
            }
        }
        #pragma unroll
        for (int i = 0; i < 4; i++) {
            float o[4];
            unpk2(acc[i][0], o[0], o[1]);
            unpk2(acc[i][1], o[2], o[3]);
            #pragma unroll
            for (int j = 0; j < 4; j++)
                g_TK[(size_t)tile*4096 + (t0+i)*64 + j0+j] = Ks[(t0+i)*68 + j0+j] + o[j];
        }
    }
    {   // TVT = (V + N V)^T
        ull acc[4][2];
        #pragma unroll
        for (int i = 0; i < 4; i++) { acc[i][0] = 0ull; acc[i][1] = 0ull; }
        for (int jj = 0; jj < 64; jj++) {
            float nt[4];
            #pragma unroll
            for (int i = 0; i < 4; i++) nt[i] = Nn[(t0+i)*68 + jj];
            const ull* vq = (const ull*)(Vs + jj*68 + j0);
            ull v0 = vq[0], v1 = vq[1];
            #pragma unroll
            for (int i = 0; i < 4; i++) {
                ull ni = pk2(nt[i], nt[i]);
                acc[i][0] = fma2(ni, v0, acc[i][0]);
                acc[i][1] = fma2(ni, v1, acc[i][1]);
            }
        }
        #pragma unroll
        for (int i = 0; i < 4; i++) {
            float o[4];
            unpk2(acc[i][0], o[0], o[1]);
            unpk2(acc[i][1], o[2], o[3]);
            #pragma unroll
            for (int j = 0; j < 4; j++)
                g_TVT[(size_t)tile*4096 + (j0+j)*64 + (t0+i)] = Vs[(t0+i)*68 + j0+j] + o[j];
        }
    }
}

// ---------------------------------------------------------------------------
// k_wy: fully double-buffered chunk pipeline — ALL per-chunk inputs
// (TK, Q, M, K, TV, z) prefetched one chunk ahead in a single cp.async group.
// 128 blocks = 8 b x 16 n-groups(4).
// smem floats: TKQ[2] 2x8704 | MsKc[2] 2x8704 | TVz[2] 2x544
//              | S2 272 | Ds 272 | Sp 1088  = 37536 (150144 B)
// ---------------------------------------------------------------------------
__global__ void __launch_bounds__(256, 1) k_wy()
{
    extern __shared__ float sm[];
    const int tid = threadIdx.x;
    const int b  = blockIdx.x >> 4;
    const int n0 = (blockIdx.x & 15) * 4;
    const int tt = tid >> 2, na = tid & 3;          // phase A/B: (t, n)
    const int qq = tid >> 6;                        // phase C quarter
    const int nn = (tid >> 4) & 3, mo = tid & 15;   // phase C (row, col-quad)

    float* S2 = sm + 35904;
    float* Ds = sm + 36176;
    float* Sp = sm + 36448;
    const unsigned sb = (unsigned)__cvta_generic_to_shared(sm);

    ull s0r = 0ull, s1r = 0ull;                     // partial S (this quarter's t)

    auto issue = [&](int c) {
        const int buf = c & 1;
        const unsigned tkq = (unsigned)(buf * 8704 * 4);
        const unsigned bkm = (unsigned)((17408 + buf * 8704) * 4);
        const unsigned tvz = (unsigned)((34816 + buf * 544) * 4);
        for (int i = tid; i < 1024; i += 256) {
            int t = i >> 4, q = (i & 15) * 4;
            CP16(sb + tkq + (unsigned)((t*68 + q) * 4),
                 g_TK + (size_t)(c*8+b)*4096 + t*64 + q);
            CP16(sb + tkq + (unsigned)((4352 + t*68 + q) * 4),
                 g_KVQZ + ((size_t)((c*64+t)*8+b))*256 + 128 + q);
            CP16(sb + bkm + (unsigned)((t*68 + q) * 4),
                 g_M + (size_t)(c*8+b)*4096 + t*64 + q);
            CP16(sb + bkm + (unsigned)((4352 + t*68 + q) * 4),
                 g_KVQZ + ((size_t)((c*64+t)*8+b))*256 + q);
        }
        if (tid < 64) {
            int n2 = tid >> 4, q = (tid & 15) * 4;
            CP16(sb + tvz + (unsigned)((n2*68 + q) * 4),
                 g_TVT + (size_t)(c*8+b)*4096 + (n0+n2)*64 + q);
            CP16(sb + tvz + (unsigned)((272 + tid*4) * 4),
                 g_KVQZ + ((size_t)((c*64+tid)*8+b))*256 + 192 + n0);
        }
        CPCOMMIT();
    };

    issue(0);

    for (int c = 0; c < NCH; c++) {
        {   // per-quarter S partials -> Sp
            ulonglong2 w; w.x = s0r; w.y = s1r;
            *(ulonglong2*)(Sp + qq*272 + nn*68 + 4*mo) = w;
        }
        __syncthreads();        // chunk c-1 done (frees buf (c+1)&1); Sp visible

        if (c + 1 < NCH) issue(c + 1);
        else CPCOMMIT();

        {   // merge Sp -> S2 (256 threads, 256 elements)
            int nr = tid >> 6, m = tid & 63;
            S2[nr*68 + m] = Sp[nr*68 + m] + Sp[272 + nr*68 + m]
                          + Sp[544 + nr*68 + m] + Sp[816 + nr*68 + m];
        }
        CPWAIT(1);              // group(c) complete (issued one chunk ago)
        __syncthreads();        // S2 + chunk-c data visible

        const int buf = c & 1;
        const float* TKs = sm + buf * 8704;
        const float* Qs  = TKs + 4352;
        const float* Ms  = sm + 17408 + buf * 8704;
        const float* Kc  = Ms + 4352;
        const float* TVs = sm + 34816 + buf * 544;
        const float* zs  = TVs + 272;

        // Phase A: w1 = TK[t].S2[n], dqa = Q[t].S2[n]
        ull aw0 = 0ull, aw1 = 0ull, ad0 = 0ull, ad1 = 0ull;
        #pragma unroll
        for (int s = 0; s < 16; s++) {
            ulonglong2 tk = *(const ulonglong2*)(TKs + tt*68 + s*4);
            ulonglong2 qv = *(const ulonglong2*)(Qs  + tt*68 + s*4);
            ulonglong2 sv = *(const ulonglong2*)(S2  + na*68 + s*4);
            aw0 = fma2(tk.x, sv.x, aw0); aw1 = fma2(tk.y, sv.y, aw1);
            ad0 = fma2(qv.x, sv.x, ad0); ad1 = fma2(qv.y, sv.y, ad1);
        }
        float w1  = rsum(aw0) + rsum(aw1);
        float dqa = rsum(ad0) + rsum(ad1);

        // Delta
        Ds[na*68 + tt] = TVs[na*68 + tt] - w1;
        __syncthreads();

        // Phase B: dq = dqa + M[t].Ds[n]; activation; store
        {
            ull ab0 = 0ull, ab1 = 0ull;
            #pragma unroll
            for (int s = 0; s < 16; s++) {
                ulonglong2 mv = *(const ulonglong2*)(Ms + tt*68 + s*4);
                ulonglong2 dv = *(const ulonglong2*)(Ds + na*68 + s*4);
                ab0 = fma2(mv.x, dv.x, ab0); ab1 = fma2(mv.y, dv.y, ab1);
            }
            float d = dqa + rsum(ab0) + rsum(ab1);
            float z = zs[tt*4 + na];
            float ax = fabsf(d);
            float e  = __expf(-2.f * ax);
            float th = __fdividef(1.f - e, 1.f + e);
            th = copysignf(th, d);
            float sg = __fdividef(1.f, 1.f + __expf(-z));
            g_Y[((size_t)((c*64 + tt)*8 + b))*64 + n0 + na] = th * sg;
        }

        // Phase C: partial S += Delta^T K over this quarter's t-range
        {
            const int tb = qq * 16;
            #pragma unroll 8
            for (int t = 0; t < 16; t++) {
                float d = Ds[nn*68 + (tb + t)];
                ull dd = pk2(d, d);
                ulonglong2 kk = *(const ulonglong2*)(Kc + (tb + t)*68 + 4*mo);
                s0r = fma2(dd, kk.x, s0r);
                s1r = fma2(dd, kk.y, s1r);
            }
        }
    }
}

// ---------------------------------------------------------------------------
__global__ void __launch_bounds__(256, 2) k_out(
    const float* __restrict__ Wout, float* __restrict__ Out)
{
    __shared__ __align__(16) float Ball[64][132];
    __shared__ __align__(16) float As[2][8][132];
    const int d0 = blockIdx.x * 128, m0 = blockIdx.y * 128;
    const int t = threadIdx.x, tx = t & 15, ty = t >> 4;
    ull acc2[8][4];
    #pragma unroll
    for (int i = 0; i < 8; i++)
        #pragma unroll
        for (int j = 0; j < 4; j++) acc2[i][j] = 0ull;

    for (int i = t; i < 2048; i += 256) {
        int d = i >> 4, kq = (i & 15) * 4;
        float4 w = *(const float4*)(Wout + (size_t)(d0 + d) * NS + kq);
        Ball[kq+0][d] = w.x; Ball[kq+1][d] = w.y;
        Ball[kq+2][d] = w.z; Ball[kq+3][d] = w.w;
    }

    const int lm = t >> 1, lk = (t & 1) * 4;
    const float* arow = g_Y + (size_t)(m0 + lm) * NS + lk;
    float4 a = *(const float4*)(arow);

    for (int c = 0; c < 8; c++) {
        const int buf = c & 1;
        As[buf][lk+0][lm] = a.x; As[buf][lk+1][lm] = a.y;
        As[buf][lk+2][lm] = a.z; As[buf][lk+3][lm] = a.w;
        if (c + 1 < 8) a = *(const float4*)(arow + (c + 1) * 8);
        __syncthreads();
        #pragma unroll
        for (int k = 0; k < 8; k++) {
            float av[8];
            *(float4*)&av[0] = *(const float4*)&As[buf][k][ty*8];
            *(float4*)&av[4] = *(const float4*)&As[buf][k][ty*8 + 4];
            const ulonglong2* bq = (const ulonglong2*)&Ball[c*8 + k][tx*8];
            ulonglong2 b01 = bq[0], b23 = bq[1];
            ull bp[4] = {b01.x, b01.y, b23.x, b23.y};
            #pragma unroll
            for (int i = 0; i < 8; i++) {
                ull ai = pk2(av[i], av[i]);
                #pragma unroll
                for (int j = 0; j < 4; j++)
                    acc2[i][j] = fma2(ai, bp[j], acc2[i][j]);
            }
        }
    }
    #pragma unroll
    for (int i = 0; i < 8; i++) {
        float o[8];
        #pragma unroll
        for (int j = 0; j < 4; j++) unpk2(acc2[i][j], o[2*j], o[2*j+1]);
        float* outp = Out + (size_t)(m0 + ty*8 + i) * DM + d0 + tx*8;
        *(float4*)(outp)     = make_float4(o[0], o[1], o[2], o[3]);
        *(float4*)(outp + 4) = make_float4(o[4], o[5], o[6], o[7]);
    }
}

// ---------------------------------------------------------------------------
extern "C" void kernel_launch(void* const* d_in, const int* in_sizes, int n_in,
                              void* d_out, int out_size)
{
    const float* x    = (const float*)d_in[0];
    const float* Win  = (const float*)d_in[1];
    const float* Wk   = (const float*)d_in[2];
    const float* Wv   = (const float*)d_in[3];
    const float* Wq   = (const float*)d_in[4];
    const float* Wz   = (const float*)d_in[5];
    const float* Wout = (const float*)d_in[6];
    float* out = (float*)d_out;

    cudaFuncSetAttribute(k_pre, cudaFuncAttributeMaxDynamicSharedMemorySize, 87040);
    cudaFuncSetAttribute(k_wy,  cudaFuncAttributeMaxDynamicSharedMemorySize, 150144);

    k_fuse<<<dim3(16, 4),  256>>>(Win, Wk, Wv, Wq, Wz);
    k_proj<<<dim3(2, 128), 256>>>(x);
    k_pre <<<256,          256, 87040>>>();
    k_wy  <<<128,          256, 150144>>>();
    k_out <<<dim3(8, 128), 256>>>(Wout, out);
}

// round 14
// speedup vs baseline: 2.9105x; 1.2923x over previous
#include <cuda_runtime.h>
#include <cuda_bf16.h>
#include <math.h>

#define TT 2048
#define BB 8
#define DM 1024
#define DI 2048
#define NS 64
#define MTOT (TT*BB)
#define NCH 32
#define NTILE 256

__device__ __align__(16) unsigned short g_Wbh[256 * DM];  // fused W hi, bf16, [n=256][k=1024]
__device__ __align__(16) unsigned short g_Wbl[256 * DM];  // fused W lo
__device__ float g_KVQZ[(size_t)MTOT * 256];   // 0-63 k, 64-127 v, 128-191 q, 192-255 z
__device__ float g_Y[(size_t)MTOT * NS];       // activated y
__device__ float g_TK [(size_t)NTILE * 4096];
__device__ float g_TVT[(size_t)NTILE * 4096];
__device__ float g_M  [(size_t)NTILE * 4096];

typedef unsigned long long ull;
__device__ __forceinline__ ull pk2(float lo, float hi) {
    ull r; asm("mov.b64 %0, {%1, %2};" : "=l"(r) : "f"(lo), "f"(hi)); return r;
}
__device__ __forceinline__ void unpk2(ull v, float& lo, float& hi) {
    asm("mov.b64 {%0, %1}, %2;" : "=f"(lo), "=f"(hi) : "l"(v));
}
__device__ __forceinline__ ull fma2(ull a, ull b, ull c) {
    ull d; asm("fma.rn.f32x2 %0, %1, %2, %3;" : "=l"(d) : "l"(a), "l"(b), "l"(c)); return d;
}
__device__ __forceinline__ float rsum(ull v) { float lo, hi; unpk2(v, lo, hi); return lo + hi; }
#define CP16(dst, src) asm volatile("cp.async.cg.shared.global [%0], [%1], 16;" :: "r"(dst), "l"(src))
#define CPCOMMIT() asm volatile("cp.async.commit_group;" ::)
#define CPWAIT(n) asm volatile("cp.async.wait_group %0;" :: "n"(n))

// pack two floats -> bf16x2 (lo in low half)
__device__ __forceinline__ unsigned bf2(float lo, float hi) {
    unsigned r; asm("cvt.rn.bf16x2.f32 %0, %1, %2;" : "=r"(r) : "f"(hi), "f"(lo)); return r;
}
__device__ __forceinline__ float bflo(unsigned p) { return __uint_as_float(p << 16); }
__device__ __forceinline__ float bfhi(unsigned p) { return __uint_as_float(p & 0xffff0000u); }

__device__ __forceinline__ void mma16816(float* d, const unsigned* a,
                                         unsigned b0, unsigned b1) {
    asm volatile(
        "mma.sync.aligned.m16n8k16.row.col.f32.bf16.bf16.f32 "
        "{%0,%1,%2,%3}, {%4,%5,%6,%7}, {%8,%9}, {%0,%1,%2,%3};"
        : "+f"(d[0]), "+f"(d[1]), "+f"(d[2]), "+f"(d[3])
        : "r"(a[0]), "r"(a[1]), "r"(a[2]), "r"(a[3]), "r"(b0), "r"(b1));
}

// ---------------------------------------------------------------------------
// k_fuse: fused W = Wsel @ Win, emitted as split-bf16 [n][k].
// ---------------------------------------------------------------------------
__global__ void __launch_bounds__(256) k_fuse(
    const float* __restrict__ Win, const float* __restrict__ Wk,
    const float* __restrict__ Wv,  const float* __restrict__ Wq,
    const float* __restrict__ Wz)
{
    __shared__ __align__(16) float As[2][16][65];
    __shared__ __align__(16) float Bs[2][16][68];
    const int d0 = blockIdx.x * 64, m0 = blockIdx.y * 64;
    const int t = threadIdx.x, tx = t & 15, ty = t >> 4;
    ull acc2[4][2];
    #pragma unroll
    for (int i = 0; i < 4; i++) { acc2[i][0] = 0ull; acc2[i][1] = 0ull; }

    const int lm = t >> 2, lk = (t & 3) * 4;
    const int r = m0 + lm;
    const float* W = (r < 64) ? Wk : (r < 128) ? Wv : (r < 192) ? Wq : Wz;
    const float* arow = W + (size_t)(r & 63) * DI + lk;
    const int bk = t >> 4, bd = (t & 15) * 4;
    const float* bsrc = Win + (size_t)bk * DM + d0 + bd;
    unsigned bdst[2];
    bdst[0] = (unsigned)__cvta_generic_to_shared(&Bs[0][bk][bd]);
    bdst[1] = (unsigned)__cvta_generic_to_shared(&Bs[1][bk][bd]);

    float4 a = *(const float4*)(arow);
    CP16(bdst[0], bsrc); CPCOMMIT();

    for (int c = 0; c < DI / 16; c++) {
        const int buf = c & 1;
        As[buf][lk+0][lm] = a.x; As[buf][lk+1][lm] = a.y;
        As[buf][lk+2][lm] = a.z; As[buf][lk+3][lm] = a.w;
        if (c + 1 < DI / 16) a = *(const float4*)(arow + (c + 1) * 16);
        CPWAIT(0);
        __syncthreads();
        if (c + 1 < DI / 16) {
            CP16(bdst[buf ^ 1], bsrc + (size_t)(c + 1) * 16 * DM); CPCOMMIT();
        }
        #pragma unroll
        for (int k = 0; k < 16; k++) {
            float av[4];
            #pragma unroll
            for (int i = 0; i < 4; i++) av[i] = As[buf][k][ty*4 + i];
            const ull* bq = (const ull*)&Bs[buf][k][tx*4];
            ull b0 = bq[0], b1 = bq[1];
            #pragma unroll
            for (int i = 0; i < 4; i++) {
                ull ai = pk2(av[i], av[i]);
                acc2[i][0] = fma2(ai, b0, acc2[i][0]);
                acc2[i][1] = fma2(ai, b1, acc2[i][1]);
            }
        }
    }
    #pragma unroll
    for (int i = 0; i < 4; i++) {
        float o[4];
        unpk2(acc2[i][0], o[0], o[1]);
        unpk2(acc2[i][1], o[2], o[3]);
        unsigned h01 = bf2(o[0], o[1]);
        unsigned h23 = bf2(o[2], o[3]);
        float l0 = o[0] - bflo(h01), l1 = o[1] - bfhi(h01);
        float l2 = o[2] - bflo(h23), l3 = o[3] - bfhi(h23);
        unsigned lo01 = bf2(l0, l1), lo23 = bf2(l2, l3);
        size_t idx = (size_t)(m0 + ty*4 + i) * DM + d0 + tx*4;
        ull hp, lp;
        asm("mov.b64 %0, {%1, %2};" : "=l"(hp) : "r"(h01), "r"(h23));
        asm("mov.b64 %0, {%1, %2};" : "=l"(lp) : "r"(lo01), "r"(lo23));
        *(ull*)(g_Wbh + idx) = hp;
        *(ull*)(g_Wbl + idx) = lp;
    }
}

// ---------------------------------------------------------------------------
// k_proj: KVQZ = X @ Wf^T via split-bf16 mma.sync (3 passes: hh + hl + lh).
// Grid (2 n-tiles x 128 m-tiles), 256 thr = 8 warps (4m x 2n).
// Block tile M=128,N=128,Kstep=32. Warp tile 32x64. Fused k-norm.
// smem bf16 row stride 40 (80B, 16B-aligned); per buf: Xh|Xl|Wh|Wl 5120 each.
// ---------------------------------------------------------------------------
__global__ void __launch_bounds__(256) k_proj(const float* __restrict__ X)
{
    extern __shared__ unsigned short smp[];
    const int t = threadIdx.x;
    const int n0 = blockIdx.x * 128, m0 = blockIdx.y * 128;
    const int wid = t >> 5, lane = t & 31;
    const int wm = wid & 3, wn = wid >> 2;
    const int l4 = lane >> 2, lq2 = (lane & 3) * 2;

    float acc[2][8][4];
    #pragma unroll
    for (int mi = 0; mi < 2; mi++)
        #pragma unroll
        for (int ni = 0; ni < 8; ni++)
            #pragma unroll
            for (int j = 0; j < 4; j++) acc[mi][ni][j] = 0.f;

    float4 xr[4];
    ulonglong2 wr[4];

    auto loadX = [&](int c, float4* dst) {
        #pragma unroll
        for (int i = 0; i < 4; i++) {
            int q = t + i * 256;                    // 1024 quads (128 rows x 8)
            int row = q >> 3, kq = (q & 7) * 4;
            dst[i] = *(const float4*)(X + (size_t)(m0 + row) * DM + c * 32 + kq);
        }
    };
    auto loadW = [&](int c, ulonglong2* dst) {
        #pragma unroll
        for (int i = 0; i < 4; i++) {
            int idx = t + i * 256;                  // 1024 chunks of 16B
            int mat = idx >> 9, j = idx & 511;      // 512 chunks per matrix
            int rr = j >> 2, seg = j & 3;           // 128 rows x 4 chunks(8 shorts)
            const unsigned short* src = (mat == 0 ? g_Wbh : g_Wbl)
                + (size_t)(n0 + rr) * DM + c * 32 + seg * 8;
            dst[i] = *(const ulonglong2*)src;
        }
    };

    loadX(0, xr);
    loadW(0, wr);

    for (int c = 0; c < 32; c++) {
        const int buf = c & 1;
        unsigned short* Xh = smp + buf * 20480;
        unsigned short* Xl = Xh + 5120;
        unsigned short* Wh = Xh + 10240;
        unsigned short* Wl = Xh + 15360;

        #pragma unroll
        for (int i = 0; i < 4; i++) {
            int q = t + i * 256;
            int row = q >> 3, kq = (q & 7) * 4;
            float4 v = xr[i];
            unsigned h01 = bf2(v.x, v.y), h23 = bf2(v.z, v.w);
            float l0 = v.x - bflo(h01), l1 = v.y - bfhi(h01);
            float l2 = v.z - bflo(h23), l3 = v.w - bfhi(h23);
            unsigned q01 = bf2(l0, l1), q23 = bf2(l2, l3);
            ull hp, lp;
            asm("mov.b64 %0, {%1, %2};" : "=l"(hp) : "r"(h01), "r"(h23));
            asm("mov.b64 %0, {%1, %2};" : "=l"(lp) : "r"(q01), "r"(q23));
            *(ull*)(Xh + row * 40 + kq) = hp;
            *(ull*)(Xl + row * 40 + kq) = lp;
        }
        #pragma unroll
        for (int i = 0; i < 4; i++) {
            int idx = t + i * 256;
            int mat = idx >> 9, j = idx & 511;
            int rr = j >> 2, seg = j & 3;
            *(ulonglong2*)((mat == 0 ? Wh : Wl) + rr * 40 + seg * 8) = wr[i];
        }
        if (c + 1 < 32) { loadX(c + 1, xr); loadW(c + 1, wr); }
        __syncthreads();

        #pragma unroll
        for (int kf = 0; kf < 2; kf++) {
            const int ka = kf * 16;
            unsigned ah[2][4], al[2][4];
            #pragma unroll
            for (int mi = 0; mi < 2; mi++) {
                int r0 = wm * 32 + mi * 16 + l4;
                ah[mi][0] = *(const unsigned*)(Xh + r0 * 40 + ka + lq2);
                ah[mi][1] = *(const unsigned*)(Xh + (r0 + 8) * 40 + ka + lq2);
                ah[mi][2] = *(const unsigned*)(Xh + r0 * 40 + ka + 8 + lq2);
                ah[mi][3] = *(const unsigned*)(Xh + (r0 + 8) * 40 + ka + 8 + lq2);
                al[mi][0] = *(const unsigned*)(Xl + r0 * 40 + ka + lq2);
                al[mi][1] = *(const unsigned*)(Xl + (r0 + 8) * 40 + ka + lq2);
                al[mi][2] = *(const unsigned*)(Xl + r0 * 40 + ka + 8 + lq2);
                al[mi][3] = *(const unsigned*)(Xl + (r0 + 8) * 40 + ka + 8 + lq2);
            }
            #pragma unroll
            for (int ni = 0; ni < 8; ni++) {
                int rn = wn * 64 + ni * 8 + l4;
                unsigned bh0 = *(const unsigned*)(Wh + rn * 40 + ka + lq2);
                unsigned bh1 = *(const unsigned*)(Wh + rn * 40 + ka + 8 + lq2);
                unsigned bl0 = *(const unsigned*)(Wl + rn * 40 + ka + lq2);
                unsigned bl1 = *(const unsigned*)(Wl + rn * 40 + ka + 8 + lq2);
                #pragma unroll
                for (int mi = 0; mi < 2; mi++) {
                    mma16816(acc[mi][ni], ah[mi], bh0, bh1);
                    mma16816(acc[mi][ni], ah[mi], bl0, bl1);
                    mma16816(acc[mi][ni], al[mi], bh0, bh1);
                }
            }
        }
        __syncthreads();
    }

    // fused k-normalization: k cols = global n 0..63 = (bx==0, wn==0)
    if (blockIdx.x == 0 && wn == 0) {
        #pragma unroll
        for (int mi = 0; mi < 2; mi++) {
            float ssA = 0.f, ssB = 0.f;
            #pragma unroll
            for (int ni = 0; ni < 8; ni++) {
                ssA = fmaf(acc[mi][ni][0], acc[mi][ni][0], ssA);
                ssA = fmaf(acc[mi][ni][1], acc[mi][ni][1], ssA);
                ssB = fmaf(acc[mi][ni][2], acc[mi][ni][2], ssB);
                ssB = fmaf(acc[mi][ni][3], acc[mi][ni][3], ssB);
            }
            ssA += __shfl_xor_sync(0xffffffffu, ssA, 1);
            ssA += __shfl_xor_sync(0xffffffffu, ssA, 2);
            ssB += __shfl_xor_sync(0xffffffffu, ssB, 1);
            ssB += __shfl_xor_sync(0xffffffffu, ssB, 2);
            float invA = __fdividef(1.f, sqrtf(ssA) + 1e-6f);
            float invB = __fdividef(1.f, sqrtf(ssB) + 1e-6f);
            #pragma unroll
            for (int ni = 0; ni < 8; ni++) {
                acc[mi][ni][0] *= invA; acc[mi][ni][1] *= invA;
                acc[mi][ni][2] *= invB; acc[mi][ni][3] *= invB;
            }
        }
    }

    #pragma unroll
    for (int mi = 0; mi < 2; mi++) {
        int rA = m0 + wm * 32 + mi * 16 + l4;
        #pragma unroll
        for (int ni = 0; ni < 8; ni++) {
            int cc = n0 + wn * 64 + ni * 8 + lq2;
            *(float2*)(g_KVQZ + (size_t)rA * 256 + cc) =
                make_float2(acc[mi][ni][0], acc[mi][ni][1]);
            *(float2*)(g_KVQZ + (size_t)(rA + 8) * 256 + cc) =
                make_float2(acc[mi][ni][2], acc[mi][ni][3]);
        }
    }
}

// ---------------------------------------------------------------------------
__global__ void __launch_bounds__(256) k_pre()
{
    extern __shared__ float sm[];
    float* Ks = sm;
    float* Vs = sm + 4352;
    float* Qs = sm + 8704;
    float* Aa = sm + 13056;
    float* Nn = sm + 17408;

    const int tile = blockIdx.x;
    const int b = tile & 7, c = tile >> 3;
    const int tid = threadIdx.x;

    for (int i = tid; i < 3072; i += 256) {
        int mat = i >> 10, rr = i & 1023, t = rr >> 4, q = (rr & 15) * 4;
        const float* src = g_KVQZ + ((size_t)((c*64+t)*8+b)) * 256 + mat * 64 + q;
        float* dst = (mat == 0 ? Ks : mat == 1 ? Vs : Qs) + t * 68 + q;
        *(float4*)dst = *(const float4*)src;
    }
    for (int i = tid; i < 4352; i += 256) Nn[i] = 0.f;
    __syncthreads();

    const int ty = tid >> 4, tx = tid & 15;
    const int t0 = ty * 4, j0 = tx * 4;

    {   // A = K K^T
        ull acc[4][4];
        #pragma unroll
        for (int i = 0; i < 4; i++)
            #pragma unroll
            for (int j = 0; j < 4; j++) acc[i][j] = 0ull;
        for (int m2 = 0; m2 < 32; m2++) {
            ull kt[4], kj[4];
            #pragma unroll
            for (int i = 0; i < 4; i++) kt[i] = *(const ull*)(Ks + (t0+i)*68 + 2*m2);
            #pragma unroll
            for (int j = 0; j < 4; j++) kj[j] = *(const ull*)(Ks + (j0+j)*68 + 2*m2);
            #pragma unroll
            for (int i = 0; i < 4; i++)
                #pragma unroll
                for (int j = 0; j < 4; j++) acc[i][j] = fma2(kt[i], kj[j], acc[i][j]);
        }
        #pragma unroll
        for (int i = 0; i < 4; i++)
            #pragma unroll
            for (int j = 0; j < 4; j++) Aa[(t0+i)*68 + j0+j] = rsum(acc[i][j]);
    }
    {   // M = tril(Q K^T)
        ull acc[4][4];
        #pragma unroll
        for (int i = 0; i < 4; i++)
            #pragma unroll
            for (int j = 0; j < 4; j++) acc[i][j] = 0ull;
        for (int m2 = 0; m2 < 32; m2++) {
            ull qt[4], kj[4];
            #pragma unroll
            for (int i = 0; i < 4; i++) qt[i] = *(const ull*)(Qs + (t0+i)*68 + 2*m2);
            #pragma unroll
            for (int j = 0; j < 4; j++) kj[j] = *(const ull*)(Ks + (j0+j)*68 + 2*m2);
            #pragma unroll
            for (int i = 0; i < 4; i++)
                #pragma unroll
                for (int j = 0; j < 4; j++) acc[i][j] = fma2(qt[i], kj[j], acc[i][j]);
        }
        #pragma unroll
        for (int i = 0; i < 4; i++)
            #pragma unroll
            for (int j = 0; j < 4; j++)
                g_M[(size_t)tile*4096 + (t0+i)*64 + j0+j] =
                    (j0+j <= t0+i) ? rsum(acc[i][j]) : 0.f;
    }
    __syncthreads();

    for (int i = 1; i < 64; i++) {
        if (tid < i) {
            float s = -Aa[i*68 + tid];
            for (int p = tid + 1; p < i; p++)
                s = fmaf(-Aa[i*68 + p], Nn[p*68 + tid], s);
            Nn[i*68 + tid] = s;
        }
        __syncthreads();
    }

    {   // TK = K + N K
        ull acc[4][2];
        #pragma unroll
        for (int i = 0; i < 4; i++) { acc[i][0] = 0ull; acc[i][1] = 0ull; }
        for (int jj = 0; jj < 64; jj++) {
            float nt[4];
            #pragma unroll
            for (int i = 0; i < 4; i++) nt[i] = Nn[(t0+i)*68 + jj];
            const ull* kq = (const ull*)(Ks + jj*68 + j0);
            ull k0 = kq[0], k1 = kq[1];
            #pragma unroll
            for (int i = 0; i < 4; i++) {
                ull ni = pk2(nt[i], nt[i]);
                acc[i][0] = fma2(ni, k0, acc[i][0]);
                acc[i][1] = fma2(ni, k1, acc[i][1]);
            }
        }
        #pragma unroll
        for (int i = 0; i < 4; i++) {
            float o[4];
            unpk2(acc[i][0], o[0], o[1]);
            unpk2(acc[i][1], o[2], o[3]);
            #pragma unroll
            for (int j = 0; j < 4; j++)
                g_TK[(size_t)tile*4096 + (t0+i)*64 + j0+j] = Ks[(t0+i)*68 + j0+j] + o[j];
        }
    }
    {   // TVT = (V + N V)^T
        ull acc[4][2];
        #pragma unroll
        for (int i = 0; i < 4; i++) { acc[i][0] = 0ull; acc[i][1] = 0ull; }
        for (int jj = 0; jj < 64; jj++) {
            float nt[4];
            #pragma unroll
            for (int i = 0; i < 4; i++) nt[i] = Nn[(t0+i)*68 + jj];
            const ull* vq = (const ull*)(Vs + jj*68 + j0);
            ull v0 = vq[0], v1 = vq[1];
            #pragma unroll
            for (int i = 0; i < 4; i++) {
                ull ni = pk2(nt[i], nt[i]);
                acc[i][0] = fma2(ni, v0, acc[i][0]);
                acc[i][1] = fma2(ni, v1, acc[i][1]);
            }
        }
        #pragma unroll
        for (int i = 0; i < 4; i++) {
            float o[4];
            unpk2(acc[i][0], o[0], o[1]);
            unpk2(acc[i][1], o[2], o[3]);
            #pragma unroll
            for (int j = 0; j < 4; j++)
                g_TVT[(size_t)tile*4096 + (j0+j)*64 + (t0+i)] = Vs[(t0+i)*68 + j0+j] + o[j];
        }
    }
}

// ---------------------------------------------------------------------------
// k_wy: double-buffered chunk pipeline (unchanged from R12).
// ---------------------------------------------------------------------------
__global__ void __launch_bounds__(256, 1) k_wy()
{
    extern __shared__ float sm[];
    const int tid = threadIdx.x;
    const int b  = blockIdx.x >> 4;
    const int n0 = (blockIdx.x & 15) * 4;
    const int tt = tid >> 2, na = tid & 3;
    const int qq = tid >> 6;
    const int nn = (tid >> 4) & 3, mo = tid & 15;

    float* S2 = sm + 35904;
    float* Ds = sm + 36176;
    float* Sp = sm + 36448;
    const unsigned sb = (unsigned)__cvta_generic_to_shared(sm);

    ull s0r = 0ull, s1r = 0ull;

    auto issue = [&](int c) {
        const int buf = c & 1;
        const unsigned tkq = (unsigned)(buf * 8704 * 4);
        const unsigned bkm = (unsigned)((17408 + buf * 8704) * 4);
        const unsigned tvz = (unsigned)((34816 + buf * 544) * 4);
        for (int i = tid; i < 1024; i += 256) {
            int t = i >> 4, q = (i & 15) * 4;
            CP16(sb + tkq + (unsigned)((t*68 + q) * 4),
                 g_TK + (size_t)(c*8+b)*4096 + t*64 + q);
            CP16(sb + tkq + (unsigned)((4352 + t*68 + q) * 4),
                 g_KVQZ + ((size_t)((c*64+t)*8+b))*256 + 128 + q);
            CP16(sb + bkm + (unsigned)((t*68 + q) * 4),
                 g_M + (size_t)(c*8+b)*4096 + t*64 + q);
            CP16(sb + bkm + (unsigned)((4352 + t*68 + q) * 4),
                 g_KVQZ + ((size_t)((c*64+t)*8+b))*256 + q);
        }
        if (tid < 64) {
            int n2 = tid >> 4, q = (tid & 15) * 4;
            CP16(sb + tvz + (unsigned)((n2*68 + q) * 4),
                 g_TVT + (size_t)(c*8+b)*4096 + (n0+n2)*64 + q);
            CP16(sb + tvz + (unsigned)((272 + tid*4) * 4),
                 g_KVQZ + ((size_t)((c*64+tid)*8+b))*256 + 192 + n0);
        }
        CPCOMMIT();
    };

    issue(0);

    for (int c = 0; c < NCH; c++) {
        {
            ulonglong2 w; w.x = s0r; w.y = s1r;
            *(ulonglong2*)(Sp + qq*272 + nn*68 + 4*mo) = w;
        }
        __syncthreads();

        if (c + 1 < NCH) issue(c + 1);
        else CPCOMMIT();

        {
            int nr = tid >> 6, m = tid & 63;
            S2[nr*68 + m] = Sp[nr*68 + m] + Sp[272 + nr*68 + m]
                          + Sp[544 + nr*68 + m] + Sp[816 + nr*68 + m];
        }
        CPWAIT(1);
        __syncthreads();

        const int buf = c & 1;
        const float* TKs = sm + buf * 8704;
        const float* Qs  = TKs + 4352;
        const float* Ms  = sm + 17408 + buf * 8704;
        const float* Kc  = Ms + 4352;
        const float* TVs = sm + 34816 + buf * 544;
        const float* zs  = TVs + 272;

        ull aw0 = 0ull, aw1 = 0ull, ad0 = 0ull, ad1 = 0ull;
        #pragma unroll
        for (int s = 0; s < 16; s++) {
            ulonglong2 tk = *(const ulonglong2*)(TKs + tt*68 + s*4);
            ulonglong2 qv = *(const ulonglong2*)(Qs  + tt*68 + s*4);
            ulonglong2 sv = *(const ulonglong2*)(S2  + na*68 + s*4);
            aw0 = fma2(tk.x, sv.x, aw0); aw1 = fma2(tk.y, sv.y, aw1);
            ad0 = fma2(qv.x, sv.x, ad0); ad1 = fma2(qv.y, sv.y, ad1);
        }
        float w1  = rsum(aw0) + rsum(aw1);
        float dqa = rsum(ad0) + rsum(ad1);

        Ds[na*68 + tt] = TVs[na*68 + tt] - w1;
        __syncthreads();

        {
            ull ab0 = 0ull, ab1 = 0ull;
            #pragma unroll
            for (int s = 0; s < 16; s++) {
                ulonglong2 mv = *(const ulonglong2*)(Ms + tt*68 + s*4);
                ulonglong2 dv = *(const ulonglong2*)(Ds + na*68 + s*4);
                ab0 = fma2(mv.x, dv.x, ab0); ab1 = fma2(mv.y, dv.y, ab1);
            }
            float d = dqa + rsum(ab0) + rsum(ab1);
            float z = zs[tt*4 + na];
            float ax = fabsf(d);
            float e  = __expf(-2.f * ax);
            float th = __fdividef(1.f - e, 1.f + e);
            th = copysignf(th, d);
            float sg = __fdividef(1.f, 1.f + __expf(-z));
            g_Y[((size_t)((c*64 + tt)*8 + b))*64 + n0 + na] = th * sg;
        }

        {
            const int tb = qq * 16;
            #pragma unroll 8
            for (int t = 0; t < 16; t++) {
                float d = Ds[nn*68 + (tb + t)];
                ull dd = pk2(d, d);
                ulonglong2 kk = *(const ulonglong2*)(Kc + (tb + t)*68 + 4*mo);
                s0r = fma2(dd, kk.x, s0r);
                s1r = fma2(dd, kk.y, s1r);
            }
        }
    }
}

// ---------------------------------------------------------------------------
__global__ void __launch_bounds__(256, 2) k_out(
    const float* __restrict__ Wout, float* __restrict__ Out)
{
    __shared__ __align__(16) float Ball[64][132];
    __shared__ __align__(16) float As[2][8][132];
    const int d0 = blockIdx.x * 128, m0 = blockIdx.y * 128;
    const int t = threadIdx.x, tx = t & 15, ty = t >> 4;
    ull acc2[8][4];
    #pragma unroll
    for (int i = 0; i < 8; i++)
        #pragma unroll
        for (int j = 0; j < 4; j++) acc2[i][j] = 0ull;

    for (int i = t; i < 2048; i += 256) {
        int d = i >> 4, kq = (i & 15) * 4;
        float4 w = *(const float4*)(Wout + (size_t)(d0 + d) * NS + kq);
        Ball[kq+0][d] = w.x; Ball[kq+1][d] = w.y;
        Ball[kq+2][d] = w.z; Ball[kq+3][d] = w.w;
    }

    const int lm = t >> 1, lk = (t & 1) * 4;
    const float* arow = g_Y + (size_t)(m0 + lm) * NS + lk;
    float4 a = *(const float4*)(arow);

    for (int c = 0; c < 8; c++) {
        const int buf = c & 1;
        As[buf][lk+0][lm] = a.x; As[buf][lk+1][lm] = a.y;
        As[buf][lk+2][lm] = a.z; As[buf][lk+3][lm] = a.w;
        if (c + 1 < 8) a = *(const float4*)(arow + (c + 1) * 8);
        __syncthreads();
        #pragma unroll
        for (int k = 0; k < 8; k++) {
            float av[8];
            *(float4*)&av[0] = *(const float4*)&As[buf][k][ty*8];
            *(float4*)&av[4] = *(const float4*)&As[buf][k][ty*8 + 4];
            const ulonglong2* bq = (const ulonglong2*)&Ball[c*8 + k][tx*8];
            ulonglong2 b01 = bq[0], b23 = bq[1];
            ull bp[4] = {b01.x, b01.y, b23.x, b23.y};
            #pragma unroll
            for (int i = 0; i < 8; i++) {
                ull ai = pk2(av[i], av[i]);
                #pragma unroll
                for (int j = 0; j < 4; j++)
                    acc2[i][j] = fma2(ai, bp[j], acc2[i][j]);
            }
        }
    }
    #pragma unroll
    for (int i = 0; i < 8; i++) {
        float o[8];
        #pragma unroll
        for (int j = 0; j < 4; j++) unpk2(acc2[i][j], o[2*j], o[2*j+1]);
        float* outp = Out + (size_t)(m0 + ty*8 + i) * DM + d0 + tx*8;
        *(float4*)(outp)     = make_float4(o[0], o[1], o[2], o[3]);
        *(float4*)(outp + 4) = make_float4(o[4], o[5], o[6], o[7]);
    }
}

// ---------------------------------------------------------------------------
extern "C" void kernel_launch(void* const* d_in, const int* in_sizes, int n_in,
                              void* d_out, int out_size)
{
    const float* x    = (const float*)d_in[0];
    const float* Win  = (const float*)d_in[1];
    const float* Wk   = (const float*)d_in[2];
    const float* Wv   = (const float*)d_in[3];
    const float* Wq   = (const float*)d_in[4];
    const float* Wz   = (const float*)d_in[5];
    const float* Wout = (const float*)d_in[6];
    float* out = (float*)d_out;

    cudaFuncSetAttribute(k_proj, cudaFuncAttributeMaxDynamicSharedMemorySize, 81920);
    cudaFuncSetAttribute(k_pre,  cudaFuncAttributeMaxDynamicSharedMemorySize, 87040);
    cudaFuncSetAttribute(k_wy,   cudaFuncAttributeMaxDynamicSharedMemorySize, 150144);

    k_fuse<<<dim3(16, 4),  256>>>(Win, Wk, Wv, Wq, Wz);
    k_proj<<<dim3(2, 128), 256, 81920>>>(x);
    k_pre <<<256,          256, 87040>>>();
    k_wy  <<<128,          256, 150144>>>();
    k_out <<<dim3(8, 128), 256>>>(Wout, out);
}

// round 15
// speedup vs baseline: 2.9980x; 1.0301x over previous
#include <cuda_runtime.h>
#include <cuda_bf16.h>
#include <math.h>

#define TT 2048
#define BB 8
#define DM 1024
#define DI 2048
#define NS 64
#define MTOT (TT*BB)
#define NCH 32
#define NTILE 256

__device__ __align__(16) unsigned short g_Wbh[256 * DM];  // fused W hi, bf16, [n=256][k=1024]
__device__ __align__(16) unsigned short g_Wbl[256 * DM];  // fused W lo
__device__ float g_KVQZ[(size_t)MTOT * 256];   // 0-63 k, 64-127 v, 128-191 q, 192-255 z
__device__ float g_Y[(size_t)MTOT * NS];       // activated y
__device__ float g_TK [(size_t)NTILE * 4096];
__device__ float g_TVT[(size_t)NTILE * 4096];
__device__ float g_M  [(size_t)NTILE * 4096];

typedef unsigned long long ull;
__device__ __forceinline__ ull pk2(float lo, float hi) {
    ull r; asm("mov.b64 %0, {%1, %2};" : "=l"(r) : "f"(lo), "f"(hi)); return r;
}
__device__ __forceinline__ void unpk2(ull v, float& lo, float& hi) {
    asm("mov.b64 {%0, %1}, %2;" : "=f"(lo), "=f"(hi) : "l"(v));
}
__device__ __forceinline__ ull fma2(ull a, ull b, ull c) {
    ull d; asm("fma.rn.f32x2 %0, %1, %2, %3;" : "=l"(d) : "l"(a), "l"(b), "l"(c)); return d;
}
__device__ __forceinline__ float rsum(ull v) { float lo, hi; unpk2(v, lo, hi); return lo + hi; }
#define CP16(dst, src) asm volatile("cp.async.cg.shared.global [%0], [%1], 16;" :: "r"(dst), "l"(src))
#define CPCOMMIT() asm volatile("cp.async.commit_group;" ::)
#define CPWAIT(n) asm volatile("cp.async.wait_group %0;" :: "n"(n))

// pack two floats -> bf16x2 (lo in low half)
__device__ __forceinline__ unsigned bf2(float lo, float hi) {
    unsigned r; asm("cvt.rn.bf16x2.f32 %0, %1, %2;" : "=r"(r) : "f"(hi), "f"(lo)); return r;
}
__device__ __forceinline__ float bflo(unsigned p) { return __uint_as_float(p << 16); }
__device__ __forceinline__ float bfhi(unsigned p) { return __uint_as_float(p & 0xffff0000u); }

__device__ __forceinline__ void mma16816(float* d, const unsigned* a,
                                         unsigned b0, unsigned b1) {
    asm volatile(
        "mma.sync.aligned.m16n8k16.row.col.f32.bf16.bf16.f32 "
        "{%0,%1,%2,%3}, {%4,%5,%6,%7}, {%8,%9}, {%0,%1,%2,%3};"
        : "+f"(d[0]), "+f"(d[1]), "+f"(d[2]), "+f"(d[3])
        : "r"(a[0]), "r"(a[1]), "r"(a[2]), "r"(a[3]), "r"(b0), "r"(b1));
}

// ---------------------------------------------------------------------------
// k_fuse: fused W = Wsel @ Win, emitted as split-bf16 [n][k].
// ---------------------------------------------------------------------------
__global__ void __launch_bounds__(256) k_fuse(
    const float* __restrict__ Win, const float* __restrict__ Wk,
    const float* __restrict__ Wv,  const float* __restrict__ Wq,
    const float* __restrict__ Wz)
{
    __shared__ __align__(16) float As[2][16][65];
    __shared__ __align__(16) float Bs[2][16][68];
    const int d0 = blockIdx.x * 64, m0 = blockIdx.y * 64;
    const int t = threadIdx.x, tx = t & 15, ty = t >> 4;
    ull acc2[4][2];
    #pragma unroll
    for (int i = 0; i < 4; i++) { acc2[i][0] = 0ull; acc2[i][1] = 0ull; }

    const int lm = t >> 2, lk = (t & 3) * 4;
    const int r = m0 + lm;
    const float* W = (r < 64) ? Wk : (r < 128) ? Wv : (r < 192) ? Wq : Wz;
    const float* arow = W + (size_t)(r & 63) * DI + lk;
    const int bk = t >> 4, bd = (t & 15) * 4;
    const float* bsrc = Win + (size_t)bk * DM + d0 + bd;
    unsigned bdst[2];
    bdst[0] = (unsigned)__cvta_generic_to_shared(&Bs[0][bk][bd]);
    bdst[1] = (unsigned)__cvta_generic_to_shared(&Bs[1][bk][bd]);

    float4 a = *(const float4*)(arow);
    CP16(bdst[0], bsrc); CPCOMMIT();

    for (int c = 0; c < DI / 16; c++) {
        const int buf = c & 1;
        As[buf][lk+0][lm] = a.x; As[buf][lk+1][lm] = a.y;
        As[buf][lk+2][lm] = a.z; As[buf][lk+3][lm] = a.w;
        if (c + 1 < DI / 16) a = *(const float4*)(arow + (c + 1) * 16);
        CPWAIT(0);
        __syncthreads();
        if (c + 1 < DI / 16) {
            CP16(bdst[buf ^ 1], bsrc + (size_t)(c + 1) * 16 * DM); CPCOMMIT();
        }
        #pragma unroll
        for (int k = 0; k < 16; k++) {
            float av[4];
            #pragma unroll
            for (int i = 0; i < 4; i++) av[i] = As[buf][k][ty*4 + i];
            const ull* bq = (const ull*)&Bs[buf][k][tx*4];
            ull b0 = bq[0], b1 = bq[1];
            #pragma unroll
            for (int i = 0; i < 4; i++) {
                ull ai = pk2(av[i], av[i]);
                acc2[i][0] = fma2(ai, b0, acc2[i][0]);
                acc2[i][1] = fma2(ai, b1, acc2[i][1]);
            }
        }
    }
    #pragma unroll
    for (int i = 0; i < 4; i++) {
        float o[4];
        unpk2(acc2[i][0], o[0], o[1]);
        unpk2(acc2[i][1], o[2], o[3]);
        unsigned h01 = bf2(o[0], o[1]);
        unsigned h23 = bf2(o[2], o[3]);
        float l0 = o[0] - bflo(h01), l1 = o[1] - bfhi(h01);
        float l2 = o[2] - bflo(h23), l3 = o[3] - bfhi(h23);
        unsigned lo01 = bf2(l0, l1), lo23 = bf2(l2, l3);
        size_t idx = (size_t)(m0 + ty*4 + i) * DM + d0 + tx*4;
        ull hp, lp;
        asm("mov.b64 %0, {%1, %2};" : "=l"(hp) : "r"(h01), "r"(h23));
        asm("mov.b64 %0, {%1, %2};" : "=l"(lp) : "r"(lo01), "r"(lo23));
        *(ull*)(g_Wbh + idx) = hp;
        *(ull*)(g_Wbl + idx) = lp;
    }
}

// ---------------------------------------------------------------------------
// k_proj: KVQZ = X @ Wf^T via split-bf16 mma.sync (3 passes: hh + hl + lh).
// ---------------------------------------------------------------------------
__global__ void __launch_bounds__(256) k_proj(const float* __restrict__ X)
{
    extern __shared__ unsigned short smp[];
    const int t = threadIdx.x;
    const int n0 = blockIdx.x * 128, m0 = blockIdx.y * 128;
    const int wid = t >> 5, lane = t & 31;
    const int wm = wid & 3, wn = wid >> 2;
    const int l4 = lane >> 2, lq2 = (lane & 3) * 2;

    float acc[2][8][4];
    #pragma unroll
    for (int mi = 0; mi < 2; mi++)
        #pragma unroll
        for (int ni = 0; ni < 8; ni++)
            #pragma unroll
            for (int j = 0; j < 4; j++) acc[mi][ni][j] = 0.f;

    float4 xr[4];
    ulonglong2 wr[4];

    auto loadX = [&](int c, float4* dst) {
        #pragma unroll
        for (int i = 0; i < 4; i++) {
            int q = t + i * 256;
            int row = q >> 3, kq = (q & 7) * 4;
            dst[i] = *(const float4*)(X + (size_t)(m0 + row) * DM + c * 32 + kq);
        }
    };
    auto loadW = [&](int c, ulonglong2* dst) {
        #pragma unroll
        for (int i = 0; i < 4; i++) {
            int idx = t + i * 256;
            int mat = idx >> 9, j = idx & 511;
            int rr = j >> 2, seg = j & 3;
            const unsigned short* src = (mat == 0 ? g_Wbh : g_Wbl)
                + (size_t)(n0 + rr) * DM + c * 32 + seg * 8;
            dst[i] = *(const ulonglong2*)src;
        }
    };

    loadX(0, xr);
    loadW(0, wr);

    for (int c = 0; c < 32; c++) {
        const int buf = c & 1;
        unsigned short* Xh = smp + buf * 20480;
        unsigned short* Xl = Xh + 5120;
        unsigned short* Wh = Xh + 10240;
        unsigned short* Wl = Xh + 15360;

        #pragma unroll
        for (int i = 0; i < 4; i++) {
            int q = t + i * 256;
            int row = q >> 3, kq = (q & 7) * 4;
            float4 v = xr[i];
            unsigned h01 = bf2(v.x, v.y), h23 = bf2(v.z, v.w);
            float l0 = v.x - bflo(h01), l1 = v.y - bfhi(h01);
            float l2 = v.z - bflo(h23), l3 = v.w - bfhi(h23);
            unsigned q01 = bf2(l0, l1), q23 = bf2(l2, l3);
            ull hp, lp;
            asm("mov.b64 %0, {%1, %2};" : "=l"(hp) : "r"(h01), "r"(h23));
            asm("mov.b64 %0, {%1, %2};" : "=l"(lp) : "r"(q01), "r"(q23));
            *(ull*)(Xh + row * 40 + kq) = hp;
            *(ull*)(Xl + row * 40 + kq) = lp;
        }
        #pragma unroll
        for (int i = 0; i < 4; i++) {
            int idx = t + i * 256;
            int mat = idx >> 9, j = idx & 511;
            int rr = j >> 2, seg = j & 3;
            *(ulonglong2*)((mat == 0 ? Wh : Wl) + rr * 40 + seg * 8) = wr[i];
        }
        if (c + 1 < 32) { loadX(c + 1, xr); loadW(c + 1, wr); }
        __syncthreads();

        #pragma unroll
        for (int kf = 0; kf < 2; kf++) {
            const int ka = kf * 16;
            unsigned ah[2][4], al[2][4];
            #pragma unroll
            for (int mi = 0; mi < 2; mi++) {
                int r0 = wm * 32 + mi * 16 + l4;
                ah[mi][0] = *(const unsigned*)(Xh + r0 * 40 + ka + lq2);
                ah[mi][1] = *(const unsigned*)(Xh + (r0 + 8) * 40 + ka + lq2);
                ah[mi][2] = *(const unsigned*)(Xh + r0 * 40 + ka + 8 + lq2);
                ah[mi][3] = *(const unsigned*)(Xh + (r0 + 8) * 40 + ka + 8 + lq2);
                al[mi][0] = *(const unsigned*)(Xl + r0 * 40 + ka + lq2);
                al[mi][1] = *(const unsigned*)(Xl + (r0 + 8) * 40 + ka + lq2);
                al[mi][2] = *(const unsigned*)(Xl + r0 * 40 + ka + 8 + lq2);
                al[mi][3] = *(const unsigned*)(Xl + (r0 + 8) * 40 + ka + 8 + lq2);
            }
            #pragma unroll
            for (int ni = 0; ni < 8; ni++) {
                int rn = wn * 64 + ni * 8 + l4;
                unsigned bh0 = *(const unsigned*)(Wh + rn * 40 + ka + lq2);
                unsigned bh1 = *(const unsigned*)(Wh + rn * 40 + ka + 8 + lq2);
                unsigned bl0 = *(const unsigned*)(Wl + rn * 40 + ka + lq2);
                unsigned bl1 = *(const unsigned*)(Wl + rn * 40 + ka + 8 + lq2);
                #pragma unroll
                for (int mi = 0; mi < 2; mi++) {
                    mma16816(acc[mi][ni], ah[mi], bh0, bh1);
                    mma16816(acc[mi][ni], ah[mi], bl0, bl1);
                    mma16816(acc[mi][ni], al[mi], bh0, bh1);
                }
            }
        }
        __syncthreads();
    }

    if (blockIdx.x == 0 && wn == 0) {
        #pragma unroll
        for (int mi = 0; mi < 2; mi++) {
            float ssA = 0.f, ssB = 0.f;
            #pragma unroll
            for (int ni = 0; ni < 8; ni++) {
                ssA = fmaf(acc[mi][ni][0], acc[mi][ni][0], ssA);
                ssA = fmaf(acc[mi][ni][1], acc[mi][ni][1], ssA);
                ssB = fmaf(acc[mi][ni][2], acc[mi][ni][2], ssB);
                ssB = fmaf(acc[mi][ni][3], acc[mi][ni][3], ssB);
            }
            ssA += __shfl_xor_sync(0xffffffffu, ssA, 1);
            ssA += __shfl_xor_sync(0xffffffffu, ssA, 2);
            ssB += __shfl_xor_sync(0xffffffffu, ssB, 1);
            ssB += __shfl_xor_sync(0xffffffffu, ssB, 2);
            float invA = __fdividef(1.f, sqrtf(ssA) + 1e-6f);
            float invB = __fdividef(1.f, sqrtf(ssB) + 1e-6f);
            #pragma unroll
            for (int ni = 0; ni < 8; ni++) {
                acc[mi][ni][0] *= invA; acc[mi][ni][1] *= invA;
                acc[mi][ni][2] *= invB; acc[mi][ni][3] *= invB;
            }
        }
    }

    #pragma unroll
    for (int mi = 0; mi < 2; mi++) {
        int rA = m0 + wm * 32 + mi * 16 + l4;
        #pragma unroll
        for (int ni = 0; ni < 8; ni++) {
            int cc = n0 + wn * 64 + ni * 8 + lq2;
            *(float2*)(g_KVQZ + (size_t)rA * 256 + cc) =
                make_float2(acc[mi][ni][0], acc[mi][ni][1]);
            *(float2*)(g_KVQZ + (size_t)(rA + 8) * 256 + cc) =
                make_float2(acc[mi][ni][2], acc[mi][ni][3]);
        }
    }
}

// ---------------------------------------------------------------------------
// k_pre: WY precompute. A/M GEMMs read the j-side from transposed KsT
// (lane-contiguous, conflict-free); old path had 8-way LDS conflicts.
// ---------------------------------------------------------------------------
__global__ void __launch_bounds__(256) k_pre()
{
    extern __shared__ float sm[];
    float* Ks  = sm;            // [t][m] 64x68
    float* Vs  = sm + 4352;
    float* Qs  = sm + 8704;
    float* Aa  = sm + 13056;
    float* Nn  = sm + 17408;
    float* KsT = sm + 21760;    // [m][t] 64x68

    const int tile = blockIdx.x;
    const int b = tile & 7, c = tile >> 3;
    const int tid = threadIdx.x;

    for (int i = tid; i < 3072; i += 256) {
        int mat = i >> 10, rr = i & 1023, t = rr >> 4, q = (rr & 15) * 4;
        const float* src = g_KVQZ + ((size_t)((c*64+t)*8+b)) * 256 + mat * 64 + q;
        float4 v = *(const float4*)src;
        float* dst = (mat == 0 ? Ks : mat == 1 ? Vs : Qs) + t * 68 + q;
        dst[0] = v.x; dst[1] = v.y; dst[2] = v.z; dst[3] = v.w;
        if (mat == 0) {
            KsT[(q+0)*68 + t] = v.x;
            KsT[(q+1)*68 + t] = v.y;
            KsT[(q+2)*68 + t] = v.z;
            KsT[(q+3)*68 + t] = v.w;
        }
    }
    for (int i = tid; i < 4352; i += 256) Nn[i] = 0.f;
    __syncthreads();

    const int ty = tid >> 4, tx = tid & 15;
    const int t0 = ty * 4, j0 = tx * 4;

    {   // A = K K^T : kj side from KsT (conflict-free ulonglong2)
        ull acc[4][2];
        #pragma unroll
        for (int i = 0; i < 4; i++) { acc[i][0] = 0ull; acc[i][1] = 0ull; }
        for (int m = 0; m < 64; m++) {
            ulonglong2 kj = *(const ulonglong2*)(KsT + m*68 + j0);
            float kt[4];
            #pragma unroll
            for (int i = 0; i < 4; i++) kt[i] = Ks[(t0+i)*68 + m];
            #pragma unroll
            for (int i = 0; i < 4; i++) {
                ull ki = pk2(kt[i], kt[i]);
                acc[i][0] = fma2(ki, kj.x, acc[i][0]);
                acc[i][1] = fma2(ki, kj.y, acc[i][1]);
            }
        }
        #pragma unroll
        for (int i = 0; i < 4; i++) {
            float o[4];
            unpk2(acc[i][0], o[0], o[1]);
            unpk2(acc[i][1], o[2], o[3]);
            #pragma unroll
            for (int j = 0; j < 4; j++) Aa[(t0+i)*68 + j0+j] = o[j];
        }
    }
    {   // M = tril(Q K^T) : qt broadcast rows, kj from KsT
        ull acc[4][2];
        #pragma unroll
        for (int i = 0; i < 4; i++) { acc[i][0] = 0ull; acc[i][1] = 0ull; }
        for (int m = 0; m < 64; m++) {
            ulonglong2 kj = *(const ulonglong2*)(KsT + m*68 + j0);
            float qt[4];
            #pragma unroll
            for (int i = 0; i < 4; i++) qt[i] = Qs[(t0+i)*68 + m];
            #pragma unroll
            for (int i = 0; i < 4; i++) {
                ull qi = pk2(qt[i], qt[i]);
                acc[i][0] = fma2(qi, kj.x, acc[i][0]);
                acc[i][1] = fma2(qi, kj.y, acc[i][1]);
            }
        }
        #pragma unroll
        for (int i = 0; i < 4; i++) {
            float o[4];
            unpk2(acc[i][0], o[0], o[1]);
            unpk2(acc[i][1], o[2], o[3]);
            #pragma unroll
            for (int j = 0; j < 4; j++)
                g_M[(size_t)tile*4096 + (t0+i)*64 + j0+j] =
                    (j0+j <= t0+i) ? o[j] : 0.f;
        }
    }
    __syncthreads();

    // forward substitution: N = (I+L)^{-1} - I
    for (int i = 1; i < 64; i++) {
        if (tid < i) {
            float s = -Aa[i*68 + tid];
            for (int p = tid + 1; p < i; p++)
                s = fmaf(-Aa[i*68 + p], Nn[p*68 + tid], s);
            Nn[i*68 + tid] = s;
        }
        __syncthreads();
    }

    {   // TK = K + N K   (reads already conflict-free)
        ull acc[4][2];
        #pragma unroll
        for (int i = 0; i < 4; i++) { acc[i][0] = 0ull; acc[i][1] = 0ull; }
        for (int jj = 0; jj < 64; jj++) {
            float nt[4];
            #pragma unroll
            for (int i = 0; i < 4; i++) nt[i] = Nn[(t0+i)*68 + jj];
            const ull* kq = (const ull*)(Ks + jj*68 + j0);
            ull k0 = kq[0], k1 = kq[1];
            #pragma unroll
            for (int i = 0; i < 4; i++) {
                ull ni = pk2(nt[i], nt[i]);
                acc[i][0] = fma2(ni, k0, acc[i][0]);
                acc[i][1] = fma2(ni, k1, acc[i][1]);
            }
        }
        #pragma unroll
        for (int i = 0; i < 4; i++) {
            float o[4];
            unpk2(acc[i][0], o[0], o[1]);
            unpk2(acc[i][1], o[2], o[3]);
            #pragma unroll
            for (int j = 0; j < 4; j++)
                g_TK[(size_t)tile*4096 + (t0+i)*64 + j0+j] = Ks[(t0+i)*68 + j0+j] + o[j];
        }
    }
    {   // TVT = (V + N V)^T
        ull acc[4][2];
        #pragma unroll
        for (int i = 0; i < 4; i++) { acc[i][0] = 0ull; acc[i][1] = 0ull; }
        for (int jj = 0; jj < 64; jj++) {
            float nt[4];
            #pragma unroll
            for (int i = 0; i < 4; i++) nt[i] = Nn[(t0+i)*68 + jj];
            const ull* vq = (const ull*)(Vs + jj*68 + j0);
            ull v0 = vq[0], v1 = vq[1];
            #pragma unroll
            for (int i = 0; i < 4; i++) {
                ull ni = pk2(nt[i], nt[i]);
                acc[i][0] = fma2(ni, v0, acc[i][0]);
                acc[i][1] = fma2(ni, v1, acc[i][1]);
            }
        }
        #pragma unroll
        for (int i = 0; i < 4; i++) {
            float o[4];
            unpk2(acc[i][0], o[0], o[1]);
            unpk2(acc[i][1], o[2], o[3]);
            #pragma unroll
            for (int j = 0; j < 4; j++)
                g_TVT[(size_t)tile*4096 + (j0+j)*64 + (t0+i)] = Vs[(t0+i)*68 + j0+j] + o[j];
        }
    }
}

// ---------------------------------------------------------------------------
// k_wy: double-buffered chunk pipeline (unchanged from R12/R14).
// ---------------------------------------------------------------------------
__global__ void __launch_bounds__(256, 1) k_wy()
{
    extern __shared__ float sm[];
    const int tid = threadIdx.x;
    const int b  = blockIdx.x >> 4;
    const int n0 = (blockIdx.x & 15) * 4;
    const int tt = tid >> 2, na = tid & 3;
    const int qq = tid >> 6;
    const int nn = (tid >> 4) & 3, mo = tid & 15;

    float* S2 = sm + 35904;
    float* Ds = sm + 36176;
    float* Sp = sm + 36448;
    const unsigned sb = (unsigned)__cvta_generic_to_shared(sm);

    ull s0r = 0ull, s1r = 0ull;

    auto issue = [&](int c) {
        const int buf = c & 1;
        const unsigned tkq = (unsigned)(buf * 8704 * 4);
        const unsigned bkm = (unsigned)((17408 + buf * 8704) * 4);
        const unsigned tvz = (unsigned)((34816 + buf * 544) * 4);
        for (int i = tid; i < 1024; i += 256) {
            int t = i >> 4, q = (i & 15) * 4;
            CP16(sb + tkq + (unsigned)((t*68 + q) * 4),
                 g_TK + (size_t)(c*8+b)*4096 + t*64 + q);
            CP16(sb + tkq + (unsigned)((4352 + t*68 + q) * 4),
                 g_KVQZ + ((size_t)((c*64+t)*8+b))*256 + 128 + q);
            CP16(sb + bkm + (unsigned)((t*68 + q) * 4),
                 g_M + (size_t)(c*8+b)*4096 + t*64 + q);
            CP16(sb + bkm + (unsigned)((4352 + t*68 + q) * 4),
                 g_KVQZ + ((size_t)((c*64+t)*8+b))*256 + q);
        }
        if (tid < 64) {
            int n2 = tid >> 4, q = (tid & 15) * 4;
            CP16(sb + tvz + (unsigned)((n2*68 + q) * 4),
                 g_TVT + (size_t)(c*8+b)*4096 + (n0+n2)*64 + q);
            CP16(sb + tvz + (unsigned)((272 + tid*4) * 4),
                 g_KVQZ + ((size_t)((c*64+tid)*8+b))*256 + 192 + n0);
        }
        CPCOMMIT();
    };

    issue(0);

    for (int c = 0; c < NCH; c++) {
        {
            ulonglong2 w; w.x = s0r; w.y = s1r;
            *(ulonglong2*)(Sp + qq*272 + nn*68 + 4*mo) = w;
        }
        __syncthreads();

        if (c + 1 < NCH) issue(c + 1);
        else CPCOMMIT();

        {
            int nr = tid >> 6, m = tid & 63;
            S2[nr*68 + m] = Sp[nr*68 + m] + Sp[272 + nr*68 + m]
                          + Sp[544 + nr*68 + m] + Sp[816 + nr*68 + m];
        }
        CPWAIT(1);
        __syncthreads();

        const int buf = c & 1;
        const float* TKs = sm + buf * 8704;
        const float* Qs  = TKs + 4352;
        const float* Ms  = sm + 17408 + buf * 8704;
        const float* Kc  = Ms + 4352;
        const float* TVs = sm + 34816 + buf * 544;
        const float* zs  = TVs + 272;

        ull aw0 = 0ull, aw1 = 0ull, ad0 = 0ull, ad1 = 0ull;
        #pragma unroll
        for (int s = 0; s < 16; s++) {
            ulonglong2 tk = *(const ulonglong2*)(TKs + tt*68 + s*4);
            ulonglong2 qv = *(const ulonglong2*)(Qs  + tt*68 + s*4);
            ulonglong2 sv = *(const ulonglong2*)(S2  + na*68 + s*4);
            aw0 = fma2(tk.x, sv.x, aw0); aw1 = fma2(tk.y, sv.y, aw1);
            ad0 = fma2(qv.x, sv.x, ad0); ad1 = fma2(qv.y, sv.y, ad1);
        }
        float w1  = rsum(aw0) + rsum(aw1);
        float dqa = rsum(ad0) + rsum(ad1);

        Ds[na*68 + tt] = TVs[na*68 + tt] - w1;
        __syncthreads();

        {
            ull ab0 = 0ull, ab1 = 0ull;
            #pragma unroll
            for (int s = 0; s < 16; s++) {
                ulonglong2 mv = *(const ulonglong2*)(Ms + tt*68 + s*4);
                ulonglong2 dv = *(const ulonglong2*)(Ds + na*68 + s*4);
                ab0 = fma2(mv.x, dv.x, ab0); ab1 = fma2(mv.y, dv.y, ab1);
            }
            float d = dqa + rsum(ab0) + rsum(ab1);
            float z = zs[tt*4 + na];
            float ax = fabsf(d);
            float e  = __expf(-2.f * ax);
            float th = __fdividef(1.f - e, 1.f + e);
            th = copysignf(th, d);
            float sg = __fdividef(1.f, 1.f + __expf(-z));
            g_Y[((size_t)((c*64 + tt)*8 + b))*64 + n0 + na] = th * sg;
        }

        {
            const int tb = qq * 16;
            #pragma unroll 8
            for (int t = 0; t < 16; t++) {
                float d = Ds[nn*68 + (tb + t)];
                ull dd = pk2(d, d);
                ulonglong2 kk = *(const ulonglong2*)(Kc + (tb + t)*68 + 4*mo);
                s0r = fma2(dd, kk.x, s0r);
                s1r = fma2(dd, kk.y, s1r);
            }
        }
    }
}

// ---------------------------------------------------------------------------
__global__ void __launch_bounds__(256, 2) k_out(
    const float* __restrict__ Wout, float* __restrict__ Out)
{
    __shared__ __align__(16) float Ball[64][132];
    __shared__ __align__(16) float As[2][8][132];
    const int d0 = blockIdx.x * 128, m0 = blockIdx.y * 128;
    const int t = threadIdx.x, tx = t & 15, ty = t >> 4;
    ull acc2[8][4];
    #pragma unroll
    for (int i = 0; i < 8; i++)
        #pragma unroll
        for (int j = 0; j < 4; j++) acc2[i][j] = 0ull;

    for (int i = t; i < 2048; i += 256) {
        int d = i >> 4, kq = (i & 15) * 4;
        float4 w = *(const float4*)(Wout + (size_t)(d0 + d) * NS + kq);
        Ball[kq+0][d] = w.x; Ball[kq+1][d] = w.y;
        Ball[kq+2][d] = w.z; Ball[kq+3][d] = w.w;
    }

    const int lm = t >> 1, lk = (t & 1) * 4;
    const float* arow = g_Y + (size_t)(m0 + lm) * NS + lk;
    float4 a = *(const float4*)(arow);

    for (int c = 0; c < 8; c++) {
        const int buf = c & 1;
        As[buf][lk+0][lm] = a.x; As[buf][lk+1][lm] = a.y;
        As[buf][lk+2][lm] = a.z; As[buf][lk+3][lm] = a.w;
        if (c + 1 < 8) a = *(const float4*)(arow + (c + 1) * 8);
        __syncthreads();
        #pragma unroll
        for (int k = 0; k < 8; k++) {
            float av[8];
            *(float4*)&av[0] = *(const float4*)&As[buf][k][ty*8];
            *(float4*)&av[4] = *(const float4*)&As[buf][k][ty*8 + 4];
            const ulonglong2* bq = (const ulonglong2*)&Ball[c*8 + k][tx*8];
            ulonglong2 b01 = bq[0], b23 = bq[1];
            ull bp[4] = {b01.x, b01.y, b23.x, b23.y};
            #pragma unroll
            for (int i = 0; i < 8; i++) {
                ull ai = pk2(av[i], av[i]);
                #pragma unroll
                for (int j = 0; j < 4; j++)
                    acc2[i][j] = fma2(ai, bp[j], acc2[i][j]);
            }
        }
    }
    #pragma unroll
    for (int i = 0; i < 8; i++) {
        float o[8];
        #pragma unroll
        for (int j = 0; j < 4; j++) unpk2(acc2[i][j], o[2*j], o[2*j+1]);
        float* outp = Out + (size_t)(m0 + ty*8 + i) * DM + d0 + tx*8;
        *(float4*)(outp)     = make_float4(o[0], o[1], o[2], o[3]);
        *(float4*)(outp + 4) = make_float4(o[4], o[5], o[6], o[7]);
    }
}

// ---------------------------------------------------------------------------
extern "C" void kernel_launch(void* const* d_in, const int* in_sizes, int n_in,
                              void* d_out, int out_size)
{
    const float* x    = (const float*)d_in[0];
    const float* Win  = (const float*)d_in[1];
    const float* Wk   = (const float*)d_in[2];
    const float* Wv   = (const float*)d_in[3];
    const float* Wq   = (const float*)d_in[4];
    const float* Wz   = (const float*)d_in[5];
    const float* Wout = (const float*)d_in[6];
    float* out = (float*)d_out;

    cudaFuncSetAttribute(k_proj, cudaFuncAttributeMaxDynamicSharedMemorySize, 81920);
    cudaFuncSetAttribute(k_pre,  cudaFuncAttributeMaxDynamicSharedMemorySize, 104448);
    cudaFuncSetAttribute(k_wy,   cudaFuncAttributeMaxDynamicSharedMemorySize, 150144);

    k_fuse<<<dim3(16, 4),  256>>>(Win, Wk, Wv, Wq, Wz);
    k_proj<<<dim3(2, 128), 256, 81920>>>(x);
    k_pre <<<256,          256, 104448>>>();
    k_wy  <<<128,          256, 150144>>>();
    k_out <<<dim3(8, 128), 256>>>(Wout, out);
}

// round 16
// speedup vs baseline: 3.9251x; 1.3092x over previous
#include <cuda_runtime.h>
#include <cuda_bf16.h>
#include <math.h>

#define TT 2048
#define BB 8
#define DM 1024
#define DI 2048
#define NS 64
#define MTOT (TT*BB)
#define NCH 32
#define NTILE 256

__device__ __align__(16) unsigned short g_Wbh[256 * DM];  // fused W hi, bf16, [n=256][k=1024]
__device__ __align__(16) unsigned short g_Wbl[256 * DM];  // fused W lo
__device__ float g_WfP[4 * 256 * DM];          // k-split partials of fused W
__device__ float g_KVQZ[(size_t)MTOT * 256];   // 0-63 k, 64-127 v, 128-191 q, 192-255 z
__device__ float g_Y[(size_t)MTOT * NS];       // activated y
__device__ float g_TK [(size_t)NTILE * 4096];
__device__ float g_TVT[(size_t)NTILE * 4096];
__device__ float g_M  [(size_t)NTILE * 4096];

typedef unsigned long long ull;
__device__ __forceinline__ ull pk2(float lo, float hi) {
    ull r; asm("mov.b64 %0, {%1, %2};" : "=l"(r) : "f"(lo), "f"(hi)); return r;
}
__device__ __forceinline__ void unpk2(ull v, float& lo, float& hi) {
    asm("mov.b64 {%0, %1}, %2;" : "=f"(lo), "=f"(hi) : "l"(v));
}
__device__ __forceinline__ ull fma2(ull a, ull b, ull c) {
    ull d; asm("fma.rn.f32x2 %0, %1, %2, %3;" : "=l"(d) : "l"(a), "l"(b), "l"(c)); return d;
}
__device__ __forceinline__ float rsum(ull v) { float lo, hi; unpk2(v, lo, hi); return lo + hi; }
#define CP16(dst, src) asm volatile("cp.async.cg.shared.global [%0], [%1], 16;" :: "r"(dst), "l"(src))
#define CPCOMMIT() asm volatile("cp.async.commit_group;" ::)
#define CPWAIT(n) asm volatile("cp.async.wait_group %0;" :: "n"(n))

__device__ __forceinline__ unsigned bf2(float lo, float hi) {
    unsigned r; asm("cvt.rn.bf16x2.f32 %0, %1, %2;" : "=r"(r) : "f"(hi), "f"(lo)); return r;
}
__device__ __forceinline__ float bflo(unsigned p) { return __uint_as_float(p << 16); }
__device__ __forceinline__ float bfhi(unsigned p) { return __uint_as_float(p & 0xffff0000u); }

__device__ __forceinline__ void mma16816(float* d, const unsigned* a,
                                         unsigned b0, unsigned b1) {
    asm volatile(
        "mma.sync.aligned.m16n8k16.row.col.f32.bf16.bf16.f32 "
        "{%0,%1,%2,%3}, {%4,%5,%6,%7}, {%8,%9}, {%0,%1,%2,%3};"
        : "+f"(d[0]), "+f"(d[1]), "+f"(d[2]), "+f"(d[3])
        : "r"(a[0]), "r"(a[1]), "r"(a[2]), "r"(a[3]), "r"(b0), "r"(b1));
}

// ---------------------------------------------------------------------------
// k_fuse: fused W = Wsel @ Win, K-split x4 (blockIdx.z), fp32 partials.
// ---------------------------------------------------------------------------
__global__ void __launch_bounds__(256) k_fuse(
    const float* __restrict__ Win, const float* __restrict__ Wk,
    const float* __restrict__ Wv,  const float* __restrict__ Wq,
    const float* __restrict__ Wz)
{
    __shared__ __align__(16) float As[2][16][65];
    __shared__ __align__(16) float Bs[2][16][68];
    const int d0 = blockIdx.x * 64, m0 = blockIdx.y * 64;
    const int kc = blockIdx.z;                      // K chunk of 512
    const int t = threadIdx.x, tx = t & 15, ty = t >> 4;
    ull acc2[4][2];
    #pragma unroll
    for (int i = 0; i < 4; i++) { acc2[i][0] = 0ull; acc2[i][1] = 0ull; }

    const int lm = t >> 2, lk = (t & 3) * 4;
    const int r = m0 + lm;
    const float* W = (r < 64) ? Wk : (r < 128) ? Wv : (r < 192) ? Wq : Wz;
    const float* arow = W + (size_t)(r & 63) * DI + kc * 512 + lk;
    const int bk = t >> 4, bd = (t & 15) * 4;
    const float* bsrc = Win + (size_t)(kc * 512 + bk) * DM + d0 + bd;
    unsigned bdst[2];
    bdst[0] = (unsigned)__cvta_generic_to_shared(&Bs[0][bk][bd]);
    bdst[1] = (unsigned)__cvta_generic_to_shared(&Bs[1][bk][bd]);

    float4 a = *(const float4*)(arow);
    CP16(bdst[0], bsrc); CPCOMMIT();

    for (int c = 0; c < 32; c++) {                  // 512 K / 16
        const int buf = c & 1;
        As[buf][lk+0][lm] = a.x; As[buf][lk+1][lm] = a.y;
        As[buf][lk+2][lm] = a.z; As[buf][lk+3][lm] = a.w;
        if (c + 1 < 32) a = *(const float4*)(arow + (c + 1) * 16);
        CPWAIT(0);
        __syncthreads();
        if (c + 1 < 32) {
            CP16(bdst[buf ^ 1], bsrc + (size_t)(c + 1) * 16 * DM); CPCOMMIT();
        }
        #pragma unroll
        for (int k = 0; k < 16; k++) {
            float av[4];
            #pragma unroll
            for (int i = 0; i < 4; i++) av[i] = As[buf][k][ty*4 + i];
            const ull* bq = (const ull*)&Bs[buf][k][tx*4];
            ull b0 = bq[0], b1 = bq[1];
            #pragma unroll
            for (int i = 0; i < 4; i++) {
                ull ai = pk2(av[i], av[i]);
                acc2[i][0] = fma2(ai, b0, acc2[i][0]);
                acc2[i][1] = fma2(ai, b1, acc2[i][1]);
            }
        }
    }
    #pragma unroll
    for (int i = 0; i < 4; i++) {
        float o[4];
        unpk2(acc2[i][0], o[0], o[1]);
        unpk2(acc2[i][1], o[2], o[3]);
        float* dst = g_WfP + (size_t)kc * (256 * DM)
                   + (size_t)(m0 + ty*4 + i) * DM + d0 + tx*4;
        *(float4*)dst = make_float4(o[0], o[1], o[2], o[3]);
    }
}

// ---------------------------------------------------------------------------
// k_w2b: sum 4 K-partials, split to bf16 hi/lo [n][k].
// 256 blocks x 256 thr; thread = (n, 4 consecutive k).
// ---------------------------------------------------------------------------
__global__ void __launch_bounds__(256) k_w2b()
{
    const int gid = blockIdx.x * 256 + threadIdx.x;   // 65536
    const int n = gid >> 8, d4 = (gid & 255) * 4;
    const size_t off = (size_t)n * DM + d4;
    float4 s0 = *(const float4*)(g_WfP + off);
    float4 s1 = *(const float4*)(g_WfP + 262144 + off);
    float4 s2 = *(const float4*)(g_WfP + 524288 + off);
    float4 s3 = *(const float4*)(g_WfP + 786432 + off);
    float o[4] = { s0.x + s1.x + s2.x + s3.x, s0.y + s1.y + s2.y + s3.y,
                   s0.z + s1.z + s2.z + s3.z, s0.w + s1.w + s2.w + s3.w };
    unsigned h01 = bf2(o[0], o[1]), h23 = bf2(o[2], o[3]);
    float l0 = o[0] - bflo(h01), l1 = o[1] - bfhi(h01);
    float l2 = o[2] - bflo(h23), l3 = o[3] - bfhi(h23);
    unsigned lo01 = bf2(l0, l1), lo23 = bf2(l2, l3);
    ull hp, lp;
    asm("mov.b64 %0, {%1, %2};" : "=l"(hp) : "r"(h01), "r"(h23));
    asm("mov.b64 %0, {%1, %2};" : "=l"(lp) : "r"(lo01), "r"(lo23));
    *(ull*)(g_Wbh + off) = hp;
    *(ull*)(g_Wbl + off) = lp;
}

// ---------------------------------------------------------------------------
// k_proj: KVQZ = X @ Wf^T via split-bf16 mma.sync (unchanged from R15).
// ---------------------------------------------------------------------------
__global__ void __launch_bounds__(256) k_proj(const float* __restrict__ X)
{
    extern __shared__ unsigned short smp[];
    const int t = threadIdx.x;
    const int n0 = blockIdx.x * 128, m0 = blockIdx.y * 128;
    const int wid = t >> 5, lane = t & 31;
    const int wm = wid & 3, wn = wid >> 2;
    const int l4 = lane >> 2, lq2 = (lane & 3) * 2;

    float acc[2][8][4];
    #pragma unroll
    for (int mi = 0; mi < 2; mi++)
        #pragma unroll
        for (int ni = 0; ni < 8; ni++)
            #pragma unroll
            for (int j = 0; j < 4; j++) acc[mi][ni][j] = 0.f;

    float4 xr[4];
    ulonglong2 wr[4];

    auto loadX = [&](int c, float4* dst) {
        #pragma unroll
        for (int i = 0; i < 4; i++) {
            int q = t + i * 256;
            int row = q >> 3, kq = (q & 7) * 4;
            dst[i] = *(const float4*)(X + (size_t)(m0 + row) * DM + c * 32 + kq);
        }
    };
    auto loadW = [&](int c, ulonglong2* dst) {
        #pragma unroll
        for (int i = 0; i < 4; i++) {
            int idx = t + i * 256;
            int mat = idx >> 9, j = idx & 511;
            int rr = j >> 2, seg = j & 3;
            const unsigned short* src = (mat == 0 ? g_Wbh : g_Wbl)
                + (size_t)(n0 + rr) * DM + c * 32 + seg * 8;
            dst[i] = *(const ulonglong2*)src;
        }
    };

    loadX(0, xr);
    loadW(0, wr);

    for (int c = 0; c < 32; c++) {
        const int buf = c & 1;
        unsigned short* Xh = smp + buf * 20480;
        unsigned short* Xl = Xh + 5120;
        unsigned short* Wh = Xh + 10240;
        unsigned short* Wl = Xh + 15360;

        #pragma unroll
        for (int i = 0; i < 4; i++) {
            int q = t + i * 256;
            int row = q >> 3, kq = (q & 7) * 4;
            float4 v = xr[i];
            unsigned h01 = bf2(v.x, v.y), h23 = bf2(v.z, v.w);
            float l0 = v.x - bflo(h01), l1 = v.y - bfhi(h01);
            float l2 = v.z - bflo(h23), l3 = v.w - bfhi(h23);
            unsigned q01 = bf2(l0, l1), q23 = bf2(l2, l3);
            ull hp, lp;
            asm("mov.b64 %0, {%1, %2};" : "=l"(hp) : "r"(h01), "r"(h23));
            asm("mov.b64 %0, {%1, %2};" : "=l"(lp) : "r"(q01), "r"(q23));
            *(ull*)(Xh + row * 40 + kq) = hp;
            *(ull*)(Xl + row * 40 + kq) = lp;
        }
        #pragma unroll
        for (int i = 0; i < 4; i++) {
            int idx = t + i * 256;
            int mat = idx >> 9, j = idx & 511;
            int rr = j >> 2, seg = j & 3;
            *(ulonglong2*)((mat == 0 ? Wh : Wl) + rr * 40 + seg * 8) = wr[i];
        }
        if (c + 1 < 32) { loadX(c + 1, xr); loadW(c + 1, wr); }
        __syncthreads();

        #pragma unroll
        for (int kf = 0; kf < 2; kf++) {
            const int ka = kf * 16;
            unsigned ah[2][4], al[2][4];
            #pragma unroll
            for (int mi = 0; mi < 2; mi++) {
                int r0 = wm * 32 + mi * 16 + l4;
                ah[mi][0] = *(const unsigned*)(Xh + r0 * 40 + ka + lq2);
                ah[mi][1] = *(const unsigned*)(Xh + (r0 + 8) * 40 + ka + lq2);
                ah[mi][2] = *(const unsigned*)(Xh + r0 * 40 + ka + 8 + lq2);
                ah[mi][3] = *(const unsigned*)(Xh + (r0 + 8) * 40 + ka + 8 + lq2);
                al[mi][0] = *(const unsigned*)(Xl + r0 * 40 + ka + lq2);
                al[mi][1] = *(const unsigned*)(Xl + (r0 + 8) * 40 + ka + lq2);
                al[mi][2] = *(const unsigned*)(Xl + r0 * 40 + ka + 8 + lq2);
                al[mi][3] = *(const unsigned*)(Xl + (r0 + 8) * 40 + ka + 8 + lq2);
            }
            #pragma unroll
            for (int ni = 0; ni < 8; ni++) {
                int rn = wn * 64 + ni * 8 + l4;
                unsigned bh0 = *(const unsigned*)(Wh + rn * 40 + ka + lq2);
                unsigned bh1 = *(const unsigned*)(Wh + rn * 40 + ka + 8 + lq2);
                unsigned bl0 = *(const unsigned*)(Wl + rn * 40 + ka + lq2);
                unsigned bl1 = *(const unsigned*)(Wl + rn * 40 + ka + 8 + lq2);
                #pragma unroll
                for (int mi = 0; mi < 2; mi++) {
                    mma16816(acc[mi][ni], ah[mi], bh0, bh1);
                    mma16816(acc[mi][ni], ah[mi], bl0, bl1);
                    mma16816(acc[mi][ni], al[mi], bh0, bh1);
                }
            }
        }
        __syncthreads();
    }

    if (blockIdx.x == 0 && wn == 0) {
        #pragma unroll
        for (int mi = 0; mi < 2; mi++) {
            float ssA = 0.f, ssB = 0.f;
            #pragma unroll
            for (int ni = 0; ni < 8; ni++) {
                ssA = fmaf(acc[mi][ni][0], acc[mi][ni][0], ssA);
                ssA = fmaf(acc[mi][ni][1], acc[mi][ni][1], ssA);
                ssB = fmaf(acc[mi][ni][2], acc[mi][ni][2], ssB);
                ssB = fmaf(acc[mi][ni][3], acc[mi][ni][3], ssB);
            }
            ssA += __shfl_xor_sync(0xffffffffu, ssA, 1);
            ssA += __shfl_xor_sync(0xffffffffu, ssA, 2);
            ssB += __shfl_xor_sync(0xffffffffu, ssB, 1);
            ssB += __shfl_xor_sync(0xffffffffu, ssB, 2);
            float invA = __fdividef(1.f, sqrtf(ssA) + 1e-6f);
            float invB = __fdividef(1.f, sqrtf(ssB) + 1e-6f);
            #pragma unroll
            for (int ni = 0; ni < 8; ni++) {
                acc[mi][ni][0] *= invA; acc[mi][ni][1] *= invA;
                acc[mi][ni][2] *= invB; acc[mi][ni][3] *= invB;
            }
        }
    }

    #pragma unroll
    for (int mi = 0; mi < 2; mi++) {
        int rA = m0 + wm * 32 + mi * 16 + l4;
        #pragma unroll
        for (int ni = 0; ni < 8; ni++) {
            int cc = n0 + wn * 64 + ni * 8 + lq2;
            *(float2*)(g_KVQZ + (size_t)rA * 256 + cc) =
                make_float2(acc[mi][ni][0], acc[mi][ni][1]);
            *(float2*)(g_KVQZ + (size_t)(rA + 8) * 256 + cc) =
                make_float2(acc[mi][ni][2], acc[mi][ni][3]);
        }
    }
}

// ---------------------------------------------------------------------------
// k_pre: WY precompute (unchanged from R15).
// ---------------------------------------------------------------------------
__global__ void __launch_bounds__(256) k_pre()
{
    extern __shared__ float sm[];
    float* Ks  = sm;
    float* Vs  = sm + 4352;
    float* Qs  = sm + 8704;
    float* Aa  = sm + 13056;
    float* Nn  = sm + 17408;
    float* KsT = sm + 21760;

    const int tile = blockIdx.x;
    const int b = tile & 7, c = tile >> 3;
    const int tid = threadIdx.x;

    for (int i = tid; i < 3072; i += 256) {
        int mat = i >> 10, rr = i & 1023, t = rr >> 4, q = (rr & 15) * 4;
        const float* src = g_KVQZ + ((size_t)((c*64+t)*8+b)) * 256 + mat * 64 + q;
        float4 v = *(const float4*)src;
        float* dst = (mat == 0 ? Ks : mat == 1 ? Vs : Qs) + t * 68 + q;
        dst[0] = v.x; dst[1] = v.y; dst[2] = v.z; dst[3] = v.w;
        if (mat == 0) {
            KsT[(q+0)*68 + t] = v.x;
            KsT[(q+1)*68 + t] = v.y;
            KsT[(q+2)*68 + t] = v.z;
            KsT[(q+3)*68 + t] = v.w;
        }
    }
    for (int i = tid; i < 4352; i += 256) Nn[i] = 0.f;
    __syncthreads();

    const int ty = tid >> 4, tx = tid & 15;
    const int t0 = ty * 4, j0 = tx * 4;

    {   // A = K K^T
        ull acc[4][2];
        #pragma unroll
        for (int i = 0; i < 4; i++) { acc[i][0] = 0ull; acc[i][1] = 0ull; }
        for (int m = 0; m < 64; m++) {
            ulonglong2 kj = *(const ulonglong2*)(KsT + m*68 + j0);
            float kt[4];
            #pragma unroll
            for (int i = 0; i < 4; i++) kt[i] = Ks[(t0+i)*68 + m];
            #pragma unroll
            for (int i = 0; i < 4; i++) {
                ull ki = pk2(kt[i], kt[i]);
                acc[i][0] = fma2(ki, kj.x, acc[i][0]);
                acc[i][1] = fma2(ki, kj.y, acc[i][1]);
            }
        }
        #pragma unroll
        for (int i = 0; i < 4; i++) {
            float o[4];
            unpk2(acc[i][0], o[0], o[1]);
            unpk2(acc[i][1], o[2], o[3]);
            #pragma unroll
            for (int j = 0; j < 4; j++) Aa[(t0+i)*68 + j0+j] = o[j];
        }
    }
    {   // M = tril(Q K^T)
        ull acc[4][2];
        #pragma unroll
        for (int i = 0; i < 4; i++) { acc[i][0] = 0ull; acc[i][1] = 0ull; }
        for (int m = 0; m < 64; m++) {
            ulonglong2 kj = *(const ulonglong2*)(KsT + m*68 + j0);
            float qt[4];
            #pragma unroll
            for (int i = 0; i < 4; i++) qt[i] = Qs[(t0+i)*68 + m];
            #pragma unroll
            for (int i = 0; i < 4; i++) {
                ull qi = pk2(qt[i], qt[i]);
                acc[i][0] = fma2(qi, kj.x, acc[i][0]);
                acc[i][1] = fma2(qi, kj.y, acc[i][1]);
            }
        }
        #pragma unroll
        for (int i = 0; i < 4; i++) {
            float o[4];
            unpk2(acc[i][0], o[0], o[1]);
            unpk2(acc[i][1], o[2], o[3]);
            #pragma unroll
            for (int j = 0; j < 4; j++)
                g_M[(size_t)tile*4096 + (t0+i)*64 + j0+j] =
                    (j0+j <= t0+i) ? o[j] : 0.f;
        }
    }
    __syncthreads();

    for (int i = 1; i < 64; i++) {
        if (tid < i) {
            float s = -Aa[i*68 + tid];
            for (int p = tid + 1; p < i; p++)
                s = fmaf(-Aa[i*68 + p], Nn[p*68 + tid], s);
            Nn[i*68 + tid] = s;
        }
        __syncthreads();
    }

    {   // TK = K + N K
        ull acc[4][2];
        #pragma unroll
        for (int i = 0; i < 4; i++) { acc[i][0] = 0ull; acc[i][1] = 0ull; }
        for (int jj = 0; jj < 64; jj++) {
            float nt[4];
            #pragma unroll
            for (int i = 0; i < 4; i++) nt[i] = Nn[(t0+i)*68 + jj];
            const ull* kq = (const ull*)(Ks + jj*68 + j0);
            ull k0 = kq[0], k1 = kq[1];
            #pragma unroll
            for (int i = 0; i < 4; i++) {
                ull ni = pk2(nt[i], nt[i]);
                acc[i][0] = fma2(ni, k0, acc[i][0]);
                acc[i][1] = fma2(ni, k1, acc[i][1]);
            }
        }
        #pragma unroll
        for (int i = 0; i < 4; i++) {
            float o[4];
            unpk2(acc[i][0], o[0], o[1]);
            unpk2(acc[i][1], o[2], o[3]);
            #pragma unroll
            for (int j = 0; j < 4; j++)
                g_TK[(size_t)tile*4096 + (t0+i)*64 + j0+j] = Ks[(t0+i)*68 + j0+j] + o[j];
        }
    }
    {   // TVT = (V + N V)^T
        ull acc[4][2];
        #pragma unroll
        for (int i = 0; i < 4; i++) { acc[i][0] = 0ull; acc[i][1] = 0ull; }
        for (int jj = 0; jj < 64; jj++) {
            float nt[4];
            #pragma unroll
            for (int i = 0; i < 4; i++) nt[i] = Nn[(t0+i)*68 + jj];
            const ull* vq = (const ull*)(Vs + jj*68 + j0);
            ull v0 = vq[0], v1 = vq[1];
            #pragma unroll
            for (int i = 0; i < 4; i++) {
                ull ni = pk2(nt[i], nt[i]);
                acc[i][0] = fma2(ni, v0, acc[i][0]);
                acc[i][1] = fma2(ni, v1, acc[i][1]);
            }
        }
        #pragma unroll
        for (int i = 0; i < 4; i++) {
            float o[4];
            unpk2(acc[i][0], o[0], o[1]);
            unpk2(acc[i][1], o[2], o[3]);
            #pragma unroll
            for (int j = 0; j < 4; j++)
                g_TVT[(size_t)tile*4096 + (j0+j)*64 + (t0+i)] = Vs[(t0+i)*68 + j0+j] + o[j];
        }
    }
}

// ---------------------------------------------------------------------------
// k_wy: double-buffered chunk pipeline (unchanged from R12/R15).
// ---------------------------------------------------------------------------
__global__ void __launch_bounds__(256, 1) k_wy()
{
    extern __shared__ float sm[];
    const int tid = threadIdx.x;
    const int b  = blockIdx.x >> 4;
    const int n0 = (blockIdx.x & 15) * 4;
    const int tt = tid >> 2, na = tid & 3;
    const int qq = tid >> 6;
    const int nn = (tid >> 4) & 3, mo = tid & 15;

    float* S2 = sm + 35904;
    float* Ds = sm + 36176;
    float* Sp = sm + 36448;
    const unsigned sb = (unsigned)__cvta_generic_to_shared(sm);

    ull s0r = 0ull, s1r = 0ull;

    auto issue = [&](int c) {
        const int buf = c & 1;
        const unsigned tkq = (unsigned)(buf * 8704 * 4);
        const unsigned bkm = (unsigned)((17408 + buf * 8704) * 4);
        const unsigned tvz = (unsigned)((34816 + buf * 544) * 4);
        for (int i = tid; i < 1024; i += 256) {
            int t = i >> 4, q = (i & 15) * 4;
            CP16(sb + tkq + (unsigned)((t*68 + q) * 4),
                 g_TK + (size_t)(c*8+b)*4096 + t*64 + q);
            CP16(sb + tkq + (unsigned)((4352 + t*68 + q) * 4),
                 g_KVQZ + ((size_t)((c*64+t)*8+b))*256 + 128 + q);
            CP16(sb + bkm + (unsigned)((t*68 + q) * 4),
                 g_M + (size_t)(c*8+b)*4096 + t*64 + q);
            CP16(sb + bkm + (unsigned)((4352 + t*68 + q) * 4),
                 g_KVQZ + ((size_t)((c*64+t)*8+b))*256 + q);
        }
        if (tid < 64) {
            int n2 = tid >> 4, q = (tid & 15) * 4;
            CP16(sb + tvz + (unsigned)((n2*68 + q) * 4),
                 g_TVT + (size_t)(c*8+b)*4096 + (n0+n2)*64 + q);
            CP16(sb + tvz + (unsigned)((272 + tid*4) * 4),
                 g_KVQZ + ((size_t)((c*64+tid)*8+b))*256 + 192 + n0);
        }
        CPCOMMIT();
    };

    issue(0);

    for (int c = 0; c < NCH; c++) {
        {
            ulonglong2 w; w.x = s0r; w.y = s1r;
            *(ulonglong2*)(Sp + qq*272 + nn*68 + 4*mo) = w;
        }
        __syncthreads();

        if (c + 1 < NCH) issue(c + 1);
        else CPCOMMIT();

        {
            int nr = tid >> 6, m = tid & 63;
            S2[nr*68 + m] = Sp[nr*68 + m] + Sp[272 + nr*68 + m]
                          + Sp[544 + nr*68 + m] + Sp[816 + nr*68 + m];
        }
        CPWAIT(1);
        __syncthreads();

        const int buf = c & 1;
        const float* TKs = sm + buf * 8704;
        const float* Qs  = TKs + 4352;
        const float* Ms  = sm + 17408 + buf * 8704;
        const float* Kc  = Ms + 4352;
        const float* TVs = sm + 34816 + buf * 544;
        const float* zs  = TVs + 272;

        ull aw0 = 0ull, aw1 = 0ull, ad0 = 0ull, ad1 = 0ull;
        #pragma unroll
        for (int s = 0; s < 16; s++) {
            ulonglong2 tk = *(const ulonglong2*)(TKs + tt*68 + s*4);
            ulonglong2 qv = *(const ulonglong2*)(Qs  + tt*68 + s*4);
            ulonglong2 sv = *(const ulonglong2*)(S2  + na*68 + s*4);
            aw0 = fma2(tk.x, sv.x, aw0); aw1 = fma2(tk.y, sv.y, aw1);
            ad0 = fma2(qv.x, sv.x, ad0); ad1 = fma2(qv.y, sv.y, ad1);
        }
        float w1  = rsum(aw0) + rsum(aw1);
        float dqa = rsum(ad0) + rsum(ad1);

        Ds[na*68 + tt] = TVs[na*68 + tt] - w1;
        __syncthreads();

        {
            ull ab0 = 0ull, ab1 = 0ull;
            #pragma unroll
            for (int s = 0; s < 16; s++) {
                ulonglong2 mv = *(const ulonglong2*)(Ms + tt*68 + s*4);
                ulonglong2 dv = *(const ulonglong2*)(Ds + na*68 + s*4);
                ab0 = fma2(mv.x, dv.x, ab0); ab1 = fma2(mv.y, dv.y, ab1);
            }
            float d = dqa + rsum(ab0) + rsum(ab1);
            float z = zs[tt*4 + na];
            float ax = fabsf(d);
            float e  = __expf(-2.f * ax);
            float th = __fdividef(1.f - e, 1.f + e);
            th = copysignf(th, d);
            float sg = __fdividef(1.f, 1.f + __expf(-z));
            g_Y[((size_t)((c*64 + tt)*8 + b))*64 + n0 + na] = th * sg;
        }

        {
            const int tb = qq * 16;
            #pragma unroll 8
            for (int t = 0; t < 16; t++) {
                float d = Ds[nn*68 + (tb + t)];
                ull dd = pk2(d, d);
                ulonglong2 kk = *(const ulonglong2*)(Kc + (tb + t)*68 + 4*mo);
                s0r = fma2(dd, kk.x, s0r);
                s1r = fma2(dd, kk.y, s1r);
            }
        }
    }
}

// ---------------------------------------------------------------------------
// k_out: Out = Y @ Wout^T via split-bf16 mma.sync (K=64, single stage).
// Grid (8 d-tiles x 128 m-tiles), 8 warps (4m x 2n), warp tile 32x64.
// smem: Yh|Yl|Wh|Wl each 128x72 shorts = 73728 B.
// ---------------------------------------------------------------------------
__global__ void __launch_bounds__(256) k_out(
    const float* __restrict__ Wout, float* __restrict__ Out)
{
    extern __shared__ unsigned short smo[];
    const int t = threadIdx.x;
    const int d0 = blockIdx.x * 128, m0 = blockIdx.y * 128;
    const int wid = t >> 5, lane = t & 31;
    const int wm = wid & 3, wn = wid >> 2;
    const int l4 = lane >> 2, lq2 = (lane & 3) * 2;

    unsigned short* Yh = smo;
    unsigned short* Yl = smo + 9216;
    unsigned short* Wh = smo + 18432;
    unsigned short* Wl = smo + 27648;

    // stage Y[m0:+128][0:64] and Wout[d0:+128][0:64], split to hi/lo
    #pragma unroll
    for (int i = 0; i < 8; i++) {
        int q = t + i * 256;                       // 2048 quads
        int row = q >> 4, kq = (q & 15) * 4;
        float4 v = *(const float4*)(g_Y + (size_t)(m0 + row) * NS + kq);
        unsigned h01 = bf2(v.x, v.y), h23 = bf2(v.z, v.w);
        float l0 = v.x - bflo(h01), l1 = v.y - bfhi(h01);
        float l2 = v.z - bflo(h23), l3 = v.w - bfhi(h23);
        unsigned q01 = bf2(l0, l1), q23 = bf2(l2, l3);
        ull hp, lp;
        asm("mov.b64 %0, {%1, %2};" : "=l"(hp) : "r"(h01), "r"(h23));
        asm("mov.b64 %0, {%1, %2};" : "=l"(lp) : "r"(q01), "r"(q23));
        *(ull*)(Yh + row * 72 + kq) = hp;
        *(ull*)(Yl + row * 72 + kq) = lp;
        float4 w = *(const float4*)(Wout + (size_t)(d0 + row) * NS + kq);
        unsigned wh01 = bf2(w.x, w.y), wh23 = bf2(w.z, w.w);
        float m0f = w.x - bflo(wh01), m1f = w.y - bfhi(wh01);
        float m2f = w.z - bflo(wh23), m3f = w.w - bfhi(wh23);
        unsigned wl01 = bf2(m0f, m1f), wl23 = bf2(m2f, m3f);
        ull whp, wlp;
        asm("mov.b64 %0, {%1, %2};" : "=l"(whp) : "r"(wh01), "r"(wh23));
        asm("mov.b64 %0, {%1, %2};" : "=l"(wlp) : "r"(wl01), "r"(wl23));
        *(ull*)(Wh + row * 72 + kq) = whp;
        *(ull*)(Wl + row * 72 + kq) = wlp;
    }
    __syncthreads();

    float acc[2][8][4];
    #pragma unroll
    for (int mi = 0; mi < 2; mi++)
        #pragma unroll
        for (int ni = 0; ni < 8; ni++)
            #pragma unroll
            for (int j = 0; j < 4; j++) acc[mi][ni][j] = 0.f;

    #pragma unroll
    for (int kf = 0; kf < 4; kf++) {
        const int ka = kf * 16;
        unsigned ah[2][4], al[2][4];
        #pragma unroll
        for (int mi = 0; mi < 2; mi++) {
            int r0 = wm * 32 + mi * 16 + l4;
            ah[mi][0] = *(const unsigned*)(Yh + r0 * 72 + ka + lq2);
            ah[mi][1] = *(const unsigned*)(Yh + (r0 + 8) * 72 + ka + lq2);
            ah[mi][2] = *(const unsigned*)(Yh + r0 * 72 + ka + 8 + lq2);
            ah[mi][3] = *(const unsigned*)(Yh + (r0 + 8) * 72 + ka + 8 + lq2);
            al[mi][0] = *(const unsigned*)(Yl + r0 * 72 + ka + lq2);
            al[mi][1] = *(const unsigned*)(Yl + (r0 + 8) * 72 + ka + lq2);
            al[mi][2] = *(const unsigned*)(Yl + r0 * 72 + ka + 8 + lq2);
            al[mi][3] = *(const unsigned*)(Yl + (r0 + 8) * 72 + ka + 8 + lq2);
        }
        #pragma unroll
        for (int ni = 0; ni < 8; ni++) {
            int rn = wn * 64 + ni * 8 + l4;
            unsigned bh0 = *(const unsigned*)(Wh + rn * 72 + ka + lq2);
            unsigned bh1 = *(const unsigned*)(Wh + rn * 72 + ka + 8 + lq2);
            unsigned bl0 = *(const unsigned*)(Wl + rn * 72 + ka + lq2);
            unsigned bl1 = *(const unsigned*)(Wl + rn * 72 + ka + 8 + lq2);
            #pragma unroll
            for (int mi = 0; mi < 2; mi++) {
                mma16816(acc[mi][ni], ah[mi], bh0, bh1);
                mma16816(acc[mi][ni], ah[mi], bl0, bl1);
                mma16816(acc[mi][ni], al[mi], bh0, bh1);
            }
        }
    }

    #pragma unroll
    for (int mi = 0; mi < 2; mi++) {
        int rA = m0 + wm * 32 + mi * 16 + l4;
        #pragma unroll
        for (int ni = 0; ni < 8; ni++) {
            int cc = d0 + wn * 64 + ni * 8 + lq2;
            *(float2*)(Out + (size_t)rA * DM + cc) =
                make_float2(acc[mi][ni][0], acc[mi][ni][1]);
            *(float2*)(Out + (size_t)(rA + 8) * DM + cc) =
                make_float2(acc[mi][ni][2], acc[mi][ni][3]);
        }
    }
}

// ---------------------------------------------------------------------------
extern "C" void kernel_launch(void* const* d_in, const int* in_sizes, int n_in,
                              void* d_out, int out_size)
{
    const float* x    = (const float*)d_in[0];
    const float* Win  = (const float*)d_in[1];
    const float* Wk   = (const float*)d_in[2];
    const float* Wv   = (const float*)d_in[3];
    const float* Wq   = (const float*)d_in[4];
    const float* Wz   = (const float*)d_in[5];
    const float* Wout = (const float*)d_in[6];
    float* out = (float*)d_out;

    cudaFuncSetAttribute(k_proj, cudaFuncAttributeMaxDynamicSharedMemorySize, 81920);
    cudaFuncSetAttribute(k_pre,  cudaFuncAttributeMaxDynamicSharedMemorySize, 104448);
    cudaFuncSetAttribute(k_wy,   cudaFuncAttributeMaxDynamicSharedMemorySize, 150144);
    cudaFuncSetAttribute(k_out,  cudaFuncAttributeMaxDynamicSharedMemorySize, 73728);

    k_fuse<<<dim3(16, 4, 4), 256>>>(Win, Wk, Wv, Wq, Wz);
    k_w2b <<<256,            256>>>();
    k_proj<<<dim3(2, 128),   256, 81920>>>(x);
    k_pre <<<256,            256, 104448>>>();
    k_wy  <<<128,            256, 150144>>>();
    k_out <<<dim3(8, 128),   256, 73728>>>(Wout, out);
}

// round 17
// speedup vs baseline: 4.0317x; 1.0272x over previous
#include <cuda_runtime.h>
#include <cuda_bf16.h>
#include <math.h>

#define TT 2048
#define BB 8
#define DM 1024
#define DI 2048
#define NS 64
#define MTOT (TT*BB)
#define NCH 32
#define NTILE 256

__device__ __align__(16) unsigned short g_Wbh[256 * DM];  // fused W hi, bf16, [n=256][k=1024]
__device__ __align__(16) unsigned short g_Wbl[256 * DM];  // fused W lo
__device__ float g_WfP[4 * 256 * DM];          // k-split partials of fused W
__device__ float g_KVQZ[(size_t)MTOT * 256];   // 0-63 k, 64-127 v, 128-191 q, 192-255 z
__device__ float g_Y[(size_t)MTOT * NS];       // activated y
__device__ float g_TK  [(size_t)NTILE * 4096]; // [tile][t*64+m]  T*K
__device__ float g_Qp  [(size_t)NTILE * 4096]; // [tile][t*64+m]  Q - M*TK
__device__ float g_TVT [(size_t)NTILE * 4096]; // [tile][n*64+t]  (T*V)^T
__device__ float g_MTVT[(size_t)NTILE * 4096]; // [tile][n*64+t]  (M*TV)^T

typedef unsigned long long ull;
__device__ __forceinline__ ull pk2(float lo, float hi) {
    ull r; asm("mov.b64 %0, {%1, %2};" : "=l"(r) : "f"(lo), "f"(hi)); return r;
}
__device__ __forceinline__ void unpk2(ull v, float& lo, float& hi) {
    asm("mov.b64 {%0, %1}, %2;" : "=f"(lo), "=f"(hi) : "l"(v));
}
__device__ __forceinline__ ull fma2(ull a, ull b, ull c) {
    ull d; asm("fma.rn.f32x2 %0, %1, %2, %3;" : "=l"(d) : "l"(a), "l"(b), "l"(c)); return d;
}
__device__ __forceinline__ float rsum(ull v) { float lo, hi; unpk2(v, lo, hi); return lo + hi; }
#define CP16(dst, src) asm volatile("cp.async.cg.shared.global [%0], [%1], 16;" :: "r"(dst), "l"(src))
#define CPCOMMIT() asm volatile("cp.async.commit_group;" ::)
#define CPWAIT(n) asm volatile("cp.async.wait_group %0;" :: "n"(n))

__device__ __forceinline__ unsigned bf2(float lo, float hi) {
    unsigned r; asm("cvt.rn.bf16x2.f32 %0, %1, %2;" : "=r"(r) : "f"(hi), "f"(lo)); return r;
}
__device__ __forceinline__ float bflo(unsigned p) { return __uint_as_float(p << 16); }
__device__ __forceinline__ float bfhi(unsigned p) { return __uint_as_float(p & 0xffff0000u); }

__device__ __forceinline__ void mma16816(float* d, const unsigned* a,
                                         unsigned b0, unsigned b1) {
    asm volatile(
        "mma.sync.aligned.m16n8k16.row.col.f32.bf16.bf16.f32 "
        "{%0,%1,%2,%3}, {%4,%5,%6,%7}, {%8,%9}, {%0,%1,%2,%3};"
        : "+f"(d[0]), "+f"(d[1]), "+f"(d[2]), "+f"(d[3])
        : "r"(a[0]), "r"(a[1]), "r"(a[2]), "r"(a[3]), "r"(b0), "r"(b1));
}

// ---------------------------------------------------------------------------
// k_fuse: fused W = Wsel @ Win, K-split x4 (blockIdx.z), fp32 partials.
// ---------------------------------------------------------------------------
__global__ void __launch_bounds__(256) k_fuse(
    const float* __restrict__ Win, const float* __restrict__ Wk,
    const float* __restrict__ Wv,  const float* __restrict__ Wq,
    const float* __restrict__ Wz)
{
    __shared__ __align__(16) float As[2][16][65];
    __shared__ __align__(16) float Bs[2][16][68];
    const int d0 = blockIdx.x * 64, m0 = blockIdx.y * 64;
    const int kc = blockIdx.z;
    const int t = threadIdx.x, tx = t & 15, ty = t >> 4;
    ull acc2[4][2];
    #pragma unroll
    for (int i = 0; i < 4; i++) { acc2[i][0] = 0ull; acc2[i][1] = 0ull; }

    const int lm = t >> 2, lk = (t & 3) * 4;
    const int r = m0 + lm;
    const float* W = (r < 64) ? Wk : (r < 128) ? Wv : (r < 192) ? Wq : Wz;
    const float* arow = W + (size_t)(r & 63) * DI + kc * 512 + lk;
    const int bk = t >> 4, bd = (t & 15) * 4;
    const float* bsrc = Win + (size_t)(kc * 512 + bk) * DM + d0 + bd;
    unsigned bdst[2];
    bdst[0] = (unsigned)__cvta_generic_to_shared(&Bs[0][bk][bd]);
    bdst[1] = (unsigned)__cvta_generic_to_shared(&Bs[1][bk][bd]);

    float4 a = *(const float4*)(arow);
    CP16(bdst[0], bsrc); CPCOMMIT();

    for (int c = 0; c < 32; c++) {
        const int buf = c & 1;
        As[buf][lk+0][lm] = a.x; As[buf][lk+1][lm] = a.y;
        As[buf][lk+2][lm] = a.z; As[buf][lk+3][lm] = a.w;
        if (c + 1 < 32) a = *(const float4*)(arow + (c + 1) * 16);
        CPWAIT(0);
        __syncthreads();
        if (c + 1 < 32) {
            CP16(bdst[buf ^ 1], bsrc + (size_t)(c + 1) * 16 * DM); CPCOMMIT();
        }
        #pragma unroll
        for (int k = 0; k < 16; k++) {
            float av[4];
            #pragma unroll
            for (int i = 0; i < 4; i++) av[i] = As[buf][k][ty*4 + i];
            const ull* bq = (const ull*)&Bs[buf][k][tx*4];
            ull b0 = bq[0], b1 = bq[1];
            #pragma unroll
            for (int i = 0; i < 4; i++) {
                ull ai = pk2(av[i], av[i]);
                acc2[i][0] = fma2(ai, b0, acc2[i][0]);
                acc2[i][1] = fma2(ai, b1, acc2[i][1]);
            }
        }
    }
    #pragma unroll
    for (int i = 0; i < 4; i++) {
        float o[4];
        unpk2(acc2[i][0], o[0], o[1]);
        unpk2(acc2[i][1], o[2], o[3]);
        float* dst = g_WfP + (size_t)kc * (256 * DM)
                   + (size_t)(m0 + ty*4 + i) * DM + d0 + tx*4;
        *(float4*)dst = make_float4(o[0], o[1], o[2], o[3]);
    }
}

// ---------------------------------------------------------------------------
// k_w2b: sum 4 K-partials, split to bf16 hi/lo [n][k].
// ---------------------------------------------------------------------------
__global__ void __launch_bounds__(256) k_w2b()
{
    const int gid = blockIdx.x * 256 + threadIdx.x;
    const int n = gid >> 8, d4 = (gid & 255) * 4;
    const size_t off = (size_t)n * DM + d4;
    float4 s0 = *(const float4*)(g_WfP + off);
    float4 s1 = *(const float4*)(g_WfP + 262144 + off);
    float4 s2 = *(const float4*)(g_WfP + 524288 + off);
    float4 s3 = *(const float4*)(g_WfP + 786432 + off);
    float o[4] = { s0.x + s1.x + s2.x + s3.x, s0.y + s1.y + s2.y + s3.y,
                   s0.z + s1.z + s2.z + s3.z, s0.w + s1.w + s2.w + s3.w };
    unsigned h01 = bf2(o[0], o[1]), h23 = bf2(o[2], o[3]);
    float l0 = o[0] - bflo(h01), l1 = o[1] - bfhi(h01);
    float l2 = o[2] - bflo(h23), l3 = o[3] - bfhi(h23);
    unsigned lo01 = bf2(l0, l1), lo23 = bf2(l2, l3);
    ull hp, lp;
    asm("mov.b64 %0, {%1, %2};" : "=l"(hp) : "r"(h01), "r"(h23));
    asm("mov.b64 %0, {%1, %2};" : "=l"(lp) : "r"(lo01), "r"(lo23));
    *(ull*)(g_Wbh + off) = hp;
    *(ull*)(g_Wbl + off) = lp;
}

// ---------------------------------------------------------------------------
// k_proj: KVQZ = X @ Wf^T via split-bf16 mma.sync (unchanged from R16).
// ---------------------------------------------------------------------------
__global__ void __launch_bounds__(256) k_proj(const float* __restrict__ X)
{
    extern __shared__ unsigned short smp[];
    const int t = threadIdx.x;
    const int n0 = blockIdx.x * 128, m0 = blockIdx.y * 128;
    const int wid = t >> 5, lane = t & 31;
    const int wm = wid & 3, wn = wid >> 2;
    const int l4 = lane >> 2, lq2 = (lane & 3) * 2;

    float acc[2][8][4];
    #pragma unroll
    for (int mi = 0; mi < 2; mi++)
        #pragma unroll
        for (int ni = 0; ni < 8; ni++)
            #pragma unroll
            for (int j = 0; j < 4; j++) acc[mi][ni][j] = 0.f;

    float4 xr[4];
    ulonglong2 wr[4];

    auto loadX = [&](int c, float4* dst) {
        #pragma unroll
        for (int i = 0; i < 4; i++) {
            int q = t + i * 256;
            int row = q >> 3, kq = (q & 7) * 4;
            dst[i] = *(const float4*)(X + (size_t)(m0 + row) * DM + c * 32 + kq);
        }
    };
    auto loadW = [&](int c, ulonglong2* dst) {
        #pragma unroll
        for (int i = 0; i < 4; i++) {
            int idx = t + i * 256;
            int mat = idx >> 9, j = idx & 511;
            int rr = j >> 2, seg = j & 3;
            const unsigned short* src = (mat == 0 ? g_Wbh : g_Wbl)
                + (size_t)(n0 + rr) * DM + c * 32 + seg * 8;
            dst[i] = *(const ulonglong2*)src;
        }
    };

    loadX(0, xr);
    loadW(0, wr);

    for (int c = 0; c < 32; c++) {
        const int buf = c & 1;
        unsigned short* Xh = smp + buf * 20480;
        unsigned short* Xl = Xh + 5120;
        unsigned short* Wh = Xh + 10240;
        unsigned short* Wl = Xh + 15360;

        #pragma unroll
        for (int i = 0; i < 4; i++) {
            int q = t + i * 256;
            int row = q >> 3, kq = (q & 7) * 4;
            float4 v = xr[i];
            unsigned h01 = bf2(v.x, v.y), h23 = bf2(v.z, v.w);
            float l0 = v.x - bflo(h01), l1 = v.y - bfhi(h01);
            float l2 = v.z - bflo(h23), l3 = v.w - bfhi(h23);
            unsigned q01 = bf2(l0, l1), q23 = bf2(l2, l3);
            ull hp, lp;
            asm("mov.b64 %0, {%1, %2};" : "=l"(hp) : "r"(h01), "r"(h23));
            asm("mov.b64 %0, {%1, %2};" : "=l"(lp) : "r"(q01), "r"(q23));
            *(ull*)(Xh + row * 40 + kq) = hp;
            *(ull*)(Xl + row * 40 + kq) = lp;
        }
        #pragma unroll
        for (int i = 0; i < 4; i++) {
            int idx = t + i * 256;
            int mat = idx >> 9, j = idx & 511;
            int rr = j >> 2, seg = j & 3;
            *(ulonglong2*)((mat == 0 ? Wh : Wl) + rr * 40 + seg * 8) = wr[i];
        }
        if (c + 1 < 32) { loadX(c + 1, xr); loadW(c + 1, wr); }
        __syncthreads();

        #pragma unroll
        for (int kf = 0; kf < 2; kf++) {
            const int ka = kf * 16;
            unsigned ah[2][4], al[2][4];
            #pragma unroll
            for (int mi = 0; mi < 2; mi++) {
                int r0 = wm * 32 + mi * 16 + l4;
                ah[mi][0] = *(const unsigned*)(Xh + r0 * 40 + ka + lq2);
                ah[mi][1] = *(const unsigned*)(Xh + (r0 + 8) * 40 + ka + lq2);
                ah[mi][2] = *(const unsigned*)(Xh + r0 * 40 + ka + 8 + lq2);
                ah[mi][3] = *(const unsigned*)(Xh + (r0 + 8) * 40 + ka + 8 + lq2);
                al[mi][0] = *(const unsigned*)(Xl + r0 * 40 + ka + lq2);
                al[mi][1] = *(const unsigned*)(Xl + (r0 + 8) * 40 + ka + lq2);
                al[mi][2] = *(const unsigned*)(Xl + r0 * 40 + ka + 8 + lq2);
                al[mi][3] = *(const unsigned*)(Xl + (r0 + 8) * 40 + ka + 8 + lq2);
            }
            #pragma unroll
            for (int ni = 0; ni < 8; ni++) {
                int rn = wn * 64 + ni * 8 + l4;
                unsigned bh0 = *(const unsigned*)(Wh + rn * 40 + ka + lq2);
                unsigned bh1 = *(const unsigned*)(Wh + rn * 40 + ka + 8 + lq2);
                unsigned bl0 = *(const unsigned*)(Wl + rn * 40 + ka + lq2);
                unsigned bl1 = *(const unsigned*)(Wl + rn * 40 + ka + 8 + lq2);
                #pragma unroll
                for (int mi = 0; mi < 2; mi++) {
                    mma16816(acc[mi][ni], ah[mi], bh0, bh1);
                    mma16816(acc[mi][ni], ah[mi], bl0, bl1);
                    mma16816(acc[mi][ni], al[mi], bh0, bh1);
                }
            }
        }
        __syncthreads();
    }

    if (blockIdx.x == 0 && wn == 0) {
        #pragma unroll
        for (int mi = 0; mi < 2; mi++) {
            float ssA = 0.f, ssB = 0.f;
            #pragma unroll
            for (int ni = 0; ni < 8; ni++) {
                ssA = fmaf(acc[mi][ni][0], acc[mi][ni][0], ssA);
                ssA = fmaf(acc[mi][ni][1], acc[mi][ni][1], ssA);
                ssB = fmaf(acc[mi][ni][2], acc[mi][ni][2], ssB);
                ssB = fmaf(acc[mi][ni][3], acc[mi][ni][3], ssB);
            }
            ssA += __shfl_xor_sync(0xffffffffu, ssA, 1);
            ssA += __shfl_xor_sync(0xffffffffu, ssA, 2);
            ssB += __shfl_xor_sync(0xffffffffu, ssB, 1);
            ssB += __shfl_xor_sync(0xffffffffu, ssB, 2);
            float invA = __fdividef(1.f, sqrtf(ssA) + 1e-6f);
            float invB = __fdividef(1.f, sqrtf(ssB) + 1e-6f);
            #pragma unroll
            for (int ni = 0; ni < 8; ni++) {
                acc[mi][ni][0] *= invA; acc[mi][ni][1] *= invA;
                acc[mi][ni][2] *= invB; acc[mi][ni][3] *= invB;
            }
        }
    }

    #pragma unroll
    for (int mi = 0; mi < 2; mi++) {
        int rA = m0 + wm * 32 + mi * 16 + l4;
        #pragma unroll
        for (int ni = 0; ni < 8; ni++) {
            int cc = n0 + wn * 64 + ni * 8 + lq2;
            *(float2*)(g_KVQZ + (size_t)rA * 256 + cc) =
                make_float2(acc[mi][ni][0], acc[mi][ni][1]);
            *(float2*)(g_KVQZ + (size_t)(rA + 8) * 256 + cc) =
                make_float2(acc[mi][ni][2], acc[mi][ni][3]);
        }
    }
}

// ---------------------------------------------------------------------------
// k_pre: WY precompute + NEW state-independent folds:
//   Q' = Q - M*TK  -> g_Qp,   MTV = M*TV -> g_MTVT (transposed)
// Buffer reuse: KsT (dead after A/M) holds M; Aa (dead after subst) holds TK;
// Vs overwritten in place by TV.
// ---------------------------------------------------------------------------
__global__ void __launch_bounds__(256) k_pre()
{
    extern __shared__ float sm[];
    float* Ks  = sm;
    float* Vs  = sm + 4352;     // V, later TV
    float* Qs  = sm + 8704;
    float* Aa  = sm + 13056;    // A, later TK
    float* Nn  = sm + 17408;
    float* KsT = sm + 21760;    // K^T, later M

    const int tile = blockIdx.x;
    const int b = tile & 7, c = tile >> 3;
    const int tid = threadIdx.x;

    for (int i = tid; i < 3072; i += 256) {
        int mat = i >> 10, rr = i & 1023, t = rr >> 4, q = (rr & 15) * 4;
        const float* src = g_KVQZ + ((size_t)((c*64+t)*8+b)) * 256 + mat * 64 + q;
        float4 v = *(const float4*)src;
        float* dst = (mat == 0 ? Ks : mat == 1 ? Vs : Qs) + t * 68 + q;
        dst[0] = v.x; dst[1] = v.y; dst[2] = v.z; dst[3] = v.w;
        if (mat == 0) {
            KsT[(q+0)*68 + t] = v.x;
            KsT[(q+1)*68 + t] = v.y;
            KsT[(q+2)*68 + t] = v.z;
            KsT[(q+3)*68 + t] = v.w;
        }
    }
    for (int i = tid; i < 4352; i += 256) Nn[i] = 0.f;
    __syncthreads();

    const int ty = tid >> 4, tx = tid & 15;
    const int t0 = ty * 4, j0 = tx * 4;

    float mreg[4][4];            // masked M tile (kept in regs until KsT is dead)
    {   // A = K K^T -> Aa ;  M = tril(Q K^T) -> mreg
        ull accA[4][2], accM[4][2];
        #pragma unroll
        for (int i = 0; i < 4; i++) {
            accA[i][0] = accA[i][1] = 0ull;
            accM[i][0] = accM[i][1] = 0ull;
        }
        for (int m = 0; m < 64; m++) {
            ulonglong2 kj = *(const ulonglong2*)(KsT + m*68 + j0);
            float kt[4], qt[4];
            #pragma unroll
            for (int i = 0; i < 4; i++) { kt[i] = Ks[(t0+i)*68 + m]; qt[i] = Qs[(t0+i)*68 + m]; }
            #pragma unroll
            for (int i = 0; i < 4; i++) {
                ull ki = pk2(kt[i], kt[i]);
                ull qi = pk2(qt[i], qt[i]);
                accA[i][0] = fma2(ki, kj.x, accA[i][0]);
                accA[i][1] = fma2(ki, kj.y, accA[i][1]);
                accM[i][0] = fma2(qi, kj.x, accM[i][0]);
                accM[i][1] = fma2(qi, kj.y, accM[i][1]);
            }
        }
        #pragma unroll
        for (int i = 0; i < 4; i++) {
            float oa[4], om[4];
            unpk2(accA[i][0], oa[0], oa[1]);
            unpk2(accA[i][1], oa[2], oa[3]);
            unpk2(accM[i][0], om[0], om[1]);
            unpk2(accM[i][1], om[2], om[3]);
            #pragma unroll
            for (int j = 0; j < 4; j++) {
                Aa[(t0+i)*68 + j0+j] = oa[j];
                mreg[i][j] = (j0+j <= t0+i) ? om[j] : 0.f;
            }
        }
    }
    __syncthreads();
    // KsT dead -> store M
    #pragma unroll
    for (int i = 0; i < 4; i++)
        #pragma unroll
        for (int j = 0; j < 4; j++)
            KsT[(t0+i)*68 + j0+j] = mreg[i][j];
    __syncthreads();
    float* Ms = KsT;

    // forward substitution: N = (I+L)^{-1} - I
    for (int i = 1; i < 64; i++) {
        if (tid < i) {
            float s = -Aa[i*68 + tid];
            for (int p = tid + 1; p < i; p++)
                s = fmaf(-Aa[i*68 + p], Nn[p*68 + tid], s);
            Nn[i*68 + tid] = s;
        }
        __syncthreads();
    }

    // TK = K + N K ; TV = V + N V   (compute both in regs first)
    float tkreg[4][4], tvreg[4][4];
    {
        ull accK[4][2], accV[4][2];
        #pragma unroll
        for (int i = 0; i < 4; i++) {
            accK[i][0] = accK[i][1] = 0ull;
            accV[i][0] = accV[i][1] = 0ull;
        }
        for (int jj = 0; jj < 64; jj++) {
            float nt[4];
            #pragma unroll
            for (int i = 0; i < 4; i++) nt[i] = Nn[(t0+i)*68 + jj];
            const ull* kq = (const ull*)(Ks + jj*68 + j0);
            const ull* vq = (const ull*)(Vs + jj*68 + j0);
            ull k0 = kq[0], k1 = kq[1], v0 = vq[0], v1 = vq[1];
            #pragma unroll
            for (int i = 0; i < 4; i++) {
                ull ni = pk2(nt[i], nt[i]);
                accK[i][0] = fma2(ni, k0, accK[i][0]);
                accK[i][1] = fma2(ni, k1, accK[i][1]);
                accV[i][0] = fma2(ni, v0, accV[i][0]);
                accV[i][1] = fma2(ni, v1, accV[i][1]);
            }
        }
        #pragma unroll
        for (int i = 0; i < 4; i++) {
            float ok[4], ov[4];
            unpk2(accK[i][0], ok[0], ok[1]);
            unpk2(accK[i][1], ok[2], ok[3]);
            unpk2(accV[i][0], ov[0], ov[1]);
            unpk2(accV[i][1], ov[2], ov[3]);
            #pragma unroll
            for (int j = 0; j < 4; j++) {
                tkreg[i][j] = Ks[(t0+i)*68 + j0+j] + ok[j];
                tvreg[i][j] = Vs[(t0+i)*68 + j0+j] + ov[j];
            }
        }
    }
    __syncthreads();
    // Aa dead -> TKs; Vs overwritten in place by TV; write globals
    #pragma unroll
    for (int i = 0; i < 4; i++)
        #pragma unroll
        for (int j = 0; j < 4; j++) {
            Aa[(t0+i)*68 + j0+j] = tkreg[i][j];
            Vs[(t0+i)*68 + j0+j] = tvreg[i][j];
            g_TK [(size_t)tile*4096 + (t0+i)*64 + j0+j] = tkreg[i][j];
            g_TVT[(size_t)tile*4096 + (j0+j)*64 + (t0+i)] = tvreg[i][j];
        }
    __syncthreads();
    float* TKs = Aa;
    float* TVf = Vs;

    // Q' = Q - M*TK -> g_Qp ;  MTV = M*TV -> g_MTVT (transposed)
    {
        ull accQ[4][2], accT[4][2];
        #pragma unroll
        for (int i = 0; i < 4; i++) {
            accQ[i][0] = accQ[i][1] = 0ull;
            accT[i][0] = accT[i][1] = 0ull;
        }
        for (int jj = 0; jj < 64; jj++) {
            float mt[4];
            #pragma unroll
            for (int i = 0; i < 4; i++) mt[i] = Ms[(t0+i)*68 + jj];
            const ull* kq = (const ull*)(TKs + jj*68 + j0);
            const ull* vq = (const ull*)(TVf + jj*68 + j0);
            ull k0 = kq[0], k1 = kq[1], v0 = vq[0], v1 = vq[1];
            #pragma unroll
            for (int i = 0; i < 4; i++) {
                ull mi = pk2(mt[i], mt[i]);
                accQ[i][0] = fma2(mi, k0, accQ[i][0]);
                accQ[i][1] = fma2(mi, k1, accQ[i][1]);
                accT[i][0] = fma2(mi, v0, accT[i][0]);
                accT[i][1] = fma2(mi, v1, accT[i][1]);
            }
        }
        #pragma unroll
        for (int i = 0; i < 4; i++) {
            float oq[4], ot[4];
            unpk2(accQ[i][0], oq[0], oq[1]);
            unpk2(accQ[i][1], oq[2], oq[3]);
            unpk2(accT[i][0], ot[0], ot[1]);
            unpk2(accT[i][1], ot[2], ot[3]);
            #pragma unroll
            for (int j = 0; j < 4; j++) {
                g_Qp  [(size_t)tile*4096 + (t0+i)*64 + j0+j] =
                    Qs[(t0+i)*68 + j0+j] - oq[j];
                g_MTVT[(size_t)tile*4096 + (j0+j)*64 + (t0+i)] = ot[j];
            }
        }
    }
}

// ---------------------------------------------------------------------------
// k_wy: chunk recurrence, phase B folded into k_pre via Q'/MTV.
// 128 blocks = 8 b x 16 n-groups(4).  Double-buffered inputs.
// smem floats: TKQ'[2] 2x8704 | Kc[2] 2x4352 | TVz[2] 2x800
//              | S2 272 | Ds 272 | Sp 1088 = 29344 (117376 B)
// ---------------------------------------------------------------------------
__global__ void __launch_bounds__(256, 1) k_wy()
{
    extern __shared__ float sm[];
    const int tid = threadIdx.x;
    const int b  = blockIdx.x >> 4;
    const int n0 = (blockIdx.x & 15) * 4;
    const int tt = tid >> 2, na = tid & 3;
    const int qq = tid >> 6;
    const int nn = (tid >> 4) & 3, mo = tid & 15;

    float* S2 = sm + 27712;
    float* Ds = sm + 27984;
    float* Sp = sm + 28256;
    const unsigned sb = (unsigned)__cvta_generic_to_shared(sm);

    ull s0r = 0ull, s1r = 0ull;

    auto issue = [&](int c) {
        const int buf = c & 1;
        const unsigned tkq = (unsigned)(buf * 8704 * 4);
        const unsigned kcb = (unsigned)((17408 + buf * 4352) * 4);
        const unsigned tvz = (unsigned)((26112 + buf * 800) * 4);
        for (int i = tid; i < 1024; i += 256) {
            int t = i >> 4, q = (i & 15) * 4;
            CP16(sb + tkq + (unsigned)((t*68 + q) * 4),
                 g_TK + (size_t)(c*8+b)*4096 + t*64 + q);
            CP16(sb + tkq + (unsigned)((4352 + t*68 + q) * 4),
                 g_Qp + (size_t)(c*8+b)*4096 + t*64 + q);
            CP16(sb + kcb + (unsigned)((t*68 + q) * 4),
                 g_KVQZ + ((size_t)((c*64+t)*8+b))*256 + q);
        }
        if (tid < 64) {
            int n2 = tid >> 4, q = (tid & 15) * 4;
            CP16(sb + tvz + (unsigned)((n2*68 + q) * 4),
                 g_TVT + (size_t)(c*8+b)*4096 + (n0+n2)*64 + q);
            CP16(sb + tvz + (unsigned)((272 + n2*68 + q) * 4),
                 g_MTVT + (size_t)(c*8+b)*4096 + (n0+n2)*64 + q);
            CP16(sb + tvz + (unsigned)((544 + tid*4) * 4),
                 g_KVQZ + ((size_t)((c*64+tid)*8+b))*256 + 192 + n0);
        }
        CPCOMMIT();
    };

    issue(0);

    for (int c = 0; c < NCH; c++) {
        {
            ulonglong2 w; w.x = s0r; w.y = s1r;
            *(ulonglong2*)(Sp + qq*272 + nn*68 + 4*mo) = w;
        }
        __syncthreads();

        if (c + 1 < NCH) issue(c + 1);
        else CPCOMMIT();

        {
            int nr = tid >> 6, m = tid & 63;
            S2[nr*68 + m] = Sp[nr*68 + m] + Sp[272 + nr*68 + m]
                          + Sp[544 + nr*68 + m] + Sp[816 + nr*68 + m];
        }
        CPWAIT(1);
        __syncthreads();

        const int buf = c & 1;
        const float* TKs  = sm + buf * 8704;
        const float* Qps  = TKs + 4352;
        const float* Kc   = sm + 17408 + buf * 4352;
        const float* TVs  = sm + 26112 + buf * 800;
        const float* MTVs = TVs + 272;
        const float* zs   = TVs + 544;

        // fused phase: w1 = TK[t].S2[n], dq = Q'[t].S2[n] + MTV[n][t]
        ull aw0 = 0ull, aw1 = 0ull, ad0 = 0ull, ad1 = 0ull;
        #pragma unroll
        for (int s = 0; s < 16; s++) {
            ulonglong2 tk = *(const ulonglong2*)(TKs + tt*68 + s*4);
            ulonglong2 qv = *(const ulonglong2*)(Qps + tt*68 + s*4);
            ulonglong2 sv = *(const ulonglong2*)(S2  + na*68 + s*4);
            aw0 = fma2(tk.x, sv.x, aw0); aw1 = fma2(tk.y, sv.y, aw1);
            ad0 = fma2(qv.x, sv.x, ad0); ad1 = fma2(qv.y, sv.y, ad1);
        }
        float w1 = rsum(aw0) + rsum(aw1);
        float dq = rsum(ad0) + rsum(ad1) + MTVs[na*68 + tt];

        Ds[na*68 + tt] = TVs[na*68 + tt] - w1;

        {   // activation + store (no dependency on Ds of other threads)
            float z = zs[tt*4 + na];
            float ax = fabsf(dq);
            float e  = __expf(-2.f * ax);
            float th = __fdividef(1.f - e, 1.f + e);
            th = copysignf(th, dq);
            float sg = __fdividef(1.f, 1.f + __expf(-z));
            g_Y[((size_t)((c*64 + tt)*8 + b))*64 + n0 + na] = th * sg;
        }
        __syncthreads();

        {   // phase C: partial S += Delta^T K over this quarter's t-range
            const int tb = qq * 16;
            #pragma unroll 8
            for (int t = 0; t < 16; t++) {
                float d = Ds[nn*68 + (tb + t)];
                ull dd = pk2(d, d);
                ulonglong2 kk = *(const ulonglong2*)(Kc + (tb + t)*68 + 4*mo);
                s0r = fma2(dd, kk.x, s0r);
                s1r = fma2(dd, kk.y, s1r);
            }
        }
    }
}

// ---------------------------------------------------------------------------
// k_out: Out = Y @ Wout^T via split-bf16 mma.sync (unchanged from R16).
// ---------------------------------------------------------------------------
__global__ void __launch_bounds__(256) k_out(
    const float* __restrict__ Wout, float* __restrict__ Out)
{
    extern __shared__ unsigned short smo[];
    const int t = threadIdx.x;
    const int d0 = blockIdx.x * 128, m0 = blockIdx.y * 128;
    const int wid = t >> 5, lane = t & 31;
    const int wm = wid & 3, wn = wid >> 2;
    const int l4 = lane >> 2, lq2 = (lane & 3) * 2;

    unsigned short* Yh = smo;
    unsigned short* Yl = smo + 9216;
    unsigned short* Wh = smo + 18432;
    unsigned short* Wl = smo + 27648;

    #pragma unroll
    for (int i = 0; i < 8; i++) {
        int q = t + i * 256;
        int row = q >> 4, kq = (q & 15) * 4;
        float4 v = *(const float4*)(g_Y + (size_t)(m0 + row) * NS + kq);
        unsigned h01 = bf2(v.x, v.y), h23 = bf2(v.z, v.w);
        float l0 = v.x - bflo(h01), l1 = v.y - bfhi(h01);
        float l2 = v.z - bflo(h23), l3 = v.w - bfhi(h23);
        unsigned q01 = bf2(l0, l1), q23 = bf2(l2, l3);
        ull hp, lp;
        asm("mov.b64 %0, {%1, %2};" : "=l"(hp) : "r"(h01), "r"(h23));
        asm("mov.b64 %0, {%1, %2};" : "=l"(lp) : "r"(q01), "r"(q23));
        *(ull*)(Yh + row * 72 + kq) = hp;
        *(ull*)(Yl + row * 72 + kq) = lp;
        float4 w = *(const float4*)(Wout + (size_t)(d0 + row) * NS + kq);
        unsigned wh01 = bf2(w.x, w.y), wh23 = bf2(w.z, w.w);
        float m0f = w.x - bflo(wh01), m1f = w.y - bfhi(wh01);
        float m2f = w.z - bflo(wh23), m3f = w.w - bfhi(wh23);
        unsigned wl01 = bf2(m0f, m1f), wl23 = bf2(m2f, m3f);
        ull whp, wlp;
        asm("mov.b64 %0, {%1, %2};" : "=l"(whp) : "r"(wh01), "r"(wh23));
        asm("mov.b64 %0, {%1, %2};" : "=l"(wlp) : "r"(wl01), "r"(wl23));
        *(ull*)(Wh + row * 72 + kq) = whp;
        *(ull*)(Wl + row * 72 + kq) = wlp;
    }
    __syncthreads();

    float acc[2][8][4];
    #pragma unroll
    for (int mi = 0; mi < 2; mi++)
        #pragma unroll
        for (int ni = 0; ni < 8; ni++)
            #pragma unroll
            for (int j = 0; j < 4; j++) acc[mi][ni][j] = 0.f;

    #pragma unroll
    for (int kf = 0; kf < 4; kf++) {
        const int ka = kf * 16;
        unsigned ah[2][4], al[2][4];
        #pragma unroll
        for (int mi = 0; mi < 2; mi++) {
            int r0 = wm * 32 + mi * 16 + l4;
            ah[mi][0] = *(const unsigned*)(Yh + r0 * 72 + ka + lq2);
            ah[mi][1] = *(const unsigned*)(Yh + (r0 + 8) * 72 + ka + lq2);
            ah[mi][2] = *(const unsigned*)(Yh + r0 * 72 + ka + 8 + lq2);
            ah[mi][3] = *(const unsigned*)(Yh + (r0 + 8) * 72 + ka + 8 + lq2);
            al[mi][0] = *(const unsigned*)(Yl + r0 * 72 + ka + lq2);
            al[mi][1] = *(const unsigned*)(Yl + (r0 + 8) * 72 + ka + lq2);
            al[mi][2] = *(const unsigned*)(Yl + r0 * 72 + ka + 8 + lq2);
            al[mi][3] = *(const unsigned*)(Yl + (r0 + 8) * 72 + ka + 8 + lq2);
        }
        #pragma unroll
        for (int ni = 0; ni < 8; ni++) {
            int rn = wn * 64 + ni * 8 + l4;
            unsigned bh0 = *(const unsigned*)(Wh + rn * 72 + ka + lq2);
            unsigned bh1 = *(const unsigned*)(Wh + rn * 72 + ka + 8 + lq2);
            unsigned bl0 = *(const unsigned*)(Wl + rn * 72 + ka + lq2);
            unsigned bl1 = *(const unsigned*)(Wl + rn * 72 + ka + 8 + lq2);
            #pragma unroll
            for (int mi = 0; mi < 2; mi++) {
                mma16816(acc[mi][ni], ah[mi], bh0, bh1);
                mma16816(acc[mi][ni], ah[mi], bl0, bl1);
                mma16816(acc[mi][ni], al[mi], bh0, bh1);
            }
        }
    }

    #pragma unroll
    for (int mi = 0; mi < 2; mi++) {
        int rA = m0 + wm * 32 + mi * 16 + l4;
        #pragma unroll
        for (int ni = 0; ni < 8; ni++) {
            int cc = d0 + wn * 64 + ni * 8 + lq2;
            *(float2*)(Out + (size_t)rA * DM + cc) =
                make_float2(acc[mi][ni][0], acc[mi][ni][1]);
            *(float2*)(Out + (size_t)(rA + 8) * DM + cc) =
                make_float2(acc[mi][ni][2], acc[mi][ni][3]);
        }
    }
}

// ---------------------------------------------------------------------------
extern "C" void kernel_launch(void* const* d_in, const int* in_sizes, int n_in,
                              void* d_out, int out_size)
{
    const float* x    = (const float*)d_in[0];
    const float* Win  = (const float*)d_in[1];
    const float* Wk   = (const float*)d_in[2];
    const float* Wv   = (const float*)d_in[3];
    const float* Wq   = (const float*)d_in[4];
    const float* Wz   = (const float*)d_in[5];
    const float* Wout = (const float*)d_in[6];
    float* out = (float*)d_out;

    cudaFuncSetAttribute(k_proj, cudaFuncAttributeMaxDynamicSharedMemorySize, 81920);
    cudaFuncSetAttribute(k_pre,  cudaFuncAttributeMaxDynamicSharedMemorySize, 104448);
    cudaFuncSetAttribute(k_wy,   cudaFuncAttributeMaxDynamicSharedMemorySize, 117376);
    cudaFuncSetAttribute(k_out,  cudaFuncAttributeMaxDynamicSharedMemorySize, 73728);

    k_fuse<<<dim3(16, 4, 4), 256>>>(Win, Wk, Wv, Wq, Wz);
    k_w2b <<<256,            256>>>();
    k_proj<<<dim3(2, 128),   256, 81920>>>(x);
    k_pre <<<256,            256, 104448>>>();
    k_wy  <<<128,            256, 117376>>>();
    k_out <<<dim3(8, 128),   256, 73728>>>(Wout, out);
}